// round 3
// baseline (speedup 1.0000x reference)
#include <cuda_runtime.h>
#include <math.h>

#define NROWS 32768
#define DDIM  1024
#define NGD   1024
#define NLD   256
#define NCOMB 1280

// ---------------- scratch (device globals; no allocations allowed) --------
__device__ float  g_h[NROWS * DDIM];        // hidden after relu
__device__ float  g_zp[NROWS * DDIM];       // z_proj (aligned scratch)
__device__ float  g_nn[NROWS * DDIM];       // noise_norm (== u_norm)
__device__ float  g_zn[NROWS * DDIM];       // z_norm
__device__ float  g_gate[NROWS * DDIM];     // gate
__device__ float  g_S[(size_t)NROWS * NCOMB]; // sims -> softmax weights (in place)
__device__ float  g_comb[NCOMB * DDIM];     // updated [gdict; ldict]
__device__ float  g_sums[NCOMB * DDIM];     // scatter sums
__device__ float  g_cnts[NCOMB];
__device__ int    g_idx[2 * NROWS];
__device__ double g_acc[3];                 // sum|S_g|, sum|S_l|, sum|dot|

// ---------------- init ----------------------------------------------------
__global__ void init_kernel() {
    int i = blockIdx.x * blockDim.x + threadIdx.x;
    if (i < NCOMB * DDIM) g_sums[i] = 0.f;
    if (i < NCOMB)        g_cnts[i] = 0.f;
    if (i < 3)            g_acc[i]  = 0.0;
}

// ---------------- misalignment-safe copy (dst only 4B-aligned) ------------
__global__ __launch_bounds__(256)
void copy_kernel(const float* __restrict__ src, float* __restrict__ dst, int n) {
    int i = (blockIdx.x * blockDim.x + threadIdx.x) * 4;
    if (i + 3 < n) {
        float4 v = *reinterpret_cast<const float4*>(&src[i]);  // src is 16B aligned
        dst[i + 0] = v.x; dst[i + 1] = v.y; dst[i + 2] = v.z; dst[i + 3] = v.w;
    }
}

// ---------------- row L2 normalize -----------------------------------------
__global__ __launch_bounds__(256)
void rownorm_kernel(const float* __restrict__ X, float* __restrict__ Y) {
    __shared__ float red[8];
    const int r = blockIdx.x, tid = threadIdx.x;
    const float* xr = X + (size_t)r * DDIM;
    float4 x = *reinterpret_cast<const float4*>(&xr[tid * 4]);
    float ss = x.x * x.x + x.y * x.y + x.z * x.z + x.w * x.w;
#pragma unroll
    for (int off = 16; off; off >>= 1) ss += __shfl_down_sync(0xffffffffu, ss, off);
    if ((tid & 31) == 0) red[tid >> 5] = ss;
    __syncthreads();
    if (tid == 0) {
        float s = 0.f;
#pragma unroll
        for (int i = 0; i < 8; i++) s += red[i];
        red[0] = s;
    }
    __syncthreads();
    float inv = 1.f / fmaxf(sqrtf(red[0]), 1e-12f);
    *reinterpret_cast<float4*>(&Y[(size_t)r * DDIM + tid * 4]) =
        make_float4(x.x * inv, x.y * inv, x.z * inv, x.w * inv);
}

// ---------------- generic 128x128x8 fp32 GEMM with fused epilogues --------
enum { EPI_RELU_BIAS = 0, EPI_BIAS = 1, EPI_SIGMOID = 2, EPI_S_LOSS = 3, EPI_ZCLEAN = 4 };

template <int EPI, bool TRANSB>
__global__ __launch_bounds__(256)
void gemm_kernel(const float* __restrict__ A, const float* __restrict__ B,
                 const float* __restrict__ bias, float* __restrict__ C,
                 int M, int Ncols, int K,
                 const float* __restrict__ e1, const float* __restrict__ e2) {
    __shared__ float As[8][128];
    __shared__ float Bs[8][128];
    const int tid  = threadIdx.x;
    const int m0   = blockIdx.y * 128;
    const int n0   = blockIdx.x * 128;
    const int arow = tid >> 1, ac4 = (tid & 1) << 2;
    const int brow = tid >> 5, bc4 = (tid & 31) << 2;
    const int ty = tid >> 4, tx = tid & 15;
    const int ry = ty << 3, cx = tx << 3;

    float acc[8][8];
#pragma unroll
    for (int i = 0; i < 8; i++)
#pragma unroll
        for (int j = 0; j < 8; j++) acc[i][j] = 0.f;

    const float* Aptr = A + (size_t)(m0 + arow) * K + ac4;
    for (int kt = 0; kt < K; kt += 8) {
        float4 av = *reinterpret_cast<const float4*>(Aptr + kt);
        As[ac4 + 0][arow] = av.x; As[ac4 + 1][arow] = av.y;
        As[ac4 + 2][arow] = av.z; As[ac4 + 3][arow] = av.w;
        if (TRANSB) {
            float4 bv = *reinterpret_cast<const float4*>(&B[(size_t)(n0 + arow) * K + kt + ac4]);
            Bs[ac4 + 0][arow] = bv.x; Bs[ac4 + 1][arow] = bv.y;
            Bs[ac4 + 2][arow] = bv.z; Bs[ac4 + 3][arow] = bv.w;
        } else {
            *reinterpret_cast<float4*>(&Bs[brow][bc4]) =
                *reinterpret_cast<const float4*>(&B[(size_t)(kt + brow) * Ncols + n0 + bc4]);
        }
        __syncthreads();
#pragma unroll
        for (int k = 0; k < 8; k++) {
            float4 a0 = *reinterpret_cast<const float4*>(&As[k][ry]);
            float4 a1 = *reinterpret_cast<const float4*>(&As[k][ry + 4]);
            float4 b0 = *reinterpret_cast<const float4*>(&Bs[k][cx]);
            float4 b1 = *reinterpret_cast<const float4*>(&Bs[k][cx + 4]);
            float a[8] = {a0.x, a0.y, a0.z, a0.w, a1.x, a1.y, a1.z, a1.w};
            float b[8] = {b0.x, b0.y, b0.z, b0.w, b1.x, b1.y, b1.z, b1.w};
#pragma unroll
            for (int i = 0; i < 8; i++)
#pragma unroll
                for (int j = 0; j < 8; j++)
                    acc[i][j] = fmaf(a[i], b[j], acc[i][j]);
        }
        __syncthreads();
    }

    float bb[8];
    if (EPI == EPI_RELU_BIAS || EPI == EPI_BIAS || EPI == EPI_SIGMOID) {
#pragma unroll
        for (int j = 0; j < 8; j++) bb[j] = bias[n0 + cx + j];
    }
    double part = 0.0;
#pragma unroll
    for (int i = 0; i < 8; i++) {
        size_t ro = (size_t)(m0 + ry + i) * Ncols + n0 + cx;
        float v[8];
#pragma unroll
        for (int j = 0; j < 8; j++) {
            float x = acc[i][j];
            if (EPI == EPI_RELU_BIAS)    x = fmaxf(x + bb[j], 0.f);
            else if (EPI == EPI_BIAS)    x = x + bb[j];
            else if (EPI == EPI_SIGMOID) x = 1.f / (1.f + expf(-(x + bb[j])));
            v[j] = x;
        }
        if (EPI == EPI_ZCLEAN) {
            float4 z0 = *reinterpret_cast<const float4*>(&e1[ro]);
            float4 z1 = *reinterpret_cast<const float4*>(&e1[ro + 4]);
            float4 q0 = *reinterpret_cast<const float4*>(&e2[ro]);
            float4 q1 = *reinterpret_cast<const float4*>(&e2[ro + 4]);
            v[0] = z0.x - q0.x * v[0]; v[1] = z0.y - q0.y * v[1];
            v[2] = z0.z - q0.z * v[2]; v[3] = z0.w - q0.w * v[3];
            v[4] = z1.x - q1.x * v[4]; v[5] = z1.y - q1.y * v[5];
            v[6] = z1.z - q1.z * v[6]; v[7] = z1.w - q1.w * v[7];
        }
        if (EPI == EPI_S_LOSS) {
#pragma unroll
            for (int j = 0; j < 8; j++) part += (double)fabsf(v[j]);
        }
        *reinterpret_cast<float4*>(&C[ro])     = make_float4(v[0], v[1], v[2], v[3]);
        *reinterpret_cast<float4*>(&C[ro + 4]) = make_float4(v[4], v[5], v[6], v[7]);
    }
    if (EPI == EPI_S_LOSS) {
#pragma unroll
        for (int off = 16; off; off >>= 1) part += __shfl_down_sync(0xffffffffu, part, off);
        if ((tid & 31) == 0) atomicAdd(&g_acc[(n0 < NGD) ? 0 : 1], part);
    }
}

// ---------------- fused sim-GEMM + per-row argmax --------------------------
__global__ __launch_bounds__(256)
void argmax_kernel(const float* __restrict__ A, const float* __restrict__ Dict,
                   int Kc, int* __restrict__ idx_out) {
    __shared__ float As[8][128];
    __shared__ float Bs[8][128];
    const int tid  = threadIdx.x;
    const int m0   = blockIdx.x * 128;
    const int arow = tid >> 1, ac4 = (tid & 1) << 2;
    const int ty = tid >> 4, tx = tid & 15;
    const int ry = ty << 3, cx = tx << 3;

    float bv[8]; int bc[8];
#pragma unroll
    for (int i = 0; i < 8; i++) { bv[i] = -1e30f; bc[i] = 0; }

    const float* Aptr = A + (size_t)(m0 + arow) * DDIM + ac4;
    for (int n0 = 0; n0 < Kc; n0 += 128) {
        float acc[8][8];
#pragma unroll
        for (int i = 0; i < 8; i++)
#pragma unroll
            for (int j = 0; j < 8; j++) acc[i][j] = 0.f;
        for (int kt = 0; kt < DDIM; kt += 8) {
            float4 av = *reinterpret_cast<const float4*>(Aptr + kt);
            As[ac4 + 0][arow] = av.x; As[ac4 + 1][arow] = av.y;
            As[ac4 + 2][arow] = av.z; As[ac4 + 3][arow] = av.w;
            float4 dv = *reinterpret_cast<const float4*>(&Dict[(size_t)(n0 + arow) * DDIM + kt + ac4]);
            Bs[ac4 + 0][arow] = dv.x; Bs[ac4 + 1][arow] = dv.y;
            Bs[ac4 + 2][arow] = dv.z; Bs[ac4 + 3][arow] = dv.w;
            __syncthreads();
#pragma unroll
            for (int k = 0; k < 8; k++) {
                float4 a0 = *reinterpret_cast<const float4*>(&As[k][ry]);
                float4 a1 = *reinterpret_cast<const float4*>(&As[k][ry + 4]);
                float4 b0 = *reinterpret_cast<const float4*>(&Bs[k][cx]);
                float4 b1 = *reinterpret_cast<const float4*>(&Bs[k][cx + 4]);
                float a[8] = {a0.x, a0.y, a0.z, a0.w, a1.x, a1.y, a1.z, a1.w};
                float b[8] = {b0.x, b0.y, b0.z, b0.w, b1.x, b1.y, b1.z, b1.w};
#pragma unroll
                for (int i = 0; i < 8; i++)
#pragma unroll
                    for (int j = 0; j < 8; j++)
                        acc[i][j] = fmaf(a[i], b[j], acc[i][j]);
            }
            __syncthreads();
        }
#pragma unroll
        for (int i = 0; i < 8; i++) {
            float v = -1e30f; int c = 0;
#pragma unroll
            for (int j = 0; j < 8; j++) {
                float x = acc[i][j];
                int cc = n0 + cx + j;
                if (x > v) { v = x; c = cc; }
            }
#pragma unroll
            for (int off = 8; off; off >>= 1) {
                float ov = __shfl_down_sync(0xffffffffu, v, off, 16);
                int   oc = __shfl_down_sync(0xffffffffu, c, off, 16);
                if (ov > v || (ov == v && oc < c)) { v = ov; c = oc; }
            }
            if (tx == 0) {
                if (v > bv[i] || (v == bv[i] && c < bc[i])) { bv[i] = v; bc[i] = c; }
            }
        }
    }
    if (tx == 0) {
#pragma unroll
        for (int i = 0; i < 8; i++) idx_out[m0 + ry + i] = bc[i];
    }
}

// ---------------- scatter-add rows into code sums --------------------------
__global__ __launch_bounds__(256)
void scatter_kernel(const float* __restrict__ NN_, const int* __restrict__ idx) {
    const int r = blockIdx.x, tid = threadIdx.x;
    const int ig = idx[r];
    const int il = NGD + idx[NROWS + r];
    float4 v = *reinterpret_cast<const float4*>(&NN_[(size_t)r * DDIM + tid * 4]);
    float* sg = &g_sums[(size_t)ig * DDIM + tid * 4];
    float* sl = &g_sums[(size_t)il * DDIM + tid * 4];
    atomicAdd(sg + 0, v.x); atomicAdd(sg + 1, v.y); atomicAdd(sg + 2, v.z); atomicAdd(sg + 3, v.w);
    atomicAdd(sl + 0, v.x); atomicAdd(sl + 1, v.y); atomicAdd(sl + 2, v.z); atomicAdd(sl + 3, v.w);
    if (tid == 0) { atomicAdd(&g_cnts[ig], 1.f); atomicAdd(&g_cnts[il], 1.f); }
}

// ---------------- EMA dict update + L2 normalize ---------------------------
__global__ __launch_bounds__(256)
void dictupd_kernel(const float* __restrict__ gd, const float* __restrict__ ld) {
    __shared__ float red[8];
    const int c = blockIdx.x, tid = threadIdx.x;
    const float* dsrc = (c < NGD) ? (gd + (size_t)c * DDIM) : (ld + (size_t)(c - NGD) * DDIM);
    const float m = (c < NGD) ? 0.999f : 0.8f;
    const float cnt = g_cnts[c];
    float4 d  = *reinterpret_cast<const float4*>(&dsrc[tid * 4]);
    float4 sm = *reinterpret_cast<const float4*>(&g_sums[(size_t)c * DDIM + tid * 4]);
    float u0, u1, u2, u3;
    if (cnt > 0.f) {
        float w = (1.f - m) / cnt;
        u0 = m * d.x + w * sm.x; u1 = m * d.y + w * sm.y;
        u2 = m * d.z + w * sm.z; u3 = m * d.w + w * sm.w;
    } else { u0 = d.x; u1 = d.y; u2 = d.z; u3 = d.w; }
    float ss = u0 * u0 + u1 * u1 + u2 * u2 + u3 * u3;
#pragma unroll
    for (int off = 16; off; off >>= 1) ss += __shfl_down_sync(0xffffffffu, ss, off);
    if ((tid & 31) == 0) red[tid >> 5] = ss;
    __syncthreads();
    if (tid == 0) {
        float s = 0.f;
#pragma unroll
        for (int i = 0; i < 8; i++) s += red[i];
        red[0] = s;
    }
    __syncthreads();
    float inv = 1.f / fmaxf(sqrtf(red[0]), 1e-12f);
    *reinterpret_cast<float4*>(&g_comb[(size_t)c * DDIM + tid * 4]) =
        make_float4(u0 * inv, u1 * inv, u2 * inv, u3 * inv);
}

// ---------------- softmax over 1280 cols (in place) ------------------------
__global__ __launch_bounds__(256)
void softmax_kernel(float* __restrict__ S) {
    __shared__ float red[8];
    const int r = blockIdx.x, tid = threadIdx.x;
    float* s = S + (size_t)r * NCOMB;
    float v[5];
#pragma unroll
    for (int i = 0; i < 5; i++) v[i] = s[tid + i * 256];
    float mx = v[0];
#pragma unroll
    for (int i = 1; i < 5; i++) mx = fmaxf(mx, v[i]);
#pragma unroll
    for (int off = 16; off; off >>= 1) mx = fmaxf(mx, __shfl_down_sync(0xffffffffu, mx, off));
    if ((tid & 31) == 0) red[tid >> 5] = mx;
    __syncthreads();
    if (tid == 0) {
        float t = red[0];
#pragma unroll
        for (int i = 1; i < 8; i++) t = fmaxf(t, red[i]);
        red[0] = t;
    }
    __syncthreads();
    mx = red[0];
    __syncthreads();
    const float invT = 1.f / 0.07f;
    float ssum = 0.f;
#pragma unroll
    for (int i = 0; i < 5; i++) { v[i] = expf((v[i] - mx) * invT); ssum += v[i]; }
#pragma unroll
    for (int off = 16; off; off >>= 1) ssum += __shfl_down_sync(0xffffffffu, ssum, off);
    if ((tid & 31) == 0) red[tid >> 5] = ssum;
    __syncthreads();
    if (tid == 0) {
        float t = 0.f;
#pragma unroll
        for (int i = 0; i < 8; i++) t += red[i];
        red[0] = t;
    }
    __syncthreads();
    float inv = 1.f / red[0];
#pragma unroll
    for (int i = 0; i < 5; i++) s[tid + i * 256] = v[i] * inv;
}

// ---------------- loss_direct: |dot(z_norm, u_norm)| per row ---------------
__global__ __launch_bounds__(256)
void dotabs_kernel(const float* __restrict__ ZN, const float* __restrict__ UN) {
    __shared__ float red[8];
    const int r = blockIdx.x, tid = threadIdx.x;
    float4 a = *reinterpret_cast<const float4*>(&ZN[(size_t)r * DDIM + tid * 4]);
    float4 b = *reinterpret_cast<const float4*>(&UN[(size_t)r * DDIM + tid * 4]);
    float p = a.x * b.x + a.y * b.y + a.z * b.z + a.w * b.w;
#pragma unroll
    for (int off = 16; off; off >>= 1) p += __shfl_down_sync(0xffffffffu, p, off);
    if ((tid & 31) == 0) red[tid >> 5] = p;
    __syncthreads();
    if (tid == 0) {
        float s = 0.f;
#pragma unroll
        for (int i = 0; i < 8; i++) s += red[i];
        atomicAdd(&g_acc[2], (double)fabsf(s));
    }
}

__global__ void finalize_kernel(float* out_loss) {
    *out_loss = (float)(g_acc[0] / ((double)NROWS * (double)NGD) +
                        g_acc[1] / ((double)NROWS * (double)NLD) +
                        g_acc[2] / (double)NROWS);
}

// ---------------- launch ---------------------------------------------------
extern "C" void kernel_launch(void* const* d_in, const int* in_sizes, int n_in,
                              void* d_out, int out_size) {
    const float* z  = (const float*)d_in[0];
    const float* u  = (const float*)d_in[1];
    const float* W1 = (const float*)d_in[2];
    const float* b1 = (const float*)d_in[3];
    const float* W2 = (const float*)d_in[4];
    const float* b2 = (const float*)d_in[5];
    const float* Wg = (const float*)d_in[6];
    const float* bg = (const float*)d_in[7];
    const float* gd = (const float*)d_in[8];
    const float* ld = (const float*)d_in[9];

    float* out       = (float*)d_out;
    float* out_zc    = out;                                   // [N, D] (16B aligned)
    float* out_loss  = out + (size_t)NROWS * DDIM;            // [1]
    float* out_zproj = out_loss + 1;                          // [N, D] (only 4B aligned!)
    float* out_u     = out_zproj + (size_t)NROWS * DDIM;      // [N, D] (only 4B aligned!)

    static float *p_h = nullptr, *p_zp, *p_nn, *p_zn, *p_gate, *p_S, *p_comb;
    static int* p_idx;
    if (!p_h) {
        cudaGetSymbolAddress((void**)&p_h, g_h);
        cudaGetSymbolAddress((void**)&p_zp, g_zp);
        cudaGetSymbolAddress((void**)&p_nn, g_nn);
        cudaGetSymbolAddress((void**)&p_zn, g_zn);
        cudaGetSymbolAddress((void**)&p_gate, g_gate);
        cudaGetSymbolAddress((void**)&p_S, g_S);
        cudaGetSymbolAddress((void**)&p_comb, g_comb);
        cudaGetSymbolAddress((void**)&p_idx, g_idx);
    }

    const int ND = NROWS * DDIM;

    init_kernel<<<(NCOMB * DDIM) / 256, 256>>>();

    // noise_norm (aligned scratch)
    rownorm_kernel<<<NROWS, 256>>>(u, p_nn);

    // projector (all into aligned scratch)
    gemm_kernel<EPI_RELU_BIAS, false><<<dim3(DDIM / 128, NROWS / 128), 256>>>(
        z, W1, b1, p_h, NROWS, DDIM, DDIM, nullptr, nullptr);
    gemm_kernel<EPI_BIAS, false><<<dim3(DDIM / 128, NROWS / 128), 256>>>(
        p_h, W2, b2, p_zp, NROWS, DDIM, DDIM, nullptr, nullptr);

    rownorm_kernel<<<NROWS, 256>>>(p_zp, p_zn);

    // gate
    gemm_kernel<EPI_SIGMOID, false><<<dim3(DDIM / 128, NROWS / 128), 256>>>(
        p_zp, Wg, bg, p_gate, NROWS, DDIM, DDIM, nullptr, nullptr);

    // dict assignment + EMA update
    argmax_kernel<<<NROWS / 128, 256>>>(p_nn, gd, NGD, p_idx);
    argmax_kernel<<<NROWS / 128, 256>>>(p_nn, ld, NLD, p_idx + NROWS);
    scatter_kernel<<<NROWS, 256>>>(p_nn, p_idx);
    dictupd_kernel<<<NCOMB, 256>>>(gd, ld);

    // S = z_norm @ comb^T  (+ fused Sum|S| for loss_g / loss_l)
    gemm_kernel<EPI_S_LOSS, true><<<dim3(NCOMB / 128, NROWS / 128), 256>>>(
        p_zn, p_comb, nullptr, p_S, NROWS, NCOMB, DDIM, nullptr, nullptr);

    softmax_kernel<<<NROWS, 256>>>(p_S);

    // weighted_u + fused z_clean epilogue (out_zc is 16B aligned: offset 0)
    gemm_kernel<EPI_ZCLEAN, false><<<dim3(DDIM / 128, NROWS / 128), 256>>>(
        p_S, p_comb, nullptr, out_zc, NROWS, DDIM, NCOMB, z, p_gate);

    dotabs_kernel<<<NROWS, 256>>>(p_zn, p_nn);
    finalize_kernel<<<1, 1>>>(out_loss);

    // misalignment-safe copies of z_proj and u_flat into the output tuple
    copy_kernel<<<ND / (256 * 4), 256>>>(p_zp, out_zproj, ND);
    copy_kernel<<<ND / (256 * 4), 256>>>(u, out_u, ND);
}

// round 6
// speedup vs baseline: 2.2757x; 2.2757x over previous
#include <cuda_runtime.h>
#include <cuda_bf16.h>
#include <math.h>
#include <stdint.h>

#define NROWS 32768
#define DDIM  1024
#define NGD   1024
#define NLD   256
#define NCOMB 1280
#define NM    (NROWS * DDIM)

typedef __nv_bfloat16 bf;

// ---------------- warp MMA primitives (plain sm_80+ PTX, no 'a' features) --
__device__ __forceinline__ uint32_t smem_u32(const void* p) {
    uint32_t a;
    asm("{ .reg .u64 t; cvta.to.shared.u64 t, %1; cvt.u32.u64 %0, t; }" : "=r"(a) : "l"(p));
    return a;
}
__device__ __forceinline__ void ldsm4(uint32_t addr, uint32_t* f) {
    asm volatile("ldmatrix.sync.aligned.m8n8.x4.shared.b16 {%0,%1,%2,%3}, [%4];"
                 : "=r"(f[0]), "=r"(f[1]), "=r"(f[2]), "=r"(f[3]) : "r"(addr));
}
__device__ __forceinline__ void mma16816(float* c, const uint32_t* a, uint32_t b0, uint32_t b1) {
    asm volatile("mma.sync.aligned.m16n8k16.row.col.f32.bf16.bf16.f32 "
                 "{%0,%1,%2,%3}, {%4,%5,%6,%7}, {%8,%9}, {%0,%1,%2,%3};"
                 : "+f"(c[0]), "+f"(c[1]), "+f"(c[2]), "+f"(c[3])
                 : "r"(a[0]), "r"(a[1]), "r"(a[2]), "r"(a[3]), "r"(b0), "r"(b1));
}
__device__ __forceinline__ void split2(float x, bf& h, bf& l) {
    h = __float2bfloat16(x);
    l = __float2bfloat16(x - __bfloat162float(h));
}
__device__ __forceinline__ uint32_t pack_hi(float a, float b) {
    __nv_bfloat162 p = __floats2bfloat162_rn(a, b);  // rn of each
    return *reinterpret_cast<uint32_t*>(&p);
}

// ---------------- scratch ---------------------------------------------------
__device__ float  g_zp[NM];
__device__ float  g_nn[NM];
__device__ float  g_zn[NM];
__device__ float  g_gate[NM];
__device__ float  g_S[(size_t)NROWS * NCOMB];
__device__ float  g_comb[NCOMB * DDIM];
__device__ float  g_sums[NCOMB * DDIM];
__device__ float  g_cnts[NCOMB];
__device__ int    g_idx[2 * NROWS];
__device__ double g_acc[3];

__device__ bf b_z[2][NM];
__device__ bf b_h[2][NM];
__device__ bf b_zp[2][NM];
__device__ bf b_nn[2][NM];
__device__ bf b_zn[2][NM];
__device__ bf b_S[2][(size_t)NROWS * NCOMB];
__device__ bf b_W1T[2][DDIM * DDIM];
__device__ bf b_W2T[2][DDIM * DDIM];
__device__ bf b_WgT[2][DDIM * DDIM];
__device__ bf b_gd[2][NGD * DDIM];
__device__ bf b_ld[2][NLD * DDIM];
__device__ bf b_comb[2][NCOMB * DDIM];
__device__ bf b_combT[2][DDIM * NCOMB];

// ---------------- small kernels --------------------------------------------
__global__ void init_kernel() {
    int i = blockIdx.x * blockDim.x + threadIdx.x;
    if (i < NCOMB * DDIM) g_sums[i] = 0.f;
    if (i < NCOMB)        g_cnts[i] = 0.f;
    if (i < 3)            g_acc[i]  = 0.0;
}

__global__ __launch_bounds__(256)
void copy_kernel(const float* __restrict__ src, float* __restrict__ dst, int n) {
    int i = (blockIdx.x * blockDim.x + threadIdx.x) * 4;
    if (i + 3 < n) {
        float4 v = *reinterpret_cast<const float4*>(&src[i]);
        dst[i] = v.x; dst[i + 1] = v.y; dst[i + 2] = v.z; dst[i + 3] = v.w;
    }
}

__global__ __launch_bounds__(256)
void conv_split_kernel(const float* __restrict__ src, bf* __restrict__ dh,
                       bf* __restrict__ dl, int n) {
    int i = (blockIdx.x * blockDim.x + threadIdx.x) * 4;
    if (i + 3 < n) {
        float4 v = *reinterpret_cast<const float4*>(&src[i]);
        bf h[4], l[4];
        split2(v.x, h[0], l[0]); split2(v.y, h[1], l[1]);
        split2(v.z, h[2], l[2]); split2(v.w, h[3], l[3]);
        *reinterpret_cast<uint2*>(&dh[i]) = *reinterpret_cast<uint2*>(h);
        *reinterpret_cast<uint2*>(&dl[i]) = *reinterpret_cast<uint2*>(l);
    }
}

// tiled transpose + split: src [R][C] fp32 -> dst [c][r] bf16 hi/lo
__global__ __launch_bounds__(256)
void transconv_kernel(const float* __restrict__ src, int R, int C,
                      bf* __restrict__ dh, bf* __restrict__ dl) {
    __shared__ float t[32][33];
    const int bx = blockIdx.x * 32, by = blockIdx.y * 32;
    const int tx = threadIdx.x & 31, ty = threadIdx.x >> 5;
#pragma unroll
    for (int i = 0; i < 4; i++)
        t[ty + 8 * i][tx] = src[(size_t)(by + ty + 8 * i) * C + bx + tx];
    __syncthreads();
#pragma unroll
    for (int i = 0; i < 4; i++) {
        float x = t[tx][ty + 8 * i];
        bf h, l; split2(x, h, l);
        size_t o = (size_t)(bx + ty + 8 * i) * R + by + tx;
        dh[o] = h; dl[o] = l;
    }
}

__global__ __launch_bounds__(256)
void rownorm_split_kernel(const float* __restrict__ X, float* __restrict__ Y,
                          bf* __restrict__ Yh, bf* __restrict__ Yl) {
    __shared__ float red[8];
    const int r = blockIdx.x, tid = threadIdx.x;
    float4 x = *reinterpret_cast<const float4*>(&X[(size_t)r * DDIM + tid * 4]);
    float ss = x.x * x.x + x.y * x.y + x.z * x.z + x.w * x.w;
#pragma unroll
    for (int off = 16; off; off >>= 1) ss += __shfl_down_sync(0xffffffffu, ss, off);
    if ((tid & 31) == 0) red[tid >> 5] = ss;
    __syncthreads();
    if (tid == 0) {
        float s = 0.f;
#pragma unroll
        for (int i = 0; i < 8; i++) s += red[i];
        red[0] = s;
    }
    __syncthreads();
    float inv = 1.f / fmaxf(sqrtf(red[0]), 1e-12f);
    float f[4] = {x.x * inv, x.y * inv, x.z * inv, x.w * inv};
    size_t o = (size_t)r * DDIM + tid * 4;
    *reinterpret_cast<float4*>(&Y[o]) = make_float4(f[0], f[1], f[2], f[3]);
    bf h[4], l[4];
#pragma unroll
    for (int i = 0; i < 4; i++) split2(f[i], h[i], l[i]);
    *reinterpret_cast<uint2*>(&Yh[o]) = *reinterpret_cast<uint2*>(h);
    *reinterpret_cast<uint2*>(&Yl[o]) = *reinterpret_cast<uint2*>(l);
}

// ---------------- HMMA GEMM ------------------------------------------------
// Block 128x128, 8 warps 2x4 (warp = 64x32), K-chunk 32, smem [128][40] bf16.
enum { EPI_RELU_BIAS = 0, EPI_BIAS = 1, EPI_SIGMOID = 2, EPI_S_LOSS = 3, EPI_ZCLEAN = 4 };

#define TPAD 40  // smem row stride in elements

// one K-chunk (32) global->smem fill for 4 tiles; expects syncthreads around
struct Fill {
    uint4 v[8];
    __device__ __forceinline__ void load(const bf* __restrict__ Ah, const bf* __restrict__ Al,
                                         const bf* __restrict__ Bh, const bf* __restrict__ Bl,
                                         int m0, int n0, int k0, int K, int tid) {
#pragma unroll
        for (int t = 0; t < 4; t++) {
            const bf* gp = (t == 0) ? Ah : (t == 1) ? Al : (t == 2) ? Bh : Bl;
            const int rb = (t < 2) ? m0 : n0;
#pragma unroll
            for (int r = 0; r < 2; r++) {
                int idx = r * 256 + tid;
                int row = idx >> 2, c8 = (idx & 3) << 3;
                v[t * 2 + r] = *reinterpret_cast<const uint4*>(
                    gp + (size_t)(rb + row) * K + k0 + c8);
            }
        }
    }
    __device__ __forceinline__ void store(char* sAh, char* sAl, char* sBh, char* sBl, int tid) {
#pragma unroll
        for (int t = 0; t < 4; t++) {
            char* sp = (t == 0) ? sAh : (t == 1) ? sAl : (t == 2) ? sBh : sBl;
#pragma unroll
            for (int r = 0; r < 2; r++) {
                int idx = r * 256 + tid;
                int row = idx >> 2, c8 = (idx & 3) << 3;
                *reinterpret_cast<uint4*>(sp + row * (TPAD * 2) + c8 * 2) = v[t * 2 + r];
            }
        }
    }
};

// 3-product hi/lo compute of one K-chunk into acc[4][4][4]
__device__ __forceinline__ void chunk_mma(float acc[4][4][4],
                                          uint32_t aH, uint32_t aL,
                                          uint32_t bH, uint32_t bL) {
#pragma unroll
    for (int ks = 0; ks < 2; ks++) {
        const int kb = ks * 32;  // 16 elems * 2B
        uint32_t bh[8], bl[8];
        ldsm4(bH + kb, bh); ldsm4(bH + 16 * (TPAD * 2) + kb, bh + 4);
        ldsm4(bL + kb, bl); ldsm4(bL + 16 * (TPAD * 2) + kb, bl + 4);
#pragma unroll
        for (int mt = 0; mt < 4; mt++) {
            uint32_t ah[4], al[4];
            ldsm4(aH + mt * 16 * (TPAD * 2) + kb, ah);
            ldsm4(aL + mt * 16 * (TPAD * 2) + kb, al);
#pragma unroll
            for (int nt = 0; nt < 4; nt++) {
                mma16816(acc[mt][nt], ah, bh[2 * nt], bh[2 * nt + 1]);
                mma16816(acc[mt][nt], ah, bl[2 * nt], bl[2 * nt + 1]);
                mma16816(acc[mt][nt], al, bh[2 * nt], bh[2 * nt + 1]);
            }
        }
    }
}

template <int EPI, bool WF32, bool WSPLIT>
__global__ __launch_bounds__(256)
void gemm_mma(const bf* __restrict__ Ah, const bf* __restrict__ Al,
              const bf* __restrict__ Bh, const bf* __restrict__ Bl,
              const float* __restrict__ bias, float* __restrict__ Cf,
              bf* __restrict__ Ch, bf* __restrict__ Cl,
              int Ncols, int K,
              const float* __restrict__ e1, const float* __restrict__ e2) {
    __shared__ __align__(16) char sAh[128 * TPAD * 2];
    __shared__ __align__(16) char sAl[128 * TPAD * 2];
    __shared__ __align__(16) char sBh[128 * TPAD * 2];
    __shared__ __align__(16) char sBl[128 * TPAD * 2];

    const int tid = threadIdx.x, lane = tid & 31, wid = tid >> 5;
    const int m0 = blockIdx.y * 128, n0 = blockIdx.x * 128;
    const int warp_m = (wid >> 2) * 64, warp_n = (wid & 3) * 32;

    // ldmatrix lane bases (bytes)
    const int aoff = (warp_m + (lane & 15)) * (TPAD * 2) + ((lane >> 4) << 3) * 2;
    const int boff = (warp_n + ((lane & 7) | ((lane >> 4) << 3))) * (TPAD * 2) +
                     (((lane >> 3) & 1) << 3) * 2;
    const uint32_t aH = smem_u32(sAh) + aoff, aL = smem_u32(sAl) + aoff;
    const uint32_t bH = smem_u32(sBh) + boff, bL = smem_u32(sBl) + boff;

    float acc[4][4][4] = {};

    for (int kc = 0; kc < K; kc += 32) {
        Fill f;
        f.load(Ah, Al, Bh, Bl, m0, n0, kc, K, tid);
        __syncthreads();
        f.store(sAh, sAl, sBh, sBl, tid);
        __syncthreads();
        chunk_mma(acc, aH, aL, bH, bL);
    }

    // ---------------- epilogue ----------------
    double part = 0.0;
#pragma unroll
    for (int mt = 0; mt < 4; mt++) {
        const int r0 = m0 + warp_m + mt * 16 + (lane >> 2);
#pragma unroll
        for (int nt = 0; nt < 4; nt++) {
            const int col = n0 + warp_n + nt * 8 + ((lane & 3) << 1);
            float b2x = 0.f, b2y = 0.f;
            if (EPI == EPI_RELU_BIAS || EPI == EPI_BIAS || EPI == EPI_SIGMOID) {
                float2 bb = *reinterpret_cast<const float2*>(bias + col);
                b2x = bb.x; b2y = bb.y;
            }
#pragma unroll
            for (int h = 0; h < 2; h++) {
                const int row = r0 + h * 8;
                float v0 = acc[mt][nt][2 * h], v1 = acc[mt][nt][2 * h + 1];
                if (EPI == EPI_RELU_BIAS) { v0 = fmaxf(v0 + b2x, 0.f); v1 = fmaxf(v1 + b2y, 0.f); }
                else if (EPI == EPI_BIAS) { v0 += b2x; v1 += b2y; }
                else if (EPI == EPI_SIGMOID) {
                    v0 = 1.f / (1.f + expf(-(v0 + b2x)));
                    v1 = 1.f / (1.f + expf(-(v1 + b2y)));
                }
                const size_t ro = (size_t)row * Ncols + col;
                if (EPI == EPI_ZCLEAN) {
                    float2 z2 = *reinterpret_cast<const float2*>(e1 + ro);
                    float2 q2 = *reinterpret_cast<const float2*>(e2 + ro);
                    v0 = z2.x - q2.x * v0;
                    v1 = z2.y - q2.y * v1;
                }
                if (EPI == EPI_S_LOSS) part += (double)fabsf(v0) + (double)fabsf(v1);
                if (WF32)
                    *reinterpret_cast<float2*>(Cf + ro) = make_float2(v0, v1);
                if (WSPLIT) {
                    bf h0, l0, h1, l1;
                    split2(v0, h0, l0); split2(v1, h1, l1);
                    bf hp[2] = {h0, h1}, lp[2] = {l0, l1};
                    *reinterpret_cast<uint32_t*>(Ch + ro) = *reinterpret_cast<uint32_t*>(hp);
                    *reinterpret_cast<uint32_t*>(Cl + ro) = *reinterpret_cast<uint32_t*>(lp);
                }
            }
        }
    }
    if (EPI == EPI_S_LOSS) {
#pragma unroll
        for (int off = 16; off; off >>= 1) part += __shfl_down_sync(0xffffffffu, part, off);
        if (lane == 0) atomicAdd(&g_acc[(n0 < NGD) ? 0 : 1], part);
    }
}

// ---------------- HMMA sim + per-row argmax --------------------------------
__global__ __launch_bounds__(256)
void argmax_mma(const bf* __restrict__ Ah, const bf* __restrict__ Al,
                const bf* __restrict__ Dh, const bf* __restrict__ Dl,
                int ncodes, int* __restrict__ idx_out) {
    __shared__ __align__(16) char sAh[128 * TPAD * 2];
    __shared__ __align__(16) char sAl[128 * TPAD * 2];
    __shared__ __align__(16) char sBh[128 * TPAD * 2];
    __shared__ __align__(16) char sBl[128 * TPAD * 2];
    __shared__ float sval[128][4];
    __shared__ int   sidx[128][4];

    const int tid = threadIdx.x, lane = tid & 31, wid = tid >> 5;
    const int m0 = blockIdx.x * 128;
    const int warp_m = (wid >> 2) * 64, warp_n = (wid & 3) * 32;

    const int aoff = (warp_m + (lane & 15)) * (TPAD * 2) + ((lane >> 4) << 3) * 2;
    const int boff = (warp_n + ((lane & 7) | ((lane >> 4) << 3))) * (TPAD * 2) +
                     (((lane >> 3) & 1) << 3) * 2;
    const uint32_t aH = smem_u32(sAh) + aoff, aL = smem_u32(sAl) + aoff;
    const uint32_t bH = smem_u32(sBh) + boff, bL = smem_u32(sBl) + boff;

    float bv[8]; int bi[8];
#pragma unroll
    for (int i = 0; i < 8; i++) { bv[i] = -1e30f; bi[i] = 0; }

    for (int n0 = 0; n0 < ncodes; n0 += 128) {
        float acc[4][4][4] = {};
        for (int kc = 0; kc < DDIM; kc += 32) {
            Fill f;
            f.load(Ah, Al, Dh, Dl, m0, n0, kc, DDIM, tid);
            __syncthreads();
            f.store(sAh, sAl, sBh, sBl, tid);
            __syncthreads();
            chunk_mma(acc, aH, aL, bH, bL);
        }
        // fold this 128-col tile into running best (strict > keeps earliest)
#pragma unroll
        for (int mt = 0; mt < 4; mt++)
#pragma unroll
            for (int h = 0; h < 2; h++) {
                float* bvp = &bv[mt * 2 + h]; int* bip = &bi[mt * 2 + h];
#pragma unroll
                for (int nt = 0; nt < 4; nt++) {
                    const int col = n0 + warp_n + nt * 8 + ((lane & 3) << 1);
                    float v0 = acc[mt][nt][2 * h], v1 = acc[mt][nt][2 * h + 1];
                    if (v0 > *bvp) { *bvp = v0; *bip = col; }
                    if (v1 > *bvp) { *bvp = v1; *bip = col + 1; }
                }
            }
    }
    // quad reduce (lanes sharing the same rows differ only in lane&3)
#pragma unroll
    for (int i = 0; i < 8; i++) {
        float v = bv[i]; int c = bi[i];
#pragma unroll
        for (int off = 1; off <= 2; off <<= 1) {
            float ov = __shfl_xor_sync(0xffffffffu, v, off);
            int   oc = __shfl_xor_sync(0xffffffffu, c, off);
            if (ov > v || (ov == v && oc < c)) { v = ov; c = oc; }
        }
        if ((lane & 3) == 0) {
            int row = warp_m + (i >> 1) * 16 + (i & 1) * 8 + (lane >> 2);
            sval[row][wid & 3] = v;
            sidx[row][wid & 3] = c;
        }
    }
    __syncthreads();
    if (tid < 128) {
        float v = sval[tid][0]; int c = sidx[tid][0];
#pragma unroll
        for (int w = 1; w < 4; w++) {
            float ov = sval[tid][w]; int oc = sidx[tid][w];
            if (ov > v || (ov == v && oc < c)) { v = ov; c = oc; }
        }
        idx_out[m0 + tid] = c;
    }
}

// ---------------- scatter / dict update / softmax / loss -------------------
__global__ __launch_bounds__(256)
void scatter_kernel(const float* __restrict__ NN_, const int* __restrict__ idx) {
    const int r = blockIdx.x, tid = threadIdx.x;
    const int ig = idx[r];
    const int il = NGD + idx[NROWS + r];
    float4 v = *reinterpret_cast<const float4*>(&NN_[(size_t)r * DDIM + tid * 4]);
    float* sg = &g_sums[(size_t)ig * DDIM + tid * 4];
    float* sl = &g_sums[(size_t)il * DDIM + tid * 4];
    atomicAdd(sg + 0, v.x); atomicAdd(sg + 1, v.y); atomicAdd(sg + 2, v.z); atomicAdd(sg + 3, v.w);
    atomicAdd(sl + 0, v.x); atomicAdd(sl + 1, v.y); atomicAdd(sl + 2, v.z); atomicAdd(sl + 3, v.w);
    if (tid == 0) { atomicAdd(&g_cnts[ig], 1.f); atomicAdd(&g_cnts[il], 1.f); }
}

__global__ __launch_bounds__(256)
void dictupd_kernel(const float* __restrict__ gd, const float* __restrict__ ld,
                    bf* __restrict__ ch, bf* __restrict__ cl) {
    __shared__ float red[8];
    const int c = blockIdx.x, tid = threadIdx.x;
    const float* dsrc = (c < NGD) ? (gd + (size_t)c * DDIM) : (ld + (size_t)(c - NGD) * DDIM);
    const float m = (c < NGD) ? 0.999f : 0.8f;
    const float cnt = g_cnts[c];
    float4 d  = *reinterpret_cast<const float4*>(&dsrc[tid * 4]);
    float4 sm = *reinterpret_cast<const float4*>(&g_sums[(size_t)c * DDIM + tid * 4]);
    float u0, u1, u2, u3;
    if (cnt > 0.f) {
        float w = (1.f - m) / cnt;
        u0 = m * d.x + w * sm.x; u1 = m * d.y + w * sm.y;
        u2 = m * d.z + w * sm.z; u3 = m * d.w + w * sm.w;
    } else { u0 = d.x; u1 = d.y; u2 = d.z; u3 = d.w; }
    float ss = u0 * u0 + u1 * u1 + u2 * u2 + u3 * u3;
#pragma unroll
    for (int off = 16; off; off >>= 1) ss += __shfl_down_sync(0xffffffffu, ss, off);
    if ((tid & 31) == 0) red[tid >> 5] = ss;
    __syncthreads();
    if (tid == 0) {
        float s = 0.f;
#pragma unroll
        for (int i = 0; i < 8; i++) s += red[i];
        red[0] = s;
    }
    __syncthreads();
    float inv = 1.f / fmaxf(sqrtf(red[0]), 1e-12f);
    float f[4] = {u0 * inv, u1 * inv, u2 * inv, u3 * inv};
    size_t o = (size_t)c * DDIM + tid * 4;
    *reinterpret_cast<float4*>(&g_comb[o]) = make_float4(f[0], f[1], f[2], f[3]);
    bf h[4], l[4];
#pragma unroll
    for (int i = 0; i < 4; i++) split2(f[i], h[i], l[i]);
    *reinterpret_cast<uint2*>(&ch[o]) = *reinterpret_cast<uint2*>(h);
    *reinterpret_cast<uint2*>(&cl[o]) = *reinterpret_cast<uint2*>(l);
}

__global__ __launch_bounds__(256)
void softmax_split_kernel(const float* __restrict__ S, bf* __restrict__ Wh,
                          bf* __restrict__ Wl) {
    __shared__ float red[8];
    const int r = blockIdx.x, tid = threadIdx.x;
    const float* s = S + (size_t)r * NCOMB;
    float v[5];
#pragma unroll
    for (int i = 0; i < 5; i++) v[i] = s[tid + i * 256];
    float mx = v[0];
#pragma unroll
    for (int i = 1; i < 5; i++) mx = fmaxf(mx, v[i]);
#pragma unroll
    for (int off = 16; off; off >>= 1) mx = fmaxf(mx, __shfl_down_sync(0xffffffffu, mx, off));
    if ((tid & 31) == 0) red[tid >> 5] = mx;
    __syncthreads();
    if (tid == 0) {
        float t = red[0];
#pragma unroll
        for (int i = 1; i < 8; i++) t = fmaxf(t, red[i]);
        red[0] = t;
    }
    __syncthreads();
    mx = red[0];
    __syncthreads();
    float ssum = 0.f;
#pragma unroll
    for (int i = 0; i < 5; i++) { v[i] = expf((v[i] - mx) * (1.f / 0.07f)); ssum += v[i]; }
#pragma unroll
    for (int off = 16; off; off >>= 1) ssum += __shfl_down_sync(0xffffffffu, ssum, off);
    if ((tid & 31) == 0) red[tid >> 5] = ssum;
    __syncthreads();
    if (tid == 0) {
        float t = 0.f;
#pragma unroll
        for (int i = 0; i < 8; i++) t += red[i];
        red[0] = t;
    }
    __syncthreads();
    float inv = 1.f / red[0];
#pragma unroll
    for (int i = 0; i < 5; i++) {
        bf h, l;
        split2(v[i] * inv, h, l);
        Wh[(size_t)r * NCOMB + tid + i * 256] = h;
        Wl[(size_t)r * NCOMB + tid + i * 256] = l;
    }
}

__global__ __launch_bounds__(256)
void dotabs_kernel(const float* __restrict__ ZN, const float* __restrict__ UN) {
    __shared__ float red[8];
    const int r = blockIdx.x, tid = threadIdx.x;
    float4 a = *reinterpret_cast<const float4*>(&ZN[(size_t)r * DDIM + tid * 4]);
    float4 b = *reinterpret_cast<const float4*>(&UN[(size_t)r * DDIM + tid * 4]);
    float p = a.x * b.x + a.y * b.y + a.z * b.z + a.w * b.w;
#pragma unroll
    for (int off = 16; off; off >>= 1) p += __shfl_down_sync(0xffffffffu, p, off);
    if ((tid & 31) == 0) red[tid >> 5] = p;
    __syncthreads();
    if (tid == 0) {
        float s = 0.f;
#pragma unroll
        for (int i = 0; i < 8; i++) s += red[i];
        atomicAdd(&g_acc[2], (double)fabsf(s));
    }
}

__global__ void finalize_kernel(float* out_loss) {
    *out_loss = (float)(g_acc[0] / ((double)NROWS * (double)NGD) +
                        g_acc[1] / ((double)NROWS * (double)NLD) +
                        g_acc[2] / (double)NROWS);
}

// ---------------- launch ----------------------------------------------------
extern "C" void kernel_launch(void* const* d_in, const int* in_sizes, int n_in,
                              void* d_out, int out_size) {
    const float* z  = (const float*)d_in[0];
    const float* u  = (const float*)d_in[1];
    const float* W1 = (const float*)d_in[2];
    const float* b1 = (const float*)d_in[3];
    const float* W2 = (const float*)d_in[4];
    const float* b2 = (const float*)d_in[5];
    const float* Wg = (const float*)d_in[6];
    const float* bg = (const float*)d_in[7];
    const float* gd = (const float*)d_in[8];
    const float* ld = (const float*)d_in[9];

    float* out       = (float*)d_out;
    float* out_zc    = out;
    float* out_loss  = out + (size_t)NROWS * DDIM;
    float* out_zproj = out_loss + 1;
    float* out_u     = out_zproj + (size_t)NROWS * DDIM;

    static float *p_zp = nullptr, *p_nn, *p_zn, *p_gate, *p_S, *p_comb;
    static int* p_idx;
    static bf *zb, *hb, *zpb, *nnb, *znb, *Sb, *W1T, *W2T, *WgT, *gdb, *ldb, *cbb, *ctb;
    static size_t szNM, szNS, szDD, szGD, szLD, szCB;
    if (!p_zp) {
        cudaGetSymbolAddress((void**)&p_zp, g_zp);
        cudaGetSymbolAddress((void**)&p_nn, g_nn);
        cudaGetSymbolAddress((void**)&p_zn, g_zn);
        cudaGetSymbolAddress((void**)&p_gate, g_gate);
        cudaGetSymbolAddress((void**)&p_S, g_S);
        cudaGetSymbolAddress((void**)&p_comb, g_comb);
        cudaGetSymbolAddress((void**)&p_idx, g_idx);
        cudaGetSymbolAddress((void**)&zb, b_z);
        cudaGetSymbolAddress((void**)&hb, b_h);
        cudaGetSymbolAddress((void**)&zpb, b_zp);
        cudaGetSymbolAddress((void**)&nnb, b_nn);
        cudaGetSymbolAddress((void**)&znb, b_zn);
        cudaGetSymbolAddress((void**)&Sb, b_S);
        cudaGetSymbolAddress((void**)&W1T, b_W1T);
        cudaGetSymbolAddress((void**)&W2T, b_W2T);
        cudaGetSymbolAddress((void**)&WgT, b_WgT);
        cudaGetSymbolAddress((void**)&gdb, b_gd);
        cudaGetSymbolAddress((void**)&ldb, b_ld);
        cudaGetSymbolAddress((void**)&cbb, b_comb);
        cudaGetSymbolAddress((void**)&ctb, b_combT);
        szNM = NM; szNS = (size_t)NROWS * NCOMB; szDD = DDIM * DDIM;
        szGD = NGD * DDIM; szLD = NLD * DDIM; szCB = NCOMB * DDIM;
    }

    init_kernel<<<(NCOMB * DDIM) / 256, 256>>>();

    // input conversions
    conv_split_kernel<<<NM / 1024, 256>>>(z, zb, zb + szNM, NM);
    conv_split_kernel<<<(NGD * DDIM) / 1024, 256>>>(gd, gdb, gdb + szGD, NGD * DDIM);
    conv_split_kernel<<<(NLD * DDIM) / 1024, 256>>>(ld, ldb, ldb + szLD, NLD * DDIM);
    transconv_kernel<<<dim3(DDIM / 32, DDIM / 32), 256>>>(W1, DDIM, DDIM, W1T, W1T + szDD);
    transconv_kernel<<<dim3(DDIM / 32, DDIM / 32), 256>>>(W2, DDIM, DDIM, W2T, W2T + szDD);
    transconv_kernel<<<dim3(DDIM / 32, DDIM / 32), 256>>>(Wg, DDIM, DDIM, WgT, WgT + szDD);

    rownorm_split_kernel<<<NROWS, 256>>>(u, p_nn, nnb, nnb + szNM);

    const dim3 gD(DDIM / 128, NROWS / 128);
    // projector
    gemm_mma<EPI_RELU_BIAS, false, true><<<gD, 256>>>(
        zb, zb + szNM, W1T, W1T + szDD, b1, nullptr, hb, hb + szNM, DDIM, DDIM,
        nullptr, nullptr);
    gemm_mma<EPI_BIAS, true, true><<<gD, 256>>>(
        hb, hb + szNM, W2T, W2T + szDD, b2, p_zp, zpb, zpb + szNM, DDIM, DDIM,
        nullptr, nullptr);

    rownorm_split_kernel<<<NROWS, 256>>>(p_zp, p_zn, znb, znb + szNM);

    // gate
    gemm_mma<EPI_SIGMOID, true, false><<<gD, 256>>>(
        zpb, zpb + szNM, WgT, WgT + szDD, bg, p_gate, nullptr, nullptr, DDIM, DDIM,
        nullptr, nullptr);

    // dict assignment + EMA update
    argmax_mma<<<NROWS / 128, 256>>>(nnb, nnb + szNM, gdb, gdb + szGD, NGD, p_idx);
    argmax_mma<<<NROWS / 128, 256>>>(nnb, nnb + szNM, ldb, ldb + szLD, NLD, p_idx + NROWS);
    scatter_kernel<<<NROWS, 256>>>(p_nn, p_idx);
    dictupd_kernel<<<NCOMB, 256>>>(gd, ld, cbb, cbb + szCB);

    // S = z_norm @ comb^T (+ fused sum|S| for loss_g / loss_l)
    gemm_mma<EPI_S_LOSS, true, false><<<dim3(NCOMB / 128, NROWS / 128), 256>>>(
        znb, znb + szNM, cbb, cbb + szCB, nullptr, p_S, nullptr, nullptr, NCOMB, DDIM,
        nullptr, nullptr);

    softmax_split_kernel<<<NROWS, 256>>>(p_S, Sb, Sb + szNS);
    transconv_kernel<<<dim3(DDIM / 32, NCOMB / 32), 256>>>(p_comb, NCOMB, DDIM, ctb, ctb + szCB);

    // weighted_u + fused z_clean epilogue
    gemm_mma<EPI_ZCLEAN, true, false><<<gD, 256>>>(
        Sb, Sb + szNS, ctb, ctb + szCB, nullptr, out_zc, nullptr, nullptr, DDIM, NCOMB,
        z, p_gate);

    dotabs_kernel<<<NROWS, 256>>>(p_zn, p_nn);
    finalize_kernel<<<1, 1>>>(out_loss);

    copy_kernel<<<NM / 1024, 256>>>(p_zp, out_zproj, NM);
    copy_kernel<<<NM / 1024, 256>>>(u, out_u, NM);
}

// round 7
// speedup vs baseline: 2.5299x; 1.1117x over previous
#include <cuda_runtime.h>
#include <cuda_bf16.h>
#include <math.h>
#include <stdint.h>

#define NROWS 32768
#define DDIM  1024
#define NGD   1024
#define NLD   256
#define NCOMB 1280
#define NM    (NROWS * DDIM)

typedef __nv_bfloat16 bf;

// ---------------- warp MMA primitives (plain sm_80+ PTX, no 'a' features) --
__device__ __forceinline__ uint32_t smem_u32(const void* p) {
    uint32_t a;
    asm("{ .reg .u64 t; cvta.to.shared.u64 t, %1; cvt.u32.u64 %0, t; }" : "=r"(a) : "l"(p));
    return a;
}
__device__ __forceinline__ void ldsm4(uint32_t addr, uint32_t* f) {
    asm volatile("ldmatrix.sync.aligned.m8n8.x4.shared.b16 {%0,%1,%2,%3}, [%4];"
                 : "=r"(f[0]), "=r"(f[1]), "=r"(f[2]), "=r"(f[3]) : "r"(addr));
}
__device__ __forceinline__ void mma16816(float* c, const uint32_t* a, uint32_t b0, uint32_t b1) {
    asm volatile("mma.sync.aligned.m16n8k16.row.col.f32.bf16.bf16.f32 "
                 "{%0,%1,%2,%3}, {%4,%5,%6,%7}, {%8,%9}, {%0,%1,%2,%3};"
                 : "+f"(c[0]), "+f"(c[1]), "+f"(c[2]), "+f"(c[3])
                 : "r"(a[0]), "r"(a[1]), "r"(a[2]), "r"(a[3]), "r"(b0), "r"(b1));
}
__device__ __forceinline__ void cp16(uint32_t dst, const void* src) {
    asm volatile("cp.async.cg.shared.global [%0], [%1], 16;" :: "r"(dst), "l"(src));
}
#define CP_COMMIT() asm volatile("cp.async.commit_group;" ::: "memory")
#define CP_WAIT(n)  asm volatile("cp.async.wait_group %0;" :: "n"(n) : "memory")

__device__ __forceinline__ void split2(float x, bf& h, bf& l) {
    h = __float2bfloat16(x);
    l = __float2bfloat16(x - __bfloat162float(h));
}

// ---------------- scratch ---------------------------------------------------
__device__ float  g_zp[NM];
__device__ float  g_nn[NM];
__device__ float  g_zn[NM];
__device__ float  g_gate[NM];
__device__ float  g_S[(size_t)NROWS * NCOMB];
__device__ float  g_comb[NCOMB * DDIM];
__device__ float  g_sums[NCOMB * DDIM];
__device__ float  g_cnts[NCOMB];
__device__ int    g_idx[2 * NROWS];
__device__ double g_acc[3];

__device__ bf b_z[2][NM];
__device__ bf b_h[2][NM];
__device__ bf b_zp[2][NM];
__device__ bf b_nn[2][NM];
__device__ bf b_zn[2][NM];
__device__ bf b_S[2][(size_t)NROWS * NCOMB];
__device__ bf b_W1T[2][DDIM * DDIM];
__device__ bf b_W2T[2][DDIM * DDIM];
__device__ bf b_WgT[2][DDIM * DDIM];
__device__ bf b_gd[2][NGD * DDIM];
__device__ bf b_ld[2][NLD * DDIM];
__device__ bf b_comb[2][NCOMB * DDIM];
__device__ bf b_combT[2][DDIM * NCOMB];

// ---------------- small kernels --------------------------------------------
__global__ void init_kernel() {
    int i = blockIdx.x * blockDim.x + threadIdx.x;
    if (i < NCOMB * DDIM) g_sums[i] = 0.f;
    if (i < NCOMB)        g_cnts[i] = 0.f;
    if (i < 3)            g_acc[i]  = 0.0;
}

__global__ __launch_bounds__(256)
void conv_split_kernel(const float* __restrict__ src, bf* __restrict__ dh,
                       bf* __restrict__ dl, int n) {
    int i = (blockIdx.x * blockDim.x + threadIdx.x) * 4;
    if (i + 3 < n) {
        float4 v = *reinterpret_cast<const float4*>(&src[i]);
        bf h[4], l[4];
        split2(v.x, h[0], l[0]); split2(v.y, h[1], l[1]);
        split2(v.z, h[2], l[2]); split2(v.w, h[3], l[3]);
        *reinterpret_cast<uint2*>(&dh[i]) = *reinterpret_cast<uint2*>(h);
        *reinterpret_cast<uint2*>(&dl[i]) = *reinterpret_cast<uint2*>(l);
    }
}

// tiled transpose + split: src [R][C] fp32 -> dst [c][r] bf16 hi/lo
__global__ __launch_bounds__(256)
void transconv_kernel(const float* __restrict__ src, int R, int C,
                      bf* __restrict__ dh, bf* __restrict__ dl) {
    __shared__ float t[32][33];
    const int bx = blockIdx.x * 32, by = blockIdx.y * 32;
    const int tx = threadIdx.x & 31, ty = threadIdx.x >> 5;
#pragma unroll
    for (int i = 0; i < 4; i++)
        t[ty + 8 * i][tx] = src[(size_t)(by + ty + 8 * i) * C + bx + tx];
    __syncthreads();
#pragma unroll
    for (int i = 0; i < 4; i++) {
        float x = t[tx][ty + 8 * i];
        bf h, l; split2(x, h, l);
        size_t o = (size_t)(bx + ty + 8 * i) * R + by + tx;
        dh[o] = h; dl[o] = l;
    }
}

// row L2 normalize; write fp32 + bf16 hi/lo (+ optional raw copy to misaligned dst)
__global__ __launch_bounds__(256)
void rownorm_split_kernel(const float* __restrict__ X, float* __restrict__ Y,
                          bf* __restrict__ Yh, bf* __restrict__ Yl,
                          float* __restrict__ Cpy) {
    __shared__ float red[8];
    const int r = blockIdx.x, tid = threadIdx.x;
    float4 x = *reinterpret_cast<const float4*>(&X[(size_t)r * DDIM + tid * 4]);
    float ss = x.x * x.x + x.y * x.y + x.z * x.z + x.w * x.w;
#pragma unroll
    for (int off = 16; off; off >>= 1) ss += __shfl_down_sync(0xffffffffu, ss, off);
    if ((tid & 31) == 0) red[tid >> 5] = ss;
    __syncthreads();
    if (tid == 0) {
        float s = 0.f;
#pragma unroll
        for (int i = 0; i < 8; i++) s += red[i];
        red[0] = s;
    }
    __syncthreads();
    float inv = 1.f / fmaxf(sqrtf(red[0]), 1e-12f);
    float f[4] = {x.x * inv, x.y * inv, x.z * inv, x.w * inv};
    size_t o = (size_t)r * DDIM + tid * 4;
    *reinterpret_cast<float4*>(&Y[o]) = make_float4(f[0], f[1], f[2], f[3]);
    bf h[4], l[4];
#pragma unroll
    for (int i = 0; i < 4; i++) split2(f[i], h[i], l[i]);
    *reinterpret_cast<uint2*>(&Yh[o]) = *reinterpret_cast<uint2*>(h);
    *reinterpret_cast<uint2*>(&Yl[o]) = *reinterpret_cast<uint2*>(l);
    if (Cpy) { Cpy[o] = x.x; Cpy[o + 1] = x.y; Cpy[o + 2] = x.z; Cpy[o + 3] = x.w; }
}

// ---------------- HMMA GEMM (cp.async double-buffered) ----------------------
// Block 128x128, 8 warps 2x4 (warp = 64x32), K-chunk 32, smem [128][40] bf16 x4 x2buf
enum { EPI_RELU_BIAS = 0, EPI_BIAS = 1, EPI_SIGMOID = 2, EPI_S_LOSS = 3, EPI_ZCLEAN = 4 };

#define TPAD 40
#define TILE_BYTES (128 * TPAD * 2)   // 10240
#define BUF_BYTES  (4 * TILE_BYTES)   // 40960 per stage
#define SM_TOTAL   (2 * BUF_BYTES)    // 81920

// issue cp.async fill of one K-chunk for all 4 tiles into stage b
__device__ __forceinline__ void fill_async(
    uint32_t sb, int b,
    const bf* __restrict__ Ah, const bf* __restrict__ Al,
    const bf* __restrict__ Bh, const bf* __restrict__ Bl,
    int m0, int n0, int k0, int K, int tid) {
    const int row = tid >> 2, c8 = (tid & 3) << 3;
    const int row2 = row + 64;
    const uint32_t soff = row * (TPAD * 2) + c8 * 2;
    const uint32_t soff2 = row2 * (TPAD * 2) + c8 * 2;
    const uint32_t base = sb + b * BUF_BYTES;
#pragma unroll
    for (int t = 0; t < 4; t++) {
        const bf* gp = (t == 0) ? Ah : (t == 1) ? Al : (t == 2) ? Bh : Bl;
        const int rb = (t < 2) ? m0 : n0;
        const uint32_t tb = base + t * TILE_BYTES;
        cp16(tb + soff,  gp + (size_t)(rb + row)  * K + k0 + c8);
        cp16(tb + soff2, gp + (size_t)(rb + row2) * K + k0 + c8);
    }
    CP_COMMIT();
}

// 3-product hi/lo compute of one K-chunk into acc[4][4][4]
__device__ __forceinline__ void chunk_mma(float acc[4][4][4], uint32_t base,
                                          int aoff, int boff) {
    const uint32_t aH = base + aoff, aL = base + TILE_BYTES + aoff;
    const uint32_t bH = base + 2 * TILE_BYTES + boff, bL = base + 3 * TILE_BYTES + boff;
#pragma unroll
    for (int ks = 0; ks < 2; ks++) {
        const int kb = ks * 32;
        uint32_t bh[8], bl[8];
        ldsm4(bH + kb, bh); ldsm4(bH + 16 * (TPAD * 2) + kb, bh + 4);
        ldsm4(bL + kb, bl); ldsm4(bL + 16 * (TPAD * 2) + kb, bl + 4);
#pragma unroll
        for (int mt = 0; mt < 4; mt++) {
            uint32_t ah[4], al[4];
            ldsm4(aH + mt * 16 * (TPAD * 2) + kb, ah);
            ldsm4(aL + mt * 16 * (TPAD * 2) + kb, al);
#pragma unroll
            for (int nt = 0; nt < 4; nt++) {
                mma16816(acc[mt][nt], ah, bh[2 * nt], bh[2 * nt + 1]);
                mma16816(acc[mt][nt], ah, bl[2 * nt], bl[2 * nt + 1]);
                mma16816(acc[mt][nt], al, bh[2 * nt], bh[2 * nt + 1]);
            }
        }
    }
}

template <int EPI, bool WF32, bool WSPLIT, bool WMIS>
__global__ __launch_bounds__(256)
void gemm_mma(const bf* __restrict__ Ah, const bf* __restrict__ Al,
              const bf* __restrict__ Bh, const bf* __restrict__ Bl,
              const float* __restrict__ bias, float* __restrict__ Cf,
              bf* __restrict__ Ch, bf* __restrict__ Cl, float* __restrict__ Cm,
              int Ncols, int K,
              const float* __restrict__ e1, const float* __restrict__ e2) {
    extern __shared__ __align__(16) char smem[];
    const uint32_t sb = smem_u32(smem);
    const int tid = threadIdx.x, lane = tid & 31, wid = tid >> 5;
    const int m0 = blockIdx.y * 128, n0 = blockIdx.x * 128;
    const int warp_m = (wid >> 2) * 64, warp_n = (wid & 3) * 32;

    const int aoff = (warp_m + (lane & 15)) * (TPAD * 2) + ((lane >> 4) << 3) * 2;
    const int boff = (warp_n + ((lane & 7) | ((lane >> 4) << 3))) * (TPAD * 2) +
                     (((lane >> 3) & 1) << 3) * 2;

    float acc[4][4][4] = {};

    const int nch = K >> 5;
    fill_async(sb, 0, Ah, Al, Bh, Bl, m0, n0, 0, K, tid);
    for (int kc = 0; kc < nch; kc++) {
        if (kc + 1 < nch)
            fill_async(sb, (kc + 1) & 1, Ah, Al, Bh, Bl, m0, n0, (kc + 1) << 5, K, tid);
        if (kc + 1 < nch) { CP_WAIT(1); } else { CP_WAIT(0); }
        __syncthreads();
        chunk_mma(acc, sb + (kc & 1) * BUF_BYTES, aoff, boff);
        __syncthreads();
    }

    // ---------------- epilogue ----------------
    double part = 0.0;
#pragma unroll
    for (int mt = 0; mt < 4; mt++) {
        const int r0 = m0 + warp_m + mt * 16 + (lane >> 2);
#pragma unroll
        for (int nt = 0; nt < 4; nt++) {
            const int col = n0 + warp_n + nt * 8 + ((lane & 3) << 1);
            float b2x = 0.f, b2y = 0.f;
            if (EPI == EPI_RELU_BIAS || EPI == EPI_BIAS || EPI == EPI_SIGMOID) {
                float2 bb = *reinterpret_cast<const float2*>(bias + col);
                b2x = bb.x; b2y = bb.y;
            }
#pragma unroll
            for (int h = 0; h < 2; h++) {
                const int row = r0 + h * 8;
                float v0 = acc[mt][nt][2 * h], v1 = acc[mt][nt][2 * h + 1];
                if (EPI == EPI_RELU_BIAS) { v0 = fmaxf(v0 + b2x, 0.f); v1 = fmaxf(v1 + b2y, 0.f); }
                else if (EPI == EPI_BIAS) { v0 += b2x; v1 += b2y; }
                else if (EPI == EPI_SIGMOID) {
                    v0 = 1.f / (1.f + expf(-(v0 + b2x)));
                    v1 = 1.f / (1.f + expf(-(v1 + b2y)));
                }
                const size_t ro = (size_t)row * Ncols + col;
                if (EPI == EPI_ZCLEAN) {
                    float2 z2 = *reinterpret_cast<const float2*>(e1 + ro);
                    float2 q2 = *reinterpret_cast<const float2*>(e2 + ro);
                    v0 = z2.x - q2.x * v0;
                    v1 = z2.y - q2.y * v1;
                }
                if (EPI == EPI_S_LOSS) part += (double)fabsf(v0) + (double)fabsf(v1);
                if (WF32)
                    *reinterpret_cast<float2*>(Cf + ro) = make_float2(v0, v1);
                if (WMIS) { Cm[ro] = v0; Cm[ro + 1] = v1; }
                if (WSPLIT) {
                    bf h0, l0, h1, l1;
                    split2(v0, h0, l0); split2(v1, h1, l1);
                    bf hp[2] = {h0, h1}, lp[2] = {l0, l1};
                    *reinterpret_cast<uint32_t*>(Ch + ro) = *reinterpret_cast<uint32_t*>(hp);
                    *reinterpret_cast<uint32_t*>(Cl + ro) = *reinterpret_cast<uint32_t*>(lp);
                }
            }
        }
    }
    if (EPI == EPI_S_LOSS) {
#pragma unroll
        for (int off = 16; off; off >>= 1) part += __shfl_down_sync(0xffffffffu, part, off);
        if (lane == 0) atomicAdd(&g_acc[(n0 < NGD) ? 0 : 1], part);
    }
}

// ---------------- HMMA sim + per-row argmax --------------------------------
__global__ __launch_bounds__(256)
void argmax_mma(const bf* __restrict__ Ah, const bf* __restrict__ Al,
                const bf* __restrict__ Dh, const bf* __restrict__ Dl,
                int ncodes, int* __restrict__ idx_out) {
    extern __shared__ __align__(16) char smem[];
    __shared__ float sval[128][4];
    __shared__ int   sidx[128][4];
    const uint32_t sb = smem_u32(smem);
    const int tid = threadIdx.x, lane = tid & 31, wid = tid >> 5;
    const int m0 = blockIdx.x * 128;
    const int warp_m = (wid >> 2) * 64, warp_n = (wid & 3) * 32;

    const int aoff = (warp_m + (lane & 15)) * (TPAD * 2) + ((lane >> 4) << 3) * 2;
    const int boff = (warp_n + ((lane & 7) | ((lane >> 4) << 3))) * (TPAD * 2) +
                     (((lane >> 3) & 1) << 3) * 2;

    float bv[8]; int bi[8];
#pragma unroll
    for (int i = 0; i < 8; i++) { bv[i] = -1e30f; bi[i] = 0; }

    for (int n0 = 0; n0 < ncodes; n0 += 128) {
        float acc[4][4][4] = {};
        const int nch = DDIM >> 5;
        fill_async(sb, 0, Ah, Al, Dh, Dl, m0, n0, 0, DDIM, tid);
        for (int kc = 0; kc < nch; kc++) {
            if (kc + 1 < nch)
                fill_async(sb, (kc + 1) & 1, Ah, Al, Dh, Dl, m0, n0, (kc + 1) << 5, DDIM, tid);
            if (kc + 1 < nch) { CP_WAIT(1); } else { CP_WAIT(0); }
            __syncthreads();
            chunk_mma(acc, sb + (kc & 1) * BUF_BYTES, aoff, boff);
            __syncthreads();
        }
#pragma unroll
        for (int mt = 0; mt < 4; mt++)
#pragma unroll
            for (int h = 0; h < 2; h++) {
                float* bvp = &bv[mt * 2 + h]; int* bip = &bi[mt * 2 + h];
#pragma unroll
                for (int nt = 0; nt < 4; nt++) {
                    const int col = n0 + warp_n + nt * 8 + ((lane & 3) << 1);
                    float v0 = acc[mt][nt][2 * h], v1 = acc[mt][nt][2 * h + 1];
                    if (v0 > *bvp) { *bvp = v0; *bip = col; }
                    if (v1 > *bvp) { *bvp = v1; *bip = col + 1; }
                }
            }
    }
#pragma unroll
    for (int i = 0; i < 8; i++) {
        float v = bv[i]; int c = bi[i];
#pragma unroll
        for (int off = 1; off <= 2; off <<= 1) {
            float ov = __shfl_xor_sync(0xffffffffu, v, off);
            int   oc = __shfl_xor_sync(0xffffffffu, c, off);
            if (ov > v || (ov == v && oc < c)) { v = ov; c = oc; }
        }
        if ((lane & 3) == 0) {
            int row = warp_m + (i >> 1) * 16 + (i & 1) * 8 + (lane >> 2);
            sval[row][wid & 3] = v;
            sidx[row][wid & 3] = c;
        }
    }
    __syncthreads();
    if (tid < 128) {
        float v = sval[tid][0]; int c = sidx[tid][0];
#pragma unroll
        for (int w = 1; w < 4; w++) {
            float ov = sval[tid][w]; int oc = sidx[tid][w];
            if (ov > v || (ov == v && oc < c)) { v = ov; c = oc; }
        }
        idx_out[m0 + tid] = c;
    }
}

// ---------------- scatter / dict update / softmax / loss -------------------
__global__ __launch_bounds__(256)
void scatter_kernel(const float* __restrict__ NN_, const int* __restrict__ idx) {
    const int r = blockIdx.x, tid = threadIdx.x;
    const int ig = idx[r];
    const int il = NGD + idx[NROWS + r];
    float4 v = *reinterpret_cast<const float4*>(&NN_[(size_t)r * DDIM + tid * 4]);
    float* sg = &g_sums[(size_t)ig * DDIM + tid * 4];
    float* sl = &g_sums[(size_t)il * DDIM + tid * 4];
    atomicAdd(sg + 0, v.x); atomicAdd(sg + 1, v.y); atomicAdd(sg + 2, v.z); atomicAdd(sg + 3, v.w);
    atomicAdd(sl + 0, v.x); atomicAdd(sl + 1, v.y); atomicAdd(sl + 2, v.z); atomicAdd(sl + 3, v.w);
    if (tid == 0) { atomicAdd(&g_cnts[ig], 1.f); atomicAdd(&g_cnts[il], 1.f); }
}

__global__ __launch_bounds__(256)
void dictupd_kernel(const float* __restrict__ gd, const float* __restrict__ ld,
                    bf* __restrict__ ch, bf* __restrict__ cl) {
    __shared__ float red[8];
    const int c = blockIdx.x, tid = threadIdx.x;
    const float* dsrc = (c < NGD) ? (gd + (size_t)c * DDIM) : (ld + (size_t)(c - NGD) * DDIM);
    const float m = (c < NGD) ? 0.999f : 0.8f;
    const float cnt = g_cnts[c];
    float4 d  = *reinterpret_cast<const float4*>(&dsrc[tid * 4]);
    float4 sm = *reinterpret_cast<const float4*>(&g_sums[(size_t)c * DDIM + tid * 4]);
    float u0, u1, u2, u3;
    if (cnt > 0.f) {
        float w = (1.f - m) / cnt;
        u0 = m * d.x + w * sm.x; u1 = m * d.y + w * sm.y;
        u2 = m * d.z + w * sm.z; u3 = m * d.w + w * sm.w;
    } else { u0 = d.x; u1 = d.y; u2 = d.z; u3 = d.w; }
    float ss = u0 * u0 + u1 * u1 + u2 * u2 + u3 * u3;
#pragma unroll
    for (int off = 16; off; off >>= 1) ss += __shfl_down_sync(0xffffffffu, ss, off);
    if ((tid & 31) == 0) red[tid >> 5] = ss;
    __syncthreads();
    if (tid == 0) {
        float s = 0.f;
#pragma unroll
        for (int i = 0; i < 8; i++) s += red[i];
        red[0] = s;
    }
    __syncthreads();
    float inv = 1.f / fmaxf(sqrtf(red[0]), 1e-12f);
    float f[4] = {u0 * inv, u1 * inv, u2 * inv, u3 * inv};
    size_t o = (size_t)c * DDIM + tid * 4;
    *reinterpret_cast<float4*>(&g_comb[o]) = make_float4(f[0], f[1], f[2], f[3]);
    bf h[4], l[4];
#pragma unroll
    for (int i = 0; i < 4; i++) split2(f[i], h[i], l[i]);
    *reinterpret_cast<uint2*>(&ch[o]) = *reinterpret_cast<uint2*>(h);
    *reinterpret_cast<uint2*>(&cl[o]) = *reinterpret_cast<uint2*>(l);
}

__global__ __launch_bounds__(256)
void softmax_split_kernel(const float* __restrict__ S, bf* __restrict__ Wh,
                          bf* __restrict__ Wl) {
    __shared__ float red[8];
    const int r = blockIdx.x, tid = threadIdx.x;
    const float* s = S + (size_t)r * NCOMB;
    float v[5];
#pragma unroll
    for (int i = 0; i < 5; i++) v[i] = s[tid + i * 256];
    float mx = v[0];
#pragma unroll
    for (int i = 1; i < 5; i++) mx = fmaxf(mx, v[i]);
#pragma unroll
    for (int off = 16; off; off >>= 1) mx = fmaxf(mx, __shfl_down_sync(0xffffffffu, mx, off));
    if ((tid & 31) == 0) red[tid >> 5] = mx;
    __syncthreads();
    if (tid == 0) {
        float t = red[0];
#pragma unroll
        for (int i = 1; i < 8; i++) t = fmaxf(t, red[i]);
        red[0] = t;
    }
    __syncthreads();
    mx = red[0];
    __syncthreads();
    float ssum = 0.f;
#pragma unroll
    for (int i = 0; i < 5; i++) { v[i] = expf((v[i] - mx) * (1.f / 0.07f)); ssum += v[i]; }
#pragma unroll
    for (int off = 16; off; off >>= 1) ssum += __shfl_down_sync(0xffffffffu, ssum, off);
    if ((tid & 31) == 0) red[tid >> 5] = ssum;
    __syncthreads();
    if (tid == 0) {
        float t = 0.f;
#pragma unroll
        for (int i = 0; i < 8; i++) t += red[i];
        red[0] = t;
    }
    __syncthreads();
    float inv = 1.f / red[0];
#pragma unroll
    for (int i = 0; i < 5; i++) {
        bf h, l;
        split2(v[i] * inv, h, l);
        Wh[(size_t)r * NCOMB + tid + i * 256] = h;
        Wl[(size_t)r * NCOMB + tid + i * 256] = l;
    }
}

__global__ __launch_bounds__(256)
void dotabs_kernel(const float* __restrict__ ZN, const float* __restrict__ UN) {
    __shared__ float red[8];
    const int r = blockIdx.x, tid = threadIdx.x;
    float4 a = *reinterpret_cast<const float4*>(&ZN[(size_t)r * DDIM + tid * 4]);
    float4 b = *reinterpret_cast<const float4*>(&UN[(size_t)r * DDIM + tid * 4]);
    float p = a.x * b.x + a.y * b.y + a.z * b.z + a.w * b.w;
#pragma unroll
    for (int off = 16; off; off >>= 1) p += __shfl_down_sync(0xffffffffu, p, off);
    if ((tid & 31) == 0) red[tid >> 5] = p;
    __syncthreads();
    if (tid == 0) {
        float s = 0.f;
#pragma unroll
        for (int i = 0; i < 8; i++) s += red[i];
        atomicAdd(&g_acc[2], (double)fabsf(s));
    }
}

__global__ void finalize_kernel(float* out_loss) {
    *out_loss = (float)(g_acc[0] / ((double)NROWS * (double)NGD) +
                        g_acc[1] / ((double)NROWS * (double)NLD) +
                        g_acc[2] / (double)NROWS);
}

// ---------------- launch ----------------------------------------------------
extern "C" void kernel_launch(void* const* d_in, const int* in_sizes, int n_in,
                              void* d_out, int out_size) {
    const float* z  = (const float*)d_in[0];
    const float* u  = (const float*)d_in[1];
    const float* W1 = (const float*)d_in[2];
    const float* b1 = (const float*)d_in[3];
    const float* W2 = (const float*)d_in[4];
    const float* b2 = (const float*)d_in[5];
    const float* Wg = (const float*)d_in[6];
    const float* bg = (const float*)d_in[7];
    const float* gd = (const float*)d_in[8];
    const float* ld = (const float*)d_in[9];

    float* out       = (float*)d_out;
    float* out_zc    = out;
    float* out_loss  = out + (size_t)NROWS * DDIM;
    float* out_zproj = out_loss + 1;
    float* out_u     = out_zproj + (size_t)NROWS * DDIM;

    static float *p_zp = nullptr, *p_nn, *p_zn, *p_gate, *p_S, *p_comb;
    static int* p_idx;
    static bf *zb, *hb, *zpb, *nnb, *znb, *Sb, *W1T, *W2T, *WgT, *gdb, *ldb, *cbb, *ctb;
    static size_t szNM, szNS, szDD, szGD, szLD, szCB;
    if (!p_zp) {
        cudaGetSymbolAddress((void**)&p_zp, g_zp);
        cudaGetSymbolAddress((void**)&p_nn, g_nn);
        cudaGetSymbolAddress((void**)&p_zn, g_zn);
        cudaGetSymbolAddress((void**)&p_gate, g_gate);
        cudaGetSymbolAddress((void**)&p_S, g_S);
        cudaGetSymbolAddress((void**)&p_comb, g_comb);
        cudaGetSymbolAddress((void**)&p_idx, g_idx);
        cudaGetSymbolAddress((void**)&zb, b_z);
        cudaGetSymbolAddress((void**)&hb, b_h);
        cudaGetSymbolAddress((void**)&zpb, b_zp);
        cudaGetSymbolAddress((void**)&nnb, b_nn);
        cudaGetSymbolAddress((void**)&znb, b_zn);
        cudaGetSymbolAddress((void**)&Sb, b_S);
        cudaGetSymbolAddress((void**)&W1T, b_W1T);
        cudaGetSymbolAddress((void**)&W2T, b_W2T);
        cudaGetSymbolAddress((void**)&WgT, b_WgT);
        cudaGetSymbolAddress((void**)&gdb, b_gd);
        cudaGetSymbolAddress((void**)&ldb, b_ld);
        cudaGetSymbolAddress((void**)&cbb, b_comb);
        cudaGetSymbolAddress((void**)&ctb, b_combT);
        szNM = NM; szNS = (size_t)NROWS * NCOMB; szDD = DDIM * DDIM;
        szGD = NGD * DDIM; szLD = NLD * DDIM; szCB = NCOMB * DDIM;
        cudaFuncSetAttribute(gemm_mma<EPI_RELU_BIAS, false, true, false>,
                             cudaFuncAttributeMaxDynamicSharedMemorySize, SM_TOTAL);
        cudaFuncSetAttribute(gemm_mma<EPI_BIAS, true, true, true>,
                             cudaFuncAttributeMaxDynamicSharedMemorySize, SM_TOTAL);
        cudaFuncSetAttribute(gemm_mma<EPI_SIGMOID, true, false, false>,
                             cudaFuncAttributeMaxDynamicSharedMemorySize, SM_TOTAL);
        cudaFuncSetAttribute(gemm_mma<EPI_S_LOSS, true, false, false>,
                             cudaFuncAttributeMaxDynamicSharedMemorySize, SM_TOTAL);
        cudaFuncSetAttribute(gemm_mma<EPI_ZCLEAN, true, false, false>,
                             cudaFuncAttributeMaxDynamicSharedMemorySize, SM_TOTAL);
        cudaFuncSetAttribute(argmax_mma,
                             cudaFuncAttributeMaxDynamicSharedMemorySize, SM_TOTAL);
    }

    init_kernel<<<(NCOMB * DDIM) / 256, 256>>>();

    // input conversions
    conv_split_kernel<<<NM / 1024, 256>>>(z, zb, zb + szNM, NM);
    conv_split_kernel<<<(NGD * DDIM) / 1024, 256>>>(gd, gdb, gdb + szGD, NGD * DDIM);
    conv_split_kernel<<<(NLD * DDIM) / 1024, 256>>>(ld, ldb, ldb + szLD, NLD * DDIM);
    transconv_kernel<<<dim3(DDIM / 32, DDIM / 32), 256>>>(W1, DDIM, DDIM, W1T, W1T + szDD);
    transconv_kernel<<<dim3(DDIM / 32, DDIM / 32), 256>>>(W2, DDIM, DDIM, W2T, W2T + szDD);
    transconv_kernel<<<dim3(DDIM / 32, DDIM / 32), 256>>>(Wg, DDIM, DDIM, WgT, WgT + szDD);

    // noise_norm + fused raw-u copy to output
    rownorm_split_kernel<<<NROWS, 256>>>(u, p_nn, nnb, nnb + szNM, out_u);

    const dim3 gD(DDIM / 128, NROWS / 128);
    // projector
    gemm_mma<EPI_RELU_BIAS, false, true, false><<<gD, 256, SM_TOTAL>>>(
        zb, zb + szNM, W1T, W1T + szDD, b1, nullptr, hb, hb + szNM, nullptr, DDIM, DDIM,
        nullptr, nullptr);
    gemm_mma<EPI_BIAS, true, true, true><<<gD, 256, SM_TOTAL>>>(
        hb, hb + szNM, W2T, W2T + szDD, b2, p_zp, zpb, zpb + szNM, out_zproj, DDIM, DDIM,
        nullptr, nullptr);

    rownorm_split_kernel<<<NROWS, 256>>>(p_zp, p_zn, znb, znb + szNM, nullptr);

    // gate
    gemm_mma<EPI_SIGMOID, true, false, false><<<gD, 256, SM_TOTAL>>>(
        zpb, zpb + szNM, WgT, WgT + szDD, bg, p_gate, nullptr, nullptr, nullptr, DDIM, DDIM,
        nullptr, nullptr);

    // dict assignment + EMA update
    argmax_mma<<<NROWS / 128, 256, SM_TOTAL>>>(nnb, nnb + szNM, gdb, gdb + szGD, NGD, p_idx);
    argmax_mma<<<NROWS / 128, 256, SM_TOTAL>>>(nnb, nnb + szNM, ldb, ldb + szLD, NLD, p_idx + NROWS);
    scatter_kernel<<<NROWS, 256>>>(p_nn, p_idx);
    dictupd_kernel<<<NCOMB, 256>>>(gd, ld, cbb, cbb + szCB);

    // S = z_norm @ comb^T (+ fused sum|S| for loss_g / loss_l)
    gemm_mma<EPI_S_LOSS, true, false, false><<<dim3(NCOMB / 128, NROWS / 128), 256, SM_TOTAL>>>(
        znb, znb + szNM, cbb, cbb + szCB, nullptr, p_S, nullptr, nullptr, nullptr, NCOMB, DDIM,
        nullptr, nullptr);

    softmax_split_kernel<<<NROWS, 256>>>(p_S, Sb, Sb + szNS);
    transconv_kernel<<<dim3(DDIM / 32, NCOMB / 32), 256>>>(p_comb, NCOMB, DDIM, ctb, ctb + szCB);

    // weighted_u + fused z_clean epilogue
    gemm_mma<EPI_ZCLEAN, true, false, false><<<gD, 256, SM_TOTAL>>>(
        Sb, Sb + szNS, ctb, ctb + szCB, nullptr, out_zc, nullptr, nullptr, nullptr, DDIM, NCOMB,
        z, p_gate);

    dotabs_kernel<<<NROWS, 256>>>(p_zn, p_nn);
    finalize_kernel<<<1, 1>>>(out_loss);
}

// round 8
// speedup vs baseline: 2.6653x; 1.0535x over previous
#include <cuda_runtime.h>
#include <cuda_bf16.h>
#include <math.h>
#include <stdint.h>

#define NROWS 32768
#define DDIM  1024
#define NGD   1024
#define NLD   256
#define NCOMB 1280
#define NM    (NROWS * DDIM)

typedef __nv_bfloat16 bf;

// ---------------- warp MMA primitives (plain sm_80+ PTX, no 'a' features) --
__device__ __forceinline__ uint32_t smem_u32(const void* p) {
    uint32_t a;
    asm("{ .reg .u64 t; cvta.to.shared.u64 t, %1; cvt.u32.u64 %0, t; }" : "=r"(a) : "l"(p));
    return a;
}
__device__ __forceinline__ void ldsm4(uint32_t addr, uint32_t* f) {
    asm volatile("ldmatrix.sync.aligned.m8n8.x4.shared.b16 {%0,%1,%2,%3}, [%4];"
                 : "=r"(f[0]), "=r"(f[1]), "=r"(f[2]), "=r"(f[3]) : "r"(addr));
}
__device__ __forceinline__ void mma16816(float* c, const uint32_t* a, uint32_t b0, uint32_t b1) {
    asm volatile("mma.sync.aligned.m16n8k16.row.col.f32.bf16.bf16.f32 "
                 "{%0,%1,%2,%3}, {%4,%5,%6,%7}, {%8,%9}, {%0,%1,%2,%3};"
                 : "+f"(c[0]), "+f"(c[1]), "+f"(c[2]), "+f"(c[3])
                 : "r"(a[0]), "r"(a[1]), "r"(a[2]), "r"(a[3]), "r"(b0), "r"(b1));
}
__device__ __forceinline__ void cp16(uint32_t dst, const void* src) {
    asm volatile("cp.async.cg.shared.global [%0], [%1], 16;" :: "r"(dst), "l"(src));
}
#define CP_COMMIT() asm volatile("cp.async.commit_group;" ::: "memory")
#define CP_WAIT(n)  asm volatile("cp.async.wait_group %0;" :: "n"(n) : "memory")

__device__ __forceinline__ void split2(float x, bf& h, bf& l) {
    h = __float2bfloat16(x);
    l = __float2bfloat16(x - __bfloat162float(h));
}

// ---------------- scratch ---------------------------------------------------
__device__ float  g_zp[NM];
__device__ float  g_nn[NM];
__device__ float  g_zn[NM];
__device__ float  g_gate[NM];
__device__ float  g_S[(size_t)NROWS * NCOMB];
__device__ float  g_comb[NCOMB * DDIM];
__device__ float  g_sums[NCOMB * DDIM];
__device__ float  g_cnts[NCOMB];
__device__ int    g_idx[2 * NROWS];
__device__ double g_acc[3];

__device__ bf b_z[2][NM];
__device__ bf b_h[2][NM];
__device__ bf b_zp[2][NM];
__device__ bf b_nn[2][NM];
__device__ bf b_zn[2][NM];
__device__ bf b_S[2][(size_t)NROWS * NCOMB];
__device__ bf b_W1T[2][DDIM * DDIM];
__device__ bf b_W2T[2][DDIM * DDIM];
__device__ bf b_WgT[2][DDIM * DDIM];
__device__ bf b_gd[2][NGD * DDIM];
__device__ bf b_ld[2][NLD * DDIM];
__device__ bf b_comb[2][NCOMB * DDIM];
__device__ bf b_combT[2][DDIM * NCOMB];

// ---------------- small kernels --------------------------------------------
__global__ void init_kernel() {
    int i = blockIdx.x * blockDim.x + threadIdx.x;
    if (i < NCOMB * DDIM) g_sums[i] = 0.f;
    if (i < NCOMB)        g_cnts[i] = 0.f;
    if (i < 3)            g_acc[i]  = 0.0;
}

__global__ __launch_bounds__(256)
void conv_split_kernel(const float* __restrict__ src, bf* __restrict__ dh,
                       bf* __restrict__ dl, int n) {
    int i = (blockIdx.x * blockDim.x + threadIdx.x) * 4;
    if (i + 3 < n) {
        float4 v = *reinterpret_cast<const float4*>(&src[i]);
        bf h[4], l[4];
        split2(v.x, h[0], l[0]); split2(v.y, h[1], l[1]);
        split2(v.z, h[2], l[2]); split2(v.w, h[3], l[3]);
        *reinterpret_cast<uint2*>(&dh[i]) = *reinterpret_cast<uint2*>(h);
        *reinterpret_cast<uint2*>(&dl[i]) = *reinterpret_cast<uint2*>(l);
    }
}

// tiled transpose + split: src [R][C] fp32 -> dst [c][r] bf16 hi/lo
__global__ __launch_bounds__(256)
void transconv_kernel(const float* __restrict__ src, int R, int C,
                      bf* __restrict__ dh, bf* __restrict__ dl) {
    __shared__ float t[32][33];
    const int bx = blockIdx.x * 32, by = blockIdx.y * 32;
    const int tx = threadIdx.x & 31, ty = threadIdx.x >> 5;
#pragma unroll
    for (int i = 0; i < 4; i++)
        t[ty + 8 * i][tx] = src[(size_t)(by + ty + 8 * i) * C + bx + tx];
    __syncthreads();
#pragma unroll
    for (int i = 0; i < 4; i++) {
        float x = t[tx][ty + 8 * i];
        bf h, l; split2(x, h, l);
        size_t o = (size_t)(bx + ty + 8 * i) * R + by + tx;
        dh[o] = h; dl[o] = l;
    }
}

// row L2 normalize; write fp32 + bf16 hi/lo; optional raw copy; optional
// fused |dot(normalized, UN_row)| accumulation into g_acc[2]
__global__ __launch_bounds__(256)
void rownorm_split_kernel(const float* __restrict__ X, float* __restrict__ Y,
                          bf* __restrict__ Yh, bf* __restrict__ Yl,
                          float* __restrict__ Cpy, const float* __restrict__ UN) {
    __shared__ float red[8];
    const int r = blockIdx.x, tid = threadIdx.x;
    float4 x = *reinterpret_cast<const float4*>(&X[(size_t)r * DDIM + tid * 4]);
    float ss = x.x * x.x + x.y * x.y + x.z * x.z + x.w * x.w;
#pragma unroll
    for (int off = 16; off; off >>= 1) ss += __shfl_down_sync(0xffffffffu, ss, off);
    if ((tid & 31) == 0) red[tid >> 5] = ss;
    __syncthreads();
    if (tid == 0) {
        float s = 0.f;
#pragma unroll
        for (int i = 0; i < 8; i++) s += red[i];
        red[0] = s;
    }
    __syncthreads();
    float inv = 1.f / fmaxf(sqrtf(red[0]), 1e-12f);
    float f[4] = {x.x * inv, x.y * inv, x.z * inv, x.w * inv};
    size_t o = (size_t)r * DDIM + tid * 4;
    *reinterpret_cast<float4*>(&Y[o]) = make_float4(f[0], f[1], f[2], f[3]);
    bf h[4], l[4];
#pragma unroll
    for (int i = 0; i < 4; i++) split2(f[i], h[i], l[i]);
    *reinterpret_cast<uint2*>(&Yh[o]) = *reinterpret_cast<uint2*>(h);
    *reinterpret_cast<uint2*>(&Yl[o]) = *reinterpret_cast<uint2*>(l);
    if (Cpy) { Cpy[o] = x.x; Cpy[o + 1] = x.y; Cpy[o + 2] = x.z; Cpy[o + 3] = x.w; }
    if (UN) {
        float4 un = *reinterpret_cast<const float4*>(&UN[o]);
        float p = f[0] * un.x + f[1] * un.y + f[2] * un.z + f[3] * un.w;
#pragma unroll
        for (int off = 16; off; off >>= 1) p += __shfl_down_sync(0xffffffffu, p, off);
        __syncthreads();
        if ((tid & 31) == 0) red[tid >> 5] = p;
        __syncthreads();
        if (tid == 0) {
            float s = 0.f;
#pragma unroll
            for (int i = 0; i < 8; i++) s += red[i];
            atomicAdd(&g_acc[2], (double)fabsf(s));
        }
    }
}

// ---------------- HMMA GEMM (cp.async 2-stage, 4 warps @ 64x64) -------------
enum { EPI_RELU_BIAS = 0, EPI_BIAS = 1, EPI_SIGMOID = 2, EPI_S_LOSS = 3, EPI_ZCLEAN = 4 };

#define TPAD 40
#define TILE_BYTES (128 * TPAD * 2)   // 10240
#define BUF_BYTES  (4 * TILE_BYTES)   // 40960 per stage
#define SM_TOTAL   (2 * BUF_BYTES)    // 81920

// issue cp.async fill of one K-chunk for all 4 tiles into stage b (128 thr)
__device__ __forceinline__ void fill_async(
    uint32_t sb, int b,
    const bf* __restrict__ Ah, const bf* __restrict__ Al,
    const bf* __restrict__ Bh, const bf* __restrict__ Bl,
    int m0, int n0, int k0, int K, int tid) {
    const uint32_t base = sb + b * BUF_BYTES;
#pragma unroll
    for (int t = 0; t < 4; t++) {
        const bf* gp = (t == 0) ? Ah : (t == 1) ? Al : (t == 2) ? Bh : Bl;
        const int rb = (t < 2) ? m0 : n0;
        const uint32_t tb = base + t * TILE_BYTES;
#pragma unroll
        for (int v = 0; v < 4; v++) {
            int idx = v * 128 + tid;
            int row = idx >> 2, c8 = (idx & 3) << 3;
            cp16(tb + row * (TPAD * 2) + c8 * 2, gp + (size_t)(rb + row) * K + k0 + c8);
        }
    }
    CP_COMMIT();
}

// 3-product hi/lo compute of one K-chunk into acc[4][8][4] (warp 64x64)
__device__ __forceinline__ void chunk_mma(float acc[4][8][4], uint32_t base,
                                          int aoff, int boff) {
    const uint32_t aH = base + aoff, aL = base + TILE_BYTES + aoff;
    const uint32_t bH = base + 2 * TILE_BYTES + boff, bL = base + 3 * TILE_BYTES + boff;
#pragma unroll
    for (int ks = 0; ks < 2; ks++) {
        const int kb = ks * 32;
        uint32_t bh[16], bl[16];
#pragma unroll
        for (int i = 0; i < 4; i++) {
            ldsm4(bH + i * 16 * (TPAD * 2) + kb, bh + 4 * i);
            ldsm4(bL + i * 16 * (TPAD * 2) + kb, bl + 4 * i);
        }
#pragma unroll
        for (int mt = 0; mt < 4; mt++) {
            uint32_t ah[4], al[4];
            ldsm4(aH + mt * 16 * (TPAD * 2) + kb, ah);
            ldsm4(aL + mt * 16 * (TPAD * 2) + kb, al);
#pragma unroll
            for (int nt = 0; nt < 8; nt++) {
                mma16816(acc[mt][nt], ah, bh[2 * nt], bh[2 * nt + 1]);
                mma16816(acc[mt][nt], ah, bl[2 * nt], bl[2 * nt + 1]);
                mma16816(acc[mt][nt], al, bh[2 * nt], bh[2 * nt + 1]);
            }
        }
    }
}

template <int EPI, bool WF32, bool WSPLIT, bool WMIS>
__global__ __launch_bounds__(128)
void gemm_mma(const bf* __restrict__ Ah, const bf* __restrict__ Al,
              const bf* __restrict__ Bh, const bf* __restrict__ Bl,
              const float* __restrict__ bias, float* __restrict__ Cf,
              bf* __restrict__ Ch, bf* __restrict__ Cl, float* __restrict__ Cm,
              int Ncols, int K,
              const float* __restrict__ e1, const float* __restrict__ e2) {
    extern __shared__ __align__(16) char smem[];
    const uint32_t sb = smem_u32(smem);
    const int tid = threadIdx.x, lane = tid & 31, wid = tid >> 5;
    const int m0 = blockIdx.y * 128, n0 = blockIdx.x * 128;
    const int warp_m = (wid >> 1) * 64, warp_n = (wid & 1) * 64;

    const int aoff = (warp_m + (lane & 15)) * (TPAD * 2) + ((lane >> 4) << 3) * 2;
    const int boff = (warp_n + ((lane & 7) | ((lane >> 4) << 3))) * (TPAD * 2) +
                     (((lane >> 3) & 1) << 3) * 2;

    float acc[4][8][4] = {};

    const int nch = K >> 5;
    fill_async(sb, 0, Ah, Al, Bh, Bl, m0, n0, 0, K, tid);
    for (int kc = 0; kc < nch; kc++) {
        if (kc + 1 < nch)
            fill_async(sb, (kc + 1) & 1, Ah, Al, Bh, Bl, m0, n0, (kc + 1) << 5, K, tid);
        if (kc + 1 < nch) { CP_WAIT(1); } else { CP_WAIT(0); }
        __syncthreads();
        chunk_mma(acc, sb + (kc & 1) * BUF_BYTES, aoff, boff);
        __syncthreads();
    }

    // ---------------- epilogue ----------------
    double part = 0.0;
#pragma unroll
    for (int mt = 0; mt < 4; mt++) {
        const int r0 = m0 + warp_m + mt * 16 + (lane >> 2);
#pragma unroll
        for (int nt = 0; nt < 8; nt++) {
            const int col = n0 + warp_n + nt * 8 + ((lane & 3) << 1);
            float b2x = 0.f, b2y = 0.f;
            if (EPI == EPI_RELU_BIAS || EPI == EPI_BIAS || EPI == EPI_SIGMOID) {
                float2 bb = *reinterpret_cast<const float2*>(bias + col);
                b2x = bb.x; b2y = bb.y;
            }
#pragma unroll
            for (int h = 0; h < 2; h++) {
                const int row = r0 + h * 8;
                float v0 = acc[mt][nt][2 * h], v1 = acc[mt][nt][2 * h + 1];
                if (EPI == EPI_RELU_BIAS) { v0 = fmaxf(v0 + b2x, 0.f); v1 = fmaxf(v1 + b2y, 0.f); }
                else if (EPI == EPI_BIAS) { v0 += b2x; v1 += b2y; }
                else if (EPI == EPI_SIGMOID) {
                    v0 = 1.f / (1.f + expf(-(v0 + b2x)));
                    v1 = 1.f / (1.f + expf(-(v1 + b2y)));
                }
                const size_t ro = (size_t)row * Ncols + col;
                if (EPI == EPI_ZCLEAN) {
                    float2 z2 = *reinterpret_cast<const float2*>(e1 + ro);
                    float2 q2 = *reinterpret_cast<const float2*>(e2 + ro);
                    v0 = z2.x - q2.x * v0;
                    v1 = z2.y - q2.y * v1;
                }
                if (EPI == EPI_S_LOSS) part += (double)fabsf(v0) + (double)fabsf(v1);
                if (WF32)
                    *reinterpret_cast<float2*>(Cf + ro) = make_float2(v0, v1);
                if (WMIS) { Cm[ro] = v0; Cm[ro + 1] = v1; }
                if (WSPLIT) {
                    bf h0, l0, h1, l1;
                    split2(v0, h0, l0); split2(v1, h1, l1);
                    bf hp[2] = {h0, h1}, lp[2] = {l0, l1};
                    *reinterpret_cast<uint32_t*>(Ch + ro) = *reinterpret_cast<uint32_t*>(hp);
                    *reinterpret_cast<uint32_t*>(Cl + ro) = *reinterpret_cast<uint32_t*>(lp);
                }
            }
        }
    }
    if (EPI == EPI_S_LOSS) {
#pragma unroll
        for (int off = 16; off; off >>= 1) part += __shfl_down_sync(0xffffffffu, part, off);
        if (lane == 0) atomicAdd(&g_acc[(n0 < NGD) ? 0 : 1], part);
    }
}

// ---------------- HMMA sim + per-row argmax (4 warps @ 64x64) ---------------
__global__ __launch_bounds__(128)
void argmax_mma(const bf* __restrict__ Ah, const bf* __restrict__ Al,
                const bf* __restrict__ Dh, const bf* __restrict__ Dl,
                int ncodes, int* __restrict__ idx_out) {
    extern __shared__ __align__(16) char smem[];
    __shared__ float sval[128][2];
    __shared__ int   sidx[128][2];
    const uint32_t sb = smem_u32(smem);
    const int tid = threadIdx.x, lane = tid & 31, wid = tid >> 5;
    const int m0 = blockIdx.x * 128;
    const int warp_m = (wid >> 1) * 64, warp_n = (wid & 1) * 64;

    const int aoff = (warp_m + (lane & 15)) * (TPAD * 2) + ((lane >> 4) << 3) * 2;
    const int boff = (warp_n + ((lane & 7) | ((lane >> 4) << 3))) * (TPAD * 2) +
                     (((lane >> 3) & 1) << 3) * 2;

    float bv[8]; int bi[8];
#pragma unroll
    for (int i = 0; i < 8; i++) { bv[i] = -1e30f; bi[i] = 0; }

    for (int n0 = 0; n0 < ncodes; n0 += 128) {
        float acc[4][8][4] = {};
        const int nch = DDIM >> 5;
        fill_async(sb, 0, Ah, Al, Dh, Dl, m0, n0, 0, DDIM, tid);
        for (int kc = 0; kc < nch; kc++) {
            if (kc + 1 < nch)
                fill_async(sb, (kc + 1) & 1, Ah, Al, Dh, Dl, m0, n0, (kc + 1) << 5, DDIM, tid);
            if (kc + 1 < nch) { CP_WAIT(1); } else { CP_WAIT(0); }
            __syncthreads();
            chunk_mma(acc, sb + (kc & 1) * BUF_BYTES, aoff, boff);
            __syncthreads();
        }
#pragma unroll
        for (int mt = 0; mt < 4; mt++)
#pragma unroll
            for (int h = 0; h < 2; h++) {
                float* bvp = &bv[mt * 2 + h]; int* bip = &bi[mt * 2 + h];
#pragma unroll
                for (int nt = 0; nt < 8; nt++) {
                    const int col = n0 + warp_n + nt * 8 + ((lane & 3) << 1);
                    float v0 = acc[mt][nt][2 * h], v1 = acc[mt][nt][2 * h + 1];
                    if (v0 > *bvp) { *bvp = v0; *bip = col; }
                    if (v1 > *bvp) { *bvp = v1; *bip = col + 1; }
                }
            }
    }
#pragma unroll
    for (int i = 0; i < 8; i++) {
        float v = bv[i]; int c = bi[i];
#pragma unroll
        for (int off = 1; off <= 2; off <<= 1) {
            float ov = __shfl_xor_sync(0xffffffffu, v, off);
            int   oc = __shfl_xor_sync(0xffffffffu, c, off);
            if (ov > v || (ov == v && oc < c)) { v = ov; c = oc; }
        }
        if ((lane & 3) == 0) {
            int row = warp_m + (i >> 1) * 16 + (i & 1) * 8 + (lane >> 2);
            sval[row][wid & 1] = v;
            sidx[row][wid & 1] = c;
        }
    }
    __syncthreads();
    {
        float v = sval[tid][0]; int c = sidx[tid][0];
        float ov = sval[tid][1]; int oc = sidx[tid][1];
        if (ov > v || (ov == v && oc < c)) { v = ov; c = oc; }
        idx_out[m0 + tid] = c;
    }
}

// ---------------- scatter / dict update / softmax ---------------------------
__global__ __launch_bounds__(256)
void scatter_kernel(const float* __restrict__ NN_, const int* __restrict__ idx) {
    const int r = blockIdx.x, tid = threadIdx.x;
    const int ig = idx[r];
    const int il = NGD + idx[NROWS + r];
    float4 v = *reinterpret_cast<const float4*>(&NN_[(size_t)r * DDIM + tid * 4]);
    float* sg = &g_sums[(size_t)ig * DDIM + tid * 4];
    float* sl = &g_sums[(size_t)il * DDIM + tid * 4];
    atomicAdd(sg + 0, v.x); atomicAdd(sg + 1, v.y); atomicAdd(sg + 2, v.z); atomicAdd(sg + 3, v.w);
    atomicAdd(sl + 0, v.x); atomicAdd(sl + 1, v.y); atomicAdd(sl + 2, v.z); atomicAdd(sl + 3, v.w);
    if (tid == 0) { atomicAdd(&g_cnts[ig], 1.f); atomicAdd(&g_cnts[il], 1.f); }
}

__global__ __launch_bounds__(256)
void dictupd_kernel(const float* __restrict__ gd, const float* __restrict__ ld,
                    bf* __restrict__ ch, bf* __restrict__ cl) {
    __shared__ float red[8];
    const int c = blockIdx.x, tid = threadIdx.x;
    const float* dsrc = (c < NGD) ? (gd + (size_t)c * DDIM) : (ld + (size_t)(c - NGD) * DDIM);
    const float m = (c < NGD) ? 0.999f : 0.8f;
    const float cnt = g_cnts[c];
    float4 d  = *reinterpret_cast<const float4*>(&dsrc[tid * 4]);
    float4 sm = *reinterpret_cast<const float4*>(&g_sums[(size_t)c * DDIM + tid * 4]);
    float u0, u1, u2, u3;
    if (cnt > 0.f) {
        float w = (1.f - m) / cnt;
        u0 = m * d.x + w * sm.x; u1 = m * d.y + w * sm.y;
        u2 = m * d.z + w * sm.z; u3 = m * d.w + w * sm.w;
    } else { u0 = d.x; u1 = d.y; u2 = d.z; u3 = d.w; }
    float ss = u0 * u0 + u1 * u1 + u2 * u2 + u3 * u3;
#pragma unroll
    for (int off = 16; off; off >>= 1) ss += __shfl_down_sync(0xffffffffu, ss, off);
    if ((tid & 31) == 0) red[tid >> 5] = ss;
    __syncthreads();
    if (tid == 0) {
        float s = 0.f;
#pragma unroll
        for (int i = 0; i < 8; i++) s += red[i];
        red[0] = s;
    }
    __syncthreads();
    float inv = 1.f / fmaxf(sqrtf(red[0]), 1e-12f);
    float f[4] = {u0 * inv, u1 * inv, u2 * inv, u3 * inv};
    size_t o = (size_t)c * DDIM + tid * 4;
    *reinterpret_cast<float4*>(&g_comb[o]) = make_float4(f[0], f[1], f[2], f[3]);
    bf h[4], l[4];
#pragma unroll
    for (int i = 0; i < 4; i++) split2(f[i], h[i], l[i]);
    *reinterpret_cast<uint2*>(&ch[o]) = *reinterpret_cast<uint2*>(h);
    *reinterpret_cast<uint2*>(&cl[o]) = *reinterpret_cast<uint2*>(l);
}

__global__ __launch_bounds__(256)
void softmax_split_kernel(const float* __restrict__ S, bf* __restrict__ Wh,
                          bf* __restrict__ Wl) {
    __shared__ float red[8];
    const int r = blockIdx.x, tid = threadIdx.x;
    const float* s = S + (size_t)r * NCOMB;
    float v[5];
#pragma unroll
    for (int i = 0; i < 5; i++) v[i] = s[tid + i * 256];
    float mx = v[0];
#pragma unroll
    for (int i = 1; i < 5; i++) mx = fmaxf(mx, v[i]);
#pragma unroll
    for (int off = 16; off; off >>= 1) mx = fmaxf(mx, __shfl_down_sync(0xffffffffu, mx, off));
    if ((tid & 31) == 0) red[tid >> 5] = mx;
    __syncthreads();
    if (tid == 0) {
        float t = red[0];
#pragma unroll
        for (int i = 1; i < 8; i++) t = fmaxf(t, red[i]);
        red[0] = t;
    }
    __syncthreads();
    mx = red[0];
    __syncthreads();
    float ssum = 0.f;
#pragma unroll
    for (int i = 0; i < 5; i++) { v[i] = expf((v[i] - mx) * (1.f / 0.07f)); ssum += v[i]; }
#pragma unroll
    for (int off = 16; off; off >>= 1) ssum += __shfl_down_sync(0xffffffffu, ssum, off);
    if ((tid & 31) == 0) red[tid >> 5] = ssum;
    __syncthreads();
    if (tid == 0) {
        float t = 0.f;
#pragma unroll
        for (int i = 0; i < 8; i++) t += red[i];
        red[0] = t;
    }
    __syncthreads();
    float inv = 1.f / red[0];
#pragma unroll
    for (int i = 0; i < 5; i++) {
        bf h, l;
        split2(v[i] * inv, h, l);
        Wh[(size_t)r * NCOMB + tid + i * 256] = h;
        Wl[(size_t)r * NCOMB + tid + i * 256] = l;
    }
}

__global__ void finalize_kernel(float* out_loss) {
    *out_loss = (float)(g_acc[0] / ((double)NROWS * (double)NGD) +
                        g_acc[1] / ((double)NROWS * (double)NLD) +
                        g_acc[2] / (double)NROWS);
}

// ---------------- launch ----------------------------------------------------
extern "C" void kernel_launch(void* const* d_in, const int* in_sizes, int n_in,
                              void* d_out, int out_size) {
    const float* z  = (const float*)d_in[0];
    const float* u  = (const float*)d_in[1];
    const float* W1 = (const float*)d_in[2];
    const float* b1 = (const float*)d_in[3];
    const float* W2 = (const float*)d_in[4];
    const float* b2 = (const float*)d_in[5];
    const float* Wg = (const float*)d_in[6];
    const float* bg = (const float*)d_in[7];
    const float* gd = (const float*)d_in[8];
    const float* ld = (const float*)d_in[9];

    float* out       = (float*)d_out;
    float* out_zc    = out;
    float* out_loss  = out + (size_t)NROWS * DDIM;
    float* out_zproj = out_loss + 1;
    float* out_u     = out_zproj + (size_t)NROWS * DDIM;

    static float *p_zp = nullptr, *p_nn, *p_zn, *p_gate, *p_S, *p_comb;
    static int* p_idx;
    static bf *zb, *hb, *zpb, *nnb, *znb, *Sb, *W1T, *W2T, *WgT, *gdb, *ldb, *cbb, *ctb;
    static size_t szNM, szNS, szDD, szGD, szLD, szCB;
    if (!p_zp) {
        cudaGetSymbolAddress((void**)&p_zp, g_zp);
        cudaGetSymbolAddress((void**)&p_nn, g_nn);
        cudaGetSymbolAddress((void**)&p_zn, g_zn);
        cudaGetSymbolAddress((void**)&p_gate, g_gate);
        cudaGetSymbolAddress((void**)&p_S, g_S);
        cudaGetSymbolAddress((void**)&p_comb, g_comb);
        cudaGetSymbolAddress((void**)&p_idx, g_idx);
        cudaGetSymbolAddress((void**)&zb, b_z);
        cudaGetSymbolAddress((void**)&hb, b_h);
        cudaGetSymbolAddress((void**)&zpb, b_zp);
        cudaGetSymbolAddress((void**)&nnb, b_nn);
        cudaGetSymbolAddress((void**)&znb, b_zn);
        cudaGetSymbolAddress((void**)&Sb, b_S);
        cudaGetSymbolAddress((void**)&W1T, b_W1T);
        cudaGetSymbolAddress((void**)&W2T, b_W2T);
        cudaGetSymbolAddress((void**)&WgT, b_WgT);
        cudaGetSymbolAddress((void**)&gdb, b_gd);
        cudaGetSymbolAddress((void**)&ldb, b_ld);
        cudaGetSymbolAddress((void**)&cbb, b_comb);
        cudaGetSymbolAddress((void**)&ctb, b_combT);
        szNM = NM; szNS = (size_t)NROWS * NCOMB; szDD = DDIM * DDIM;
        szGD = NGD * DDIM; szLD = NLD * DDIM; szCB = NCOMB * DDIM;
        cudaFuncSetAttribute(gemm_mma<EPI_RELU_BIAS, false, true, false>,
                             cudaFuncAttributeMaxDynamicSharedMemorySize, SM_TOTAL);
        cudaFuncSetAttribute(gemm_mma<EPI_BIAS, true, true, true>,
                             cudaFuncAttributeMaxDynamicSharedMemorySize, SM_TOTAL);
        cudaFuncSetAttribute(gemm_mma<EPI_SIGMOID, true, false, false>,
                             cudaFuncAttributeMaxDynamicSharedMemorySize, SM_TOTAL);
        cudaFuncSetAttribute(gemm_mma<EPI_S_LOSS, true, false, false>,
                             cudaFuncAttributeMaxDynamicSharedMemorySize, SM_TOTAL);
        cudaFuncSetAttribute(gemm_mma<EPI_ZCLEAN, true, false, false>,
                             cudaFuncAttributeMaxDynamicSharedMemorySize, SM_TOTAL);
        cudaFuncSetAttribute(argmax_mma,
                             cudaFuncAttributeMaxDynamicSharedMemorySize, SM_TOTAL);
    }

    init_kernel<<<(NCOMB * DDIM) / 256, 256>>>();

    // input conversions
    conv_split_kernel<<<NM / 1024, 256>>>(z, zb, zb + szNM, NM);
    conv_split_kernel<<<(NGD * DDIM) / 1024, 256>>>(gd, gdb, gdb + szGD, NGD * DDIM);
    conv_split_kernel<<<(NLD * DDIM) / 1024, 256>>>(ld, ldb, ldb + szLD, NLD * DDIM);
    transconv_kernel<<<dim3(DDIM / 32, DDIM / 32), 256>>>(W1, DDIM, DDIM, W1T, W1T + szDD);
    transconv_kernel<<<dim3(DDIM / 32, DDIM / 32), 256>>>(W2, DDIM, DDIM, W2T, W2T + szDD);
    transconv_kernel<<<dim3(DDIM / 32, DDIM / 32), 256>>>(Wg, DDIM, DDIM, WgT, WgT + szDD);

    // noise_norm + fused raw-u copy to output
    rownorm_split_kernel<<<NROWS, 256>>>(u, p_nn, nnb, nnb + szNM, out_u, nullptr);

    const dim3 gD(DDIM / 128, NROWS / 128);
    // projector
    gemm_mma<EPI_RELU_BIAS, false, true, false><<<gD, 128, SM_TOTAL>>>(
        zb, zb + szNM, W1T, W1T + szDD, b1, nullptr, hb, hb + szNM, nullptr, DDIM, DDIM,
        nullptr, nullptr);
    gemm_mma<EPI_BIAS, true, true, true><<<gD, 128, SM_TOTAL>>>(
        hb, hb + szNM, W2T, W2T + szDD, b2, p_zp, zpb, zpb + szNM, out_zproj, DDIM, DDIM,
        nullptr, nullptr);

    // z_norm + fused loss_direct (reads u_norm = p_nn)
    rownorm_split_kernel<<<NROWS, 256>>>(p_zp, p_zn, znb, znb + szNM, nullptr, p_nn);

    // gate
    gemm_mma<EPI_SIGMOID, true, false, false><<<gD, 128, SM_TOTAL>>>(
        zpb, zpb + szNM, WgT, WgT + szDD, bg, p_gate, nullptr, nullptr, nullptr, DDIM, DDIM,
        nullptr, nullptr);

    // dict assignment + EMA update
    argmax_mma<<<NROWS / 128, 128, SM_TOTAL>>>(nnb, nnb + szNM, gdb, gdb + szGD, NGD, p_idx);
    argmax_mma<<<NROWS / 128, 128, SM_TOTAL>>>(nnb, nnb + szNM, ldb, ldb + szLD, NLD, p_idx + NROWS);
    scatter_kernel<<<NROWS, 256>>>(p_nn, p_idx);
    dictupd_kernel<<<NCOMB, 256>>>(gd, ld, cbb, cbb + szCB);

    // S = z_norm @ comb^T (+ fused sum|S| for loss_g / loss_l)
    gemm_mma<EPI_S_LOSS, true, false, false><<<dim3(NCOMB / 128, NROWS / 128), 128, SM_TOTAL>>>(
        znb, znb + szNM, cbb, cbb + szCB, nullptr, p_S, nullptr, nullptr, nullptr, NCOMB, DDIM,
        nullptr, nullptr);

    softmax_split_kernel<<<NROWS, 256>>>(p_S, Sb, Sb + szNS);
    transconv_kernel<<<dim3(DDIM / 32, NCOMB / 32), 256>>>(p_comb, NCOMB, DDIM, ctb, ctb + szCB);

    // weighted_u + fused z_clean epilogue
    gemm_mma<EPI_ZCLEAN, true, false, false><<<gD, 128, SM_TOTAL>>>(
        Sb, Sb + szNS, ctb, ctb + szCB, nullptr, out_zc, nullptr, nullptr, nullptr, DDIM, NCOMB,
        z, p_gate);

    finalize_kernel<<<1, 1>>>(out_loss);
}

// round 10
// speedup vs baseline: 2.7434x; 1.0293x over previous
#include <cuda_runtime.h>
#include <cuda_bf16.h>
#include <math.h>
#include <stdint.h>

#define NROWS 32768
#define DDIM  1024
#define NGD   1024
#define NLD   256
#define NCOMB 1280
#define NM    (NROWS * DDIM)

typedef __nv_bfloat16 bf;

// ---------------- warp MMA primitives (plain sm_80+ PTX, no 'a' features) --
__device__ __forceinline__ uint32_t smem_u32(const void* p) {
    uint32_t a;
    asm("{ .reg .u64 t; cvta.to.shared.u64 t, %1; cvt.u32.u64 %0, t; }" : "=r"(a) : "l"(p));
    return a;
}
__device__ __forceinline__ void ldsm4(uint32_t addr, uint32_t* f) {
    asm volatile("ldmatrix.sync.aligned.m8n8.x4.shared.b16 {%0,%1,%2,%3}, [%4];"
                 : "=r"(f[0]), "=r"(f[1]), "=r"(f[2]), "=r"(f[3]) : "r"(addr));
}
__device__ __forceinline__ void mma16816(float* c, const uint32_t* a, uint32_t b0, uint32_t b1) {
    asm volatile("mma.sync.aligned.m16n8k16.row.col.f32.bf16.bf16.f32 "
                 "{%0,%1,%2,%3}, {%4,%5,%6,%7}, {%8,%9}, {%0,%1,%2,%3};"
                 : "+f"(c[0]), "+f"(c[1]), "+f"(c[2]), "+f"(c[3])
                 : "r"(a[0]), "r"(a[1]), "r"(a[2]), "r"(a[3]), "r"(b0), "r"(b1));
}
__device__ __forceinline__ void cp16(uint32_t dst, const void* src) {
    asm volatile("cp.async.cg.shared.global [%0], [%1], 16;" :: "r"(dst), "l"(src));
}
#define CP_COMMIT() asm volatile("cp.async.commit_group;" ::: "memory")
#define CP_WAIT(n)  asm volatile("cp.async.wait_group %0;" :: "n"(n) : "memory")

__device__ __forceinline__ void split2(float x, bf& h, bf& l) {
    h = __float2bfloat16(x);
    l = __float2bfloat16(x - __bfloat162float(h));
}

// ---------------- scratch ---------------------------------------------------
__device__ float  g_zp[NM];
__device__ float  g_nn[NM];
__device__ float  g_zn[NM];
__device__ float  g_gate[NM];
__device__ float  g_S[(size_t)NROWS * NCOMB];
__device__ float  g_comb[NCOMB * DDIM];
__device__ float  g_cnts[NCOMB];
__device__ int    g_cnt_i[NCOMB];
__device__ int    g_cur[NCOMB];
__device__ int    g_off[NCOMB];
__device__ int    g_list[2 * NROWS];
__device__ int    g_idx[2 * NROWS];
__device__ double g_acc[3];

__device__ bf b_z[2][NM];
__device__ bf b_h[2][NM];
__device__ bf b_zp[2][NM];
__device__ bf b_nn[2][NM];
__device__ bf b_zn[2][NM];
__device__ bf b_S[2][(size_t)NROWS * NCOMB];
__device__ bf b_W1T[2][DDIM * DDIM];
__device__ bf b_W2T[2][DDIM * DDIM];
__device__ bf b_WgT[2][DDIM * DDIM];
__device__ bf b_gd[2][NGD * DDIM];
__device__ bf b_ld[2][NLD * DDIM];
__device__ bf b_comb[2][NCOMB * DDIM];
__device__ bf b_combT[2][DDIM * NCOMB];

// ---------------- small kernels --------------------------------------------
__global__ void init_kernel() {
    int i = blockIdx.x * blockDim.x + threadIdx.x;
    if (i < NCOMB) { g_cnt_i[i] = 0; g_cur[i] = 0; }
    if (i < 3)     g_acc[i] = 0.0;
}

__global__ __launch_bounds__(256)
void conv_split_kernel(const float* __restrict__ src, bf* __restrict__ dh,
                       bf* __restrict__ dl, int n) {
    int i = (blockIdx.x * blockDim.x + threadIdx.x) * 4;
    if (i + 3 < n) {
        float4 v = *reinterpret_cast<const float4*>(&src[i]);
        bf h[4], l[4];
        split2(v.x, h[0], l[0]); split2(v.y, h[1], l[1]);
        split2(v.z, h[2], l[2]); split2(v.w, h[3], l[3]);
        *reinterpret_cast<uint2*>(&dh[i]) = *reinterpret_cast<uint2*>(h);
        *reinterpret_cast<uint2*>(&dl[i]) = *reinterpret_cast<uint2*>(l);
    }
}

// tiled transpose + split: src [R][C] fp32 -> dst [c][r] bf16 hi/lo
__global__ __launch_bounds__(256)
void transconv_kernel(const float* __restrict__ src, int R, int C,
                      bf* __restrict__ dh, bf* __restrict__ dl) {
    __shared__ float t[32][33];
    const int bx = blockIdx.x * 32, by = blockIdx.y * 32;
    const int tx = threadIdx.x & 31, ty = threadIdx.x >> 5;
#pragma unroll
    for (int i = 0; i < 4; i++)
        t[ty + 8 * i][tx] = src[(size_t)(by + ty + 8 * i) * C + bx + tx];
    __syncthreads();
#pragma unroll
    for (int i = 0; i < 4; i++) {
        float x = t[tx][ty + 8 * i];
        bf h, l; split2(x, h, l);
        size_t o = (size_t)(bx + ty + 8 * i) * R + by + tx;
        dh[o] = h; dl[o] = l;
    }
}

// row L2 normalize; write fp32 + bf16 hi/lo; optional raw copy; optional
// fused |dot(normalized, UN_row)| accumulation into g_acc[2]
__global__ __launch_bounds__(256)
void rownorm_split_kernel(const float* __restrict__ X, float* __restrict__ Y,
                          bf* __restrict__ Yh, bf* __restrict__ Yl,
                          float* __restrict__ Cpy, const float* __restrict__ UN) {
    __shared__ float red[8];
    const int r = blockIdx.x, tid = threadIdx.x;
    float4 x = *reinterpret_cast<const float4*>(&X[(size_t)r * DDIM + tid * 4]);
    float ss = x.x * x.x + x.y * x.y + x.z * x.z + x.w * x.w;
#pragma unroll
    for (int off = 16; off; off >>= 1) ss += __shfl_down_sync(0xffffffffu, ss, off);
    if ((tid & 31) == 0) red[tid >> 5] = ss;
    __syncthreads();
    if (tid == 0) {
        float s = 0.f;
#pragma unroll
        for (int i = 0; i < 8; i++) s += red[i];
        red[0] = s;
    }
    __syncthreads();
    float inv = 1.f / fmaxf(sqrtf(red[0]), 1e-12f);
    float f[4] = {x.x * inv, x.y * inv, x.z * inv, x.w * inv};
    size_t o = (size_t)r * DDIM + tid * 4;
    *reinterpret_cast<float4*>(&Y[o]) = make_float4(f[0], f[1], f[2], f[3]);
    bf h[4], l[4];
#pragma unroll
    for (int i = 0; i < 4; i++) split2(f[i], h[i], l[i]);
    *reinterpret_cast<uint2*>(&Yh[o]) = *reinterpret_cast<uint2*>(h);
    *reinterpret_cast<uint2*>(&Yl[o]) = *reinterpret_cast<uint2*>(l);
    if (Cpy) { Cpy[o] = x.x; Cpy[o + 1] = x.y; Cpy[o + 2] = x.z; Cpy[o + 3] = x.w; }
    if (UN) {
        float4 un = *reinterpret_cast<const float4*>(&UN[o]);
        float p = f[0] * un.x + f[1] * un.y + f[2] * un.z + f[3] * un.w;
#pragma unroll
        for (int off = 16; off; off >>= 1) p += __shfl_down_sync(0xffffffffu, p, off);
        __syncthreads();
        if ((tid & 31) == 0) red[tid >> 5] = p;
        __syncthreads();
        if (tid == 0) {
            float s = 0.f;
#pragma unroll
            for (int i = 0; i < 8; i++) s += red[i];
            atomicAdd(&g_acc[2], (double)fabsf(s));
        }
    }
}

// ---------------- HMMA GEMM (cp.async 2-stage, 4 warps @ 64x64) -------------
enum { EPI_RELU_BIAS = 0, EPI_BIAS = 1, EPI_SIGMOID = 2, EPI_S_LOSS = 3, EPI_ZCLEAN = 4 };

#define TPAD 40
#define TILE_BYTES (128 * TPAD * 2)   // 10240
#define BUF_BYTES  (4 * TILE_BYTES)   // 40960 per stage
#define SM_TOTAL   (2 * BUF_BYTES)    // 81920

// issue cp.async fill of one K-chunk for all 4 tiles into stage b (128 thr)
__device__ __forceinline__ void fill_async(
    uint32_t sb, int b,
    const bf* __restrict__ Ah, const bf* __restrict__ Al,
    const bf* __restrict__ Bh, const bf* __restrict__ Bl,
    int m0, int n0, int k0, int K, int tid) {
    const uint32_t base = sb + b * BUF_BYTES;
#pragma unroll
    for (int t = 0; t < 4; t++) {
        const bf* gp = (t == 0) ? Ah : (t == 1) ? Al : (t == 2) ? Bh : Bl;
        const int rb = (t < 2) ? m0 : n0;
        const uint32_t tb = base + t * TILE_BYTES;
#pragma unroll
        for (int v = 0; v < 4; v++) {
            int idx = v * 128 + tid;
            int row = idx >> 2, c8 = (idx & 3) << 3;
            cp16(tb + row * (TPAD * 2) + c8 * 2, gp + (size_t)(rb + row) * K + k0 + c8);
        }
    }
    CP_COMMIT();
}

// 3-product hi/lo compute of one K-chunk into acc[4][8][4] (warp 64x64)
__device__ __forceinline__ void chunk_mma(float acc[4][8][4], uint32_t base,
                                          int aoff, int boff) {
    const uint32_t aH = base + aoff, aL = base + TILE_BYTES + aoff;
    const uint32_t bH = base + 2 * TILE_BYTES + boff, bL = base + 3 * TILE_BYTES + boff;
#pragma unroll
    for (int ks = 0; ks < 2; ks++) {
        const int kb = ks * 32;
        uint32_t bh[16], bl[16];
#pragma unroll
        for (int i = 0; i < 4; i++) {
            ldsm4(bH + i * 16 * (TPAD * 2) + kb, bh + 4 * i);
            ldsm4(bL + i * 16 * (TPAD * 2) + kb, bl + 4 * i);
        }
#pragma unroll
        for (int mt = 0; mt < 4; mt++) {
            uint32_t ah[4], al[4];
            ldsm4(aH + mt * 16 * (TPAD * 2) + kb, ah);
            ldsm4(aL + mt * 16 * (TPAD * 2) + kb, al);
#pragma unroll
            for (int nt = 0; nt < 8; nt++) {
                mma16816(acc[mt][nt], ah, bh[2 * nt], bh[2 * nt + 1]);
                mma16816(acc[mt][nt], ah, bl[2 * nt], bl[2 * nt + 1]);
                mma16816(acc[mt][nt], al, bh[2 * nt], bh[2 * nt + 1]);
            }
        }
    }
}

template <int EPI, bool WF32, bool WSPLIT, bool WMIS>
__global__ __launch_bounds__(128)
void gemm_mma(const bf* __restrict__ Ah, const bf* __restrict__ Al,
              const bf* __restrict__ Bh, const bf* __restrict__ Bl,
              const float* __restrict__ bias, float* __restrict__ Cf,
              bf* __restrict__ Ch, bf* __restrict__ Cl, float* __restrict__ Cm,
              int Ncols, int K,
              const float* __restrict__ e1, const float* __restrict__ e2) {
    extern __shared__ __align__(16) char smem[];
    const uint32_t sb = smem_u32(smem);
    const int tid = threadIdx.x, lane = tid & 31, wid = tid >> 5;
    const int m0 = blockIdx.y * 128, n0 = blockIdx.x * 128;
    const int warp_m = (wid >> 1) * 64, warp_n = (wid & 1) * 64;

    const int aoff = (warp_m + (lane & 15)) * (TPAD * 2) + ((lane >> 4) << 3) * 2;
    const int boff = (warp_n + ((lane & 7) | ((lane >> 4) << 3))) * (TPAD * 2) +
                     (((lane >> 3) & 1) << 3) * 2;

    float acc[4][8][4] = {};

    const int nch = K >> 5;
    fill_async(sb, 0, Ah, Al, Bh, Bl, m0, n0, 0, K, tid);
    for (int kc = 0; kc < nch; kc++) {
        if (kc + 1 < nch)
            fill_async(sb, (kc + 1) & 1, Ah, Al, Bh, Bl, m0, n0, (kc + 1) << 5, K, tid);
        if (kc + 1 < nch) { CP_WAIT(1); } else { CP_WAIT(0); }
        __syncthreads();
        chunk_mma(acc, sb + (kc & 1) * BUF_BYTES, aoff, boff);
        __syncthreads();
    }

    // ---------------- epilogue ----------------
    double part = 0.0;
#pragma unroll
    for (int mt = 0; mt < 4; mt++) {
        const int r0 = m0 + warp_m + mt * 16 + (lane >> 2);
#pragma unroll
        for (int nt = 0; nt < 8; nt++) {
            const int col = n0 + warp_n + nt * 8 + ((lane & 3) << 1);
            float b2x = 0.f, b2y = 0.f;
            if (EPI == EPI_RELU_BIAS || EPI == EPI_BIAS || EPI == EPI_SIGMOID) {
                float2 bb = *reinterpret_cast<const float2*>(bias + col);
                b2x = bb.x; b2y = bb.y;
            }
#pragma unroll
            for (int h = 0; h < 2; h++) {
                const int row = r0 + h * 8;
                float v0 = acc[mt][nt][2 * h], v1 = acc[mt][nt][2 * h + 1];
                if (EPI == EPI_RELU_BIAS) { v0 = fmaxf(v0 + b2x, 0.f); v1 = fmaxf(v1 + b2y, 0.f); }
                else if (EPI == EPI_BIAS) { v0 += b2x; v1 += b2y; }
                else if (EPI == EPI_SIGMOID) {
                    v0 = 1.f / (1.f + expf(-(v0 + b2x)));
                    v1 = 1.f / (1.f + expf(-(v1 + b2y)));
                }
                const size_t ro = (size_t)row * Ncols + col;
                if (EPI == EPI_ZCLEAN) {
                    float2 z2 = *reinterpret_cast<const float2*>(e1 + ro);
                    float2 q2 = *reinterpret_cast<const float2*>(e2 + ro);
                    v0 = z2.x - q2.x * v0;
                    v1 = z2.y - q2.y * v1;
                }
                if (EPI == EPI_S_LOSS) part += (double)fabsf(v0) + (double)fabsf(v1);
                if (WF32)
                    *reinterpret_cast<float2*>(Cf + ro) = make_float2(v0, v1);
                if (WMIS) { Cm[ro] = v0; Cm[ro + 1] = v1; }
                if (WSPLIT) {
                    bf h0, l0, h1, l1;
                    split2(v0, h0, l0); split2(v1, h1, l1);
                    bf hp[2] = {h0, h1}, lp[2] = {l0, l1};
                    *reinterpret_cast<uint32_t*>(Ch + ro) = *reinterpret_cast<uint32_t*>(hp);
                    *reinterpret_cast<uint32_t*>(Cl + ro) = *reinterpret_cast<uint32_t*>(lp);
                }
            }
        }
    }
    if (EPI == EPI_S_LOSS) {
#pragma unroll
        for (int off = 16; off; off >>= 1) part += __shfl_down_sync(0xffffffffu, part, off);
        if (lane == 0) atomicAdd(&g_acc[(n0 < NGD) ? 0 : 1], part);
    }
}

// ---------------- dual-dict HMMA argmax + count ------------------------------
__global__ __launch_bounds__(128)
void argmax_dual(const bf* __restrict__ Ah, const bf* __restrict__ Al,
                 const bf* __restrict__ Gh, const bf* __restrict__ Gl,
                 const bf* __restrict__ Lh, const bf* __restrict__ Ll,
                 int* __restrict__ idx_out) {
    extern __shared__ __align__(16) char smem[];
    __shared__ float sval[128][2];
    __shared__ int   sidx[128][2];
    const uint32_t sb = smem_u32(smem);
    const int tid = threadIdx.x, lane = tid & 31, wid = tid >> 5;
    const int m0 = blockIdx.x * 128;
    const int warp_m = (wid >> 1) * 64, warp_n = (wid & 1) * 64;

    const int aoff = (warp_m + (lane & 15)) * (TPAD * 2) + ((lane >> 4) << 3) * 2;
    const int boff = (warp_n + ((lane & 7) | ((lane >> 4) << 3))) * (TPAD * 2) +
                     (((lane >> 3) & 1) << 3) * 2;

    for (int part = 0; part < 2; part++) {
        const bf* Dh = part ? Lh : Gh;
        const bf* Dl = part ? Ll : Gl;
        const int ncodes = part ? NLD : NGD;

        float bv[8]; int bi[8];
#pragma unroll
        for (int i = 0; i < 8; i++) { bv[i] = -1e30f; bi[i] = 0; }

        for (int n0 = 0; n0 < ncodes; n0 += 128) {
            float acc[4][8][4] = {};
            const int nch = DDIM >> 5;
            fill_async(sb, 0, Ah, Al, Dh, Dl, m0, n0, 0, DDIM, tid);
            for (int kc = 0; kc < nch; kc++) {
                if (kc + 1 < nch)
                    fill_async(sb, (kc + 1) & 1, Ah, Al, Dh, Dl, m0, n0, (kc + 1) << 5, DDIM, tid);
                if (kc + 1 < nch) { CP_WAIT(1); } else { CP_WAIT(0); }
                __syncthreads();
                chunk_mma(acc, sb + (kc & 1) * BUF_BYTES, aoff, boff);
                __syncthreads();
            }
#pragma unroll
            for (int mt = 0; mt < 4; mt++)
#pragma unroll
                for (int h = 0; h < 2; h++) {
                    float* bvp = &bv[mt * 2 + h]; int* bip = &bi[mt * 2 + h];
#pragma unroll
                    for (int nt = 0; nt < 8; nt++) {
                        const int col = n0 + warp_n + nt * 8 + ((lane & 3) << 1);
                        float v0 = acc[mt][nt][2 * h], v1 = acc[mt][nt][2 * h + 1];
                        if (v0 > *bvp) { *bvp = v0; *bip = col; }
                        if (v1 > *bvp) { *bvp = v1; *bip = col + 1; }
                    }
                }
        }
#pragma unroll
        for (int i = 0; i < 8; i++) {
            float v = bv[i]; int c = bi[i];
#pragma unroll
            for (int off = 1; off <= 2; off <<= 1) {
                float ov = __shfl_xor_sync(0xffffffffu, v, off);
                int   oc = __shfl_xor_sync(0xffffffffu, c, off);
                if (ov > v || (ov == v && oc < c)) { v = ov; c = oc; }
            }
            if ((lane & 3) == 0) {
                int row = warp_m + (i >> 1) * 16 + (i & 1) * 8 + (lane >> 2);
                sval[row][wid & 1] = v;
                sidx[row][wid & 1] = c;
            }
        }
        __syncthreads();
        {
            float v = sval[tid][0]; int c = sidx[tid][0];
            float ov = sval[tid][1]; int oc = sidx[tid][1];
            if (ov > v || (ov == v && oc < c)) { v = ov; c = oc; }
            idx_out[part * NROWS + m0 + tid] = c;
            atomicAdd(&g_cnt_i[part ? NGD + c : c], 1);
        }
        __syncthreads();
    }
}

// ---------------- scan / fill / gather dict update --------------------------
__global__ __launch_bounds__(256)
void scan_kernel() {
    __shared__ int ws[8];
    const int tid = threadIdx.x, lane = tid & 31, wid = tid >> 5;
    int v[5]; int s = 0;
#pragma unroll
    for (int i = 0; i < 5; i++) { v[i] = g_cnt_i[tid * 5 + i]; s += v[i]; }
    int x = s;
#pragma unroll
    for (int off = 1; off < 32; off <<= 1) {
        int t = __shfl_up_sync(0xffffffffu, x, off);
        if (lane >= off) x += t;
    }
    if (lane == 31) ws[wid] = x;
    __syncthreads();
    if (tid == 0) {
        int a = 0;
#pragma unroll
        for (int w = 0; w < 8; w++) { int t = ws[w]; ws[w] = a; a += t; }
    }
    __syncthreads();
    int run = x - s + ws[wid];  // exclusive offset of this thread's first element
#pragma unroll
    for (int i = 0; i < 5; i++) {
        g_off[tid * 5 + i] = run;
        g_cnts[tid * 5 + i] = (float)v[i];
        run += v[i];
    }
}

__global__ __launch_bounds__(256)
void fill_list_kernel(const int* __restrict__ idx) {
    const int r = blockIdx.x * blockDim.x + threadIdx.x;
    if (r < NROWS) {
        int ig = idx[r];
        int pos = atomicAdd(&g_cur[ig], 1);
        g_list[g_off[ig] + pos] = r;
        int il = NGD + idx[NROWS + r];
        int pos2 = atomicAdd(&g_cur[il], 1);
        g_list[g_off[il] + pos2] = r;
    }
}

__global__ __launch_bounds__(256)
void dictupd_kernel(const float* __restrict__ gd, const float* __restrict__ ld,
                    bf* __restrict__ ch, bf* __restrict__ cl) {
    __shared__ float red[8];
    const int c = blockIdx.x, tid = threadIdx.x;
    const int cnt = g_cnt_i[c], off = g_off[c];
    float4 acc = make_float4(0.f, 0.f, 0.f, 0.f);
    int i = 0;
    for (; i + 1 < cnt; i += 2) {
        int r0 = g_list[off + i], r1 = g_list[off + i + 1];
        float4 a = *reinterpret_cast<const float4*>(&g_nn[(size_t)r0 * DDIM + tid * 4]);
        float4 b = *reinterpret_cast<const float4*>(&g_nn[(size_t)r1 * DDIM + tid * 4]);
        acc.x += a.x + b.x; acc.y += a.y + b.y; acc.z += a.z + b.z; acc.w += a.w + b.w;
    }
    if (i < cnt) {
        int r0 = g_list[off + i];
        float4 a = *reinterpret_cast<const float4*>(&g_nn[(size_t)r0 * DDIM + tid * 4]);
        acc.x += a.x; acc.y += a.y; acc.z += a.z; acc.w += a.w;
    }
    const float* dsrc = (c < NGD) ? (gd + (size_t)c * DDIM) : (ld + (size_t)(c - NGD) * DDIM);
    const float m = (c < NGD) ? 0.999f : 0.8f;
    float4 d = *reinterpret_cast<const float4*>(&dsrc[tid * 4]);
    float u0, u1, u2, u3;
    if (cnt > 0) {
        float w = (1.f - m) / (float)cnt;
        u0 = m * d.x + w * acc.x; u1 = m * d.y + w * acc.y;
        u2 = m * d.z + w * acc.z; u3 = m * d.w + w * acc.w;
    } else { u0 = d.x; u1 = d.y; u2 = d.z; u3 = d.w; }
    float ss = u0 * u0 + u1 * u1 + u2 * u2 + u3 * u3;
#pragma unroll
    for (int off2 = 16; off2; off2 >>= 1) ss += __shfl_down_sync(0xffffffffu, ss, off2);
    if ((tid & 31) == 0) red[tid >> 5] = ss;
    __syncthreads();
    if (tid == 0) {
        float s = 0.f;
#pragma unroll
        for (int j = 0; j < 8; j++) s += red[j];
        red[0] = s;
    }
    __syncthreads();
    float inv = 1.f / fmaxf(sqrtf(red[0]), 1e-12f);
    float f[4] = {u0 * inv, u1 * inv, u2 * inv, u3 * inv};
    size_t o = (size_t)c * DDIM + tid * 4;
    *reinterpret_cast<float4*>(&g_comb[o]) = make_float4(f[0], f[1], f[2], f[3]);
    bf h[4], l[4];
#pragma unroll
    for (int j = 0; j < 4; j++) split2(f[j], h[j], l[j]);
    *reinterpret_cast<uint2*>(&ch[o]) = *reinterpret_cast<uint2*>(h);
    *reinterpret_cast<uint2*>(&cl[o]) = *reinterpret_cast<uint2*>(l);
}

// ---------------- softmax ----------------------------------------------------
__global__ __launch_bounds__(256)
void softmax_split_kernel(const float* __restrict__ S, bf* __restrict__ Wh,
                          bf* __restrict__ Wl) {
    __shared__ float red[8];
    const int r = blockIdx.x, tid = threadIdx.x;
    const float* s = S + (size_t)r * NCOMB;
    float v[5];
#pragma unroll
    for (int i = 0; i < 5; i++) v[i] = s[tid + i * 256];
    float mx = v[0];
#pragma unroll
    for (int i = 1; i < 5; i++) mx = fmaxf(mx, v[i]);
#pragma unroll
    for (int off = 16; off; off >>= 1) mx = fmaxf(mx, __shfl_down_sync(0xffffffffu, mx, off));
    if ((tid & 31) == 0) red[tid >> 5] = mx;
    __syncthreads();
    if (tid == 0) {
        float t = red[0];
#pragma unroll
        for (int i = 1; i < 8; i++) t = fmaxf(t, red[i]);
        red[0] = t;
    }
    __syncthreads();
    mx = red[0];
    __syncthreads();
    float ssum = 0.f;
#pragma unroll
    for (int i = 0; i < 5; i++) { v[i] = expf((v[i] - mx) * (1.f / 0.07f)); ssum += v[i]; }
#pragma unroll
    for (int off = 16; off; off >>= 1) ssum += __shfl_down_sync(0xffffffffu, ssum, off);
    if ((tid & 31) == 0) red[tid >> 5] = ssum;
    __syncthreads();
    if (tid == 0) {
        float t = 0.f;
#pragma unroll
        for (int i = 0; i < 8; i++) t += red[i];
        red[0] = t;
    }
    __syncthreads();
    float inv = 1.f / red[0];
#pragma unroll
    for (int i = 0; i < 5; i++) {
        bf h, l;
        split2(v[i] * inv, h, l);
        Wh[(size_t)r * NCOMB + tid + i * 256] = h;
        Wl[(size_t)r * NCOMB + tid + i * 256] = l;
    }
}

__global__ void finalize_kernel(float* out_loss) {
    *out_loss = (float)(g_acc[0] / ((double)NROWS * (double)NGD) +
                        g_acc[1] / ((double)NROWS * (double)NLD) +
                        g_acc[2] / (double)NROWS);
}

// ---------------- launch ----------------------------------------------------
extern "C" void kernel_launch(void* const* d_in, const int* in_sizes, int n_in,
                              void* d_out, int out_size) {
    const float* z  = (const float*)d_in[0];
    const float* u  = (const float*)d_in[1];
    const float* W1 = (const float*)d_in[2];
    const float* b1 = (const float*)d_in[3];
    const float* W2 = (const float*)d_in[4];
    const float* b2 = (const float*)d_in[5];
    const float* Wg = (const float*)d_in[6];
    const float* bg = (const float*)d_in[7];
    const float* gd = (const float*)d_in[8];
    const float* ld = (const float*)d_in[9];

    float* out       = (float*)d_out;
    float* out_zc    = out;
    float* out_loss  = out + (size_t)NROWS * DDIM;
    float* out_zproj = out_loss + 1;
    float* out_u     = out_zproj + (size_t)NROWS * DDIM;

    static float *p_zp = nullptr, *p_nn, *p_zn, *p_gate, *p_S, *p_comb;
    static int* p_idx;
    static bf *zb, *hb, *zpb, *nnb, *znb, *Sb, *W1T, *W2T, *WgT, *gdb, *ldb, *cbb, *ctb;
    static size_t szNM, szNS, szDD, szGD, szLD, szCB;
    if (!p_zp) {
        cudaGetSymbolAddress((void**)&p_zp, g_zp);
        cudaGetSymbolAddress((void**)&p_nn, g_nn);
        cudaGetSymbolAddress((void**)&p_zn, g_zn);
        cudaGetSymbolAddress((void**)&p_gate, g_gate);
        cudaGetSymbolAddress((void**)&p_S, g_S);
        cudaGetSymbolAddress((void**)&p_comb, g_comb);
        cudaGetSymbolAddress((void**)&p_idx, g_idx);
        cudaGetSymbolAddress((void**)&zb, b_z);
        cudaGetSymbolAddress((void**)&hb, b_h);
        cudaGetSymbolAddress((void**)&zpb, b_zp);
        cudaGetSymbolAddress((void**)&nnb, b_nn);
        cudaGetSymbolAddress((void**)&znb, b_zn);
        cudaGetSymbolAddress((void**)&Sb, b_S);
        cudaGetSymbolAddress((void**)&W1T, b_W1T);
        cudaGetSymbolAddress((void**)&W2T, b_W2T);
        cudaGetSymbolAddress((void**)&WgT, b_WgT);
        cudaGetSymbolAddress((void**)&gdb, b_gd);
        cudaGetSymbolAddress((void**)&ldb, b_ld);
        cudaGetSymbolAddress((void**)&cbb, b_comb);
        cudaGetSymbolAddress((void**)&ctb, b_combT);
        szNM = NM; szNS = (size_t)NROWS * NCOMB; szDD = DDIM * DDIM;
        szGD = NGD * DDIM; szLD = NLD * DDIM; szCB = NCOMB * DDIM;
        cudaFuncSetAttribute(gemm_mma<EPI_RELU_BIAS, false, true, false>,
                             cudaFuncAttributeMaxDynamicSharedMemorySize, SM_TOTAL);
        cudaFuncSetAttribute(gemm_mma<EPI_BIAS, true, true, true>,
                             cudaFuncAttributeMaxDynamicSharedMemorySize, SM_TOTAL);
        cudaFuncSetAttribute(gemm_mma<EPI_SIGMOID, true, false, false>,
                             cudaFuncAttributeMaxDynamicSharedMemorySize, SM_TOTAL);
        cudaFuncSetAttribute(gemm_mma<EPI_S_LOSS, true, false, false>,
                             cudaFuncAttributeMaxDynamicSharedMemorySize, SM_TOTAL);
        cudaFuncSetAttribute(gemm_mma<EPI_ZCLEAN, true, false, false>,
                             cudaFuncAttributeMaxDynamicSharedMemorySize, SM_TOTAL);
        cudaFuncSetAttribute(argmax_dual,
                             cudaFuncAttributeMaxDynamicSharedMemorySize, SM_TOTAL);
    }

    const dim3 gD(DDIM / 128, NROWS / 128);

    // [0] init
    init_kernel<<<5, 256>>>();
    // [1] convert z
    conv_split_kernel<<<NM / 1024, 256>>>(z, zb, zb + szNM, NM);
    // [2] W1^T
    transconv_kernel<<<dim3(DDIM / 32, DDIM / 32), 256>>>(W1, DDIM, DDIM, W1T, W1T + szDD);
    // [3] proj1 GEMM  <-- ncu capture window target
    gemm_mma<EPI_RELU_BIAS, false, true, false><<<gD, 128, SM_TOTAL>>>(
        zb, zb + szNM, W1T, W1T + szDD, b1, nullptr, hb, hb + szNM, nullptr, DDIM, DDIM,
        nullptr, nullptr);
    // [4..7] remaining conversions
    conv_split_kernel<<<(NGD * DDIM) / 1024, 256>>>(gd, gdb, gdb + szGD, NGD * DDIM);
    conv_split_kernel<<<(NLD * DDIM) / 1024, 256>>>(ld, ldb, ldb + szLD, NLD * DDIM);
    transconv_kernel<<<dim3(DDIM / 32, DDIM / 32), 256>>>(W2, DDIM, DDIM, W2T, W2T + szDD);
    transconv_kernel<<<dim3(DDIM / 32, DDIM / 32), 256>>>(Wg, DDIM, DDIM, WgT, WgT + szDD);
    // [8] noise_norm + fused raw-u copy
    rownorm_split_kernel<<<NROWS, 256>>>(u, p_nn, nnb, nnb + szNM, out_u, nullptr);
    // [9] proj2
    gemm_mma<EPI_BIAS, true, true, true><<<gD, 128, SM_TOTAL>>>(
        hb, hb + szNM, W2T, W2T + szDD, b2, p_zp, zpb, zpb + szNM, out_zproj, DDIM, DDIM,
        nullptr, nullptr);
    // [10] z_norm + fused loss_direct
    rownorm_split_kernel<<<NROWS, 256>>>(p_zp, p_zn, znb, znb + szNM, nullptr, p_nn);
    // [11] gate
    gemm_mma<EPI_SIGMOID, true, false, false><<<gD, 128, SM_TOTAL>>>(
        zpb, zpb + szNM, WgT, WgT + szDD, bg, p_gate, nullptr, nullptr, nullptr, DDIM, DDIM,
        nullptr, nullptr);
    // [12] dual argmax + counts
    argmax_dual<<<NROWS / 128, 128, SM_TOTAL>>>(nnb, nnb + szNM,
                                                gdb, gdb + szGD, ldb, ldb + szLD, p_idx);
    // [13..15] scan / fill lists / gather dict update
    scan_kernel<<<1, 256>>>();
    fill_list_kernel<<<NROWS / 256, 256>>>(p_idx);
    dictupd_kernel<<<NCOMB, 256>>>(gd, ld, cbb, cbb + szCB);
    // [16] S = z_norm @ comb^T (+ fused sum|S|)
    gemm_mma<EPI_S_LOSS, true, false, false><<<dim3(NCOMB / 128, NROWS / 128), 128, SM_TOTAL>>>(
        znb, znb + szNM, cbb, cbb + szCB, nullptr, p_S, nullptr, nullptr, nullptr, NCOMB, DDIM,
        nullptr, nullptr);
    // [17..18] softmax + comb^T
    softmax_split_kernel<<<NROWS, 256>>>(p_S, Sb, Sb + szNS);
    transconv_kernel<<<dim3(DDIM / 32, NCOMB / 32), 256>>>(p_comb, NCOMB, DDIM, ctb, ctb + szCB);
    // [19] weighted_u + fused z_clean
    gemm_mma<EPI_ZCLEAN, true, false, false><<<gD, 128, SM_TOTAL>>>(
        Sb, Sb + szNS, ctb, ctb + szCB, nullptr, out_zc, nullptr, nullptr, nullptr, DDIM, NCOMB,
        z, p_gate);
    // [20] finalize loss
    finalize_kernel<<<1, 1>>>(out_loss);
}

// round 11
// speedup vs baseline: 3.0022x; 1.0943x over previous
#include <cuda_runtime.h>
#include <cuda_bf16.h>
#include <math.h>
#include <stdint.h>

#define NROWS 32768
#define DDIM  1024
#define NGD   1024
#define NLD   256
#define NCOMB 1280
#define NM    (NROWS * DDIM)

typedef __nv_bfloat16 bf;

// ---------------- warp MMA primitives (plain sm_80+ PTX, no 'a' features) --
__device__ __forceinline__ uint32_t smem_u32(const void* p) {
    uint32_t a;
    asm("{ .reg .u64 t; cvta.to.shared.u64 t, %1; cvt.u32.u64 %0, t; }" : "=r"(a) : "l"(p));
    return a;
}
__device__ __forceinline__ void ldsm4(uint32_t addr, uint32_t* f) {
    asm volatile("ldmatrix.sync.aligned.m8n8.x4.shared.b16 {%0,%1,%2,%3}, [%4];"
                 : "=r"(f[0]), "=r"(f[1]), "=r"(f[2]), "=r"(f[3]) : "r"(addr));
}
__device__ __forceinline__ void mma16816(float* c, const uint32_t* a, uint32_t b0, uint32_t b1) {
    asm volatile("mma.sync.aligned.m16n8k16.row.col.f32.bf16.bf16.f32 "
                 "{%0,%1,%2,%3}, {%4,%5,%6,%7}, {%8,%9}, {%0,%1,%2,%3};"
                 : "+f"(c[0]), "+f"(c[1]), "+f"(c[2]), "+f"(c[3])
                 : "r"(a[0]), "r"(a[1]), "r"(a[2]), "r"(a[3]), "r"(b0), "r"(b1));
}
__device__ __forceinline__ void cp16(uint32_t dst, const void* src) {
    asm volatile("cp.async.cg.shared.global [%0], [%1], 16;" :: "r"(dst), "l"(src));
}
#define CP_COMMIT() asm volatile("cp.async.commit_group;" ::: "memory")
#define CP_WAIT(n)  asm volatile("cp.async.wait_group %0;" :: "n"(n) : "memory")

__device__ __forceinline__ void split2(float x, bf& h, bf& l) {
    h = __float2bfloat16(x);
    l = __float2bfloat16(x - __bfloat162float(h));
}

// ---------------- scratch ---------------------------------------------------
__device__ float  g_zp[NM];
__device__ float  g_nn[NM];
__device__ float  g_zn[NM];
__device__ float  g_gate[NM];
__device__ float  g_S[(size_t)NROWS * NCOMB];
__device__ float  g_comb[NCOMB * DDIM];
__device__ float  g_cnts[NCOMB];
__device__ int    g_cnt_i[NCOMB];
__device__ int    g_cur[NCOMB];
__device__ int    g_off[NCOMB];
__device__ int    g_list[2 * NROWS];
__device__ int    g_idx[2 * NROWS];
__device__ double g_acc[3];

__device__ bf b_z[2][NM];
__device__ bf b_h[2][NM];
__device__ bf b_zp[2][NM];
__device__ bf b_nn[2][NM];
__device__ bf b_zn[2][NM];
__device__ bf b_S[2][(size_t)NROWS * NCOMB];
__device__ bf b_W1T[2][DDIM * DDIM];
__device__ bf b_W2T[2][DDIM * DDIM];
__device__ bf b_WgT[2][DDIM * DDIM];
__device__ bf b_gd[2][NGD * DDIM];
__device__ bf b_ld[2][NLD * DDIM];
__device__ bf b_comb[2][NCOMB * DDIM];
__device__ bf b_combT[2][DDIM * NCOMB];

// ---------------- small kernels --------------------------------------------
__global__ void init_kernel() {
    int i = blockIdx.x * blockDim.x + threadIdx.x;
    if (i < NCOMB) { g_cnt_i[i] = 0; g_cur[i] = 0; }
    if (i < 3)     g_acc[i] = 0.0;
}

__global__ __launch_bounds__(256)
void conv_split_kernel(const float* __restrict__ src, bf* __restrict__ dh,
                       bf* __restrict__ dl, int n) {
    int i = (blockIdx.x * blockDim.x + threadIdx.x) * 4;
    if (i + 3 < n) {
        float4 v = *reinterpret_cast<const float4*>(&src[i]);
        bf h[4], l[4];
        split2(v.x, h[0], l[0]); split2(v.y, h[1], l[1]);
        split2(v.z, h[2], l[2]); split2(v.w, h[3], l[3]);
        *reinterpret_cast<uint2*>(&dh[i]) = *reinterpret_cast<uint2*>(h);
        *reinterpret_cast<uint2*>(&dl[i]) = *reinterpret_cast<uint2*>(l);
    }
}

// tiled transpose + split: src [R][C] fp32 -> dst [c][r] bf16 hi/lo
__global__ __launch_bounds__(256)
void transconv_kernel(const float* __restrict__ src, int R, int C,
                      bf* __restrict__ dh, bf* __restrict__ dl) {
    __shared__ float t[32][33];
    const int bx = blockIdx.x * 32, by = blockIdx.y * 32;
    const int tx = threadIdx.x & 31, ty = threadIdx.x >> 5;
#pragma unroll
    for (int i = 0; i < 4; i++)
        t[ty + 8 * i][tx] = src[(size_t)(by + ty + 8 * i) * C + bx + tx];
    __syncthreads();
#pragma unroll
    for (int i = 0; i < 4; i++) {
        float x = t[tx][ty + 8 * i];
        bf h, l; split2(x, h, l);
        size_t o = (size_t)(bx + ty + 8 * i) * R + by + tx;
        dh[o] = h; dl[o] = l;
    }
}

// row L2 normalize; fp32 + bf16 hi/lo; optional raw copy; optional fused
// |dot(normalized, UN_row)| accumulation into g_acc[2]
__global__ __launch_bounds__(256)
void rownorm_split_kernel(const float* __restrict__ X, float* __restrict__ Y,
                          bf* __restrict__ Yh, bf* __restrict__ Yl,
                          float* __restrict__ Cpy, const float* __restrict__ UN) {
    __shared__ float red[8];
    const int r = blockIdx.x, tid = threadIdx.x;
    float4 x = *reinterpret_cast<const float4*>(&X[(size_t)r * DDIM + tid * 4]);
    float ss = x.x * x.x + x.y * x.y + x.z * x.z + x.w * x.w;
#pragma unroll
    for (int off = 16; off; off >>= 1) ss += __shfl_down_sync(0xffffffffu, ss, off);
    if ((tid & 31) == 0) red[tid >> 5] = ss;
    __syncthreads();
    if (tid == 0) {
        float s = 0.f;
#pragma unroll
        for (int i = 0; i < 8; i++) s += red[i];
        red[0] = s;
    }
    __syncthreads();
    float inv = 1.f / fmaxf(sqrtf(red[0]), 1e-12f);
    float f[4] = {x.x * inv, x.y * inv, x.z * inv, x.w * inv};
    size_t o = (size_t)r * DDIM + tid * 4;
    *reinterpret_cast<float4*>(&Y[o]) = make_float4(f[0], f[1], f[2], f[3]);
    bf h[4], l[4];
#pragma unroll
    for (int i = 0; i < 4; i++) split2(f[i], h[i], l[i]);
    *reinterpret_cast<uint2*>(&Yh[o]) = *reinterpret_cast<uint2*>(h);
    *reinterpret_cast<uint2*>(&Yl[o]) = *reinterpret_cast<uint2*>(l);
    if (Cpy) { Cpy[o] = x.x; Cpy[o + 1] = x.y; Cpy[o + 2] = x.z; Cpy[o + 3] = x.w; }
    if (UN) {
        float4 un = *reinterpret_cast<const float4*>(&UN[o]);
        float p = f[0] * un.x + f[1] * un.y + f[2] * un.z + f[3] * un.w;
#pragma unroll
        for (int off = 16; off; off >>= 1) p += __shfl_down_sync(0xffffffffu, p, off);
        __syncthreads();
        if ((tid & 31) == 0) red[tid >> 5] = p;
        __syncthreads();
        if (tid == 0) {
            float s = 0.f;
#pragma unroll
            for (int i = 0; i < 8; i++) s += red[i];
            atomicAdd(&g_acc[2], (double)fabsf(s));
        }
    }
}

// ---------------- HMMA GEMM (3-stage cp.async, XOR swizzle, 4 warps @64x64) --
enum { EPI_RELU_BIAS = 0, EPI_BIAS = 1, EPI_SIGMOID = 2, EPI_S_LOSS = 3, EPI_ZCLEAN = 4 };

#define TILE_B  8192                 // 128 rows x 64 bytes (32 bf16), swizzled
#define STAGE_B (4 * TILE_B)         // 32768 per stage (Ah, Al, Bh, Bl)
#define SM_TOTAL (3 * STAGE_B)       // 98304 : 2 CTAs/SM (196 KB < 227 KB)

// swizzled byte offset inside a tile: row in [0,128), c16 in [0,4)
__device__ __forceinline__ uint32_t swz(int row, int c16) {
    return (uint32_t)(row * 64 + ((c16 ^ ((row >> 1) & 3)) << 4));
}

// cp.async fill of one 32-wide K-chunk for all 4 tiles into stage s (128 thr)
__device__ __forceinline__ void fill_async(
    uint32_t sb, int s,
    const bf* __restrict__ Ah, const bf* __restrict__ Al,
    const bf* __restrict__ Bh, const bf* __restrict__ Bl,
    int m0, int n0, int k0, int K, int tid) {
    const uint32_t base = sb + s * STAGE_B;
#pragma unroll
    for (int t = 0; t < 4; t++) {
        const bf* gp = (t == 0) ? Ah : (t == 1) ? Al : (t == 2) ? Bh : Bl;
        const int rb = (t < 2) ? m0 : n0;
        const uint32_t tb = base + t * TILE_B;
#pragma unroll
        for (int v = 0; v < 4; v++) {
            int idx = v * 128 + tid;
            int row = idx >> 2, c16 = idx & 3;
            cp16(tb + swz(row, c16), gp + (size_t)(rb + row) * K + k0 + c16 * 8);
        }
    }
    CP_COMMIT();
}

// 3-product hi/lo compute of one K-chunk into acc[4][8][4] (warp 64x64)
__device__ __forceinline__ void chunk_mma(float acc[4][8][4], uint32_t base,
                                          int lane, int warp_m, int warp_n) {
    const int arow = warp_m + (lane & 15);
    const int ahi  = lane >> 4;
    const int brow = warp_n + ((lane & 7) | ((lane >> 4) << 3));
    const int bhi  = (lane >> 3) & 1;
#pragma unroll
    for (int ks = 0; ks < 2; ks++) {
        uint32_t bh[16], bl[16];
#pragma unroll
        for (int i = 0; i < 4; i++) {
            uint32_t off = swz(brow + i * 16, ks * 2 + bhi);
            ldsm4(base + 2 * TILE_B + off, bh + 4 * i);
            ldsm4(base + 3 * TILE_B + off, bl + 4 * i);
        }
#pragma unroll
        for (int mt = 0; mt < 4; mt++) {
            uint32_t off = swz(arow + mt * 16, ks * 2 + ahi);
            uint32_t ah[4], al[4];
            ldsm4(base + off, ah);
            ldsm4(base + TILE_B + off, al);
#pragma unroll
            for (int nt = 0; nt < 8; nt++) {
                mma16816(acc[mt][nt], ah, bh[2 * nt], bh[2 * nt + 1]);
                mma16816(acc[mt][nt], ah, bl[2 * nt], bl[2 * nt + 1]);
                mma16816(acc[mt][nt], al, bh[2 * nt], bh[2 * nt + 1]);
            }
        }
    }
}

// 3-stage mainloop: one __syncthreads per chunk.
// iter kc: wait(stage kc ready) -> sync (publish + protect) -> fill(kc+2) -> mma(kc)
#define GEMM_MAINLOOP(Ahp, Alp, Bhp, Blp, M0, N0, KK)                                   \
    do {                                                                                \
        const int nch = (KK) >> 5;                                                      \
        fill_async(sb, 0, Ahp, Alp, Bhp, Blp, M0, N0, 0, KK, tid);                      \
        fill_async(sb, 1, Ahp, Alp, Bhp, Blp, M0, N0, 32, KK, tid);                     \
        for (int kc = 0; kc < nch; kc++) {                                              \
            if (kc + 1 < nch) { CP_WAIT(1); } else { CP_WAIT(0); }                      \
            __syncthreads();                                                            \
            if (kc + 2 < nch)                                                           \
                fill_async(sb, (kc + 2) % 3, Ahp, Alp, Bhp, Blp, M0, N0,                \
                           (kc + 2) << 5, KK, tid);                                     \
            chunk_mma(acc, sb + (kc % 3) * STAGE_B, lane, warp_m, warp_n);              \
        }                                                                               \
    } while (0)

template <int EPI, bool WF32, bool WSPLIT, bool WMIS>
__global__ __launch_bounds__(128)
void gemm_mma(const bf* __restrict__ Ah, const bf* __restrict__ Al,
              const bf* __restrict__ Bh, const bf* __restrict__ Bl,
              const float* __restrict__ bias, float* __restrict__ Cf,
              bf* __restrict__ Ch, bf* __restrict__ Cl, float* __restrict__ Cm,
              int Ncols, int K,
              const float* __restrict__ e1, const float* __restrict__ e2) {
    extern __shared__ __align__(16) char smem[];
    const uint32_t sb = smem_u32(smem);
    const int tid = threadIdx.x, lane = tid & 31, wid = tid >> 5;
    const int m0 = blockIdx.y * 128, n0 = blockIdx.x * 128;
    const int warp_m = (wid >> 1) * 64, warp_n = (wid & 1) * 64;

    float acc[4][8][4] = {};
    GEMM_MAINLOOP(Ah, Al, Bh, Bl, m0, n0, K);

    // ---------------- epilogue ----------------
    double part = 0.0;
#pragma unroll
    for (int mt = 0; mt < 4; mt++) {
        const int r0 = m0 + warp_m + mt * 16 + (lane >> 2);
#pragma unroll
        for (int nt = 0; nt < 8; nt++) {
            const int col = n0 + warp_n + nt * 8 + ((lane & 3) << 1);
            float b2x = 0.f, b2y = 0.f;
            if (EPI == EPI_RELU_BIAS || EPI == EPI_BIAS || EPI == EPI_SIGMOID) {
                float2 bb = *reinterpret_cast<const float2*>(bias + col);
                b2x = bb.x; b2y = bb.y;
            }
#pragma unroll
            for (int h = 0; h < 2; h++) {
                const int row = r0 + h * 8;
                float v0 = acc[mt][nt][2 * h], v1 = acc[mt][nt][2 * h + 1];
                if (EPI == EPI_RELU_BIAS) { v0 = fmaxf(v0 + b2x, 0.f); v1 = fmaxf(v1 + b2y, 0.f); }
                else if (EPI == EPI_BIAS) { v0 += b2x; v1 += b2y; }
                else if (EPI == EPI_SIGMOID) {
                    v0 = 1.f / (1.f + expf(-(v0 + b2x)));
                    v1 = 1.f / (1.f + expf(-(v1 + b2y)));
                }
                const size_t ro = (size_t)row * Ncols + col;
                if (EPI == EPI_ZCLEAN) {
                    float2 z2 = *reinterpret_cast<const float2*>(e1 + ro);
                    float2 q2 = *reinterpret_cast<const float2*>(e2 + ro);
                    v0 = z2.x - q2.x * v0;
                    v1 = z2.y - q2.y * v1;
                }
                if (EPI == EPI_S_LOSS) part += (double)fabsf(v0) + (double)fabsf(v1);
                if (WF32)
                    *reinterpret_cast<float2*>(Cf + ro) = make_float2(v0, v1);
                if (WMIS) { Cm[ro] = v0; Cm[ro + 1] = v1; }
                if (WSPLIT) {
                    bf h0, l0, h1, l1;
                    split2(v0, h0, l0); split2(v1, h1, l1);
                    bf hp[2] = {h0, h1}, lp[2] = {l0, l1};
                    *reinterpret_cast<uint32_t*>(Ch + ro) = *reinterpret_cast<uint32_t*>(hp);
                    *reinterpret_cast<uint32_t*>(Cl + ro) = *reinterpret_cast<uint32_t*>(lp);
                }
            }
        }
    }
    if (EPI == EPI_S_LOSS) {
#pragma unroll
        for (int off = 16; off; off >>= 1) part += __shfl_down_sync(0xffffffffu, part, off);
        if (lane == 0) atomicAdd(&g_acc[(n0 < NGD) ? 0 : 1], part);
    }
}

// ---------------- dual-dict HMMA argmax + count ------------------------------
__global__ __launch_bounds__(128)
void argmax_dual(const bf* __restrict__ Ah, const bf* __restrict__ Al,
                 const bf* __restrict__ Gh, const bf* __restrict__ Gl,
                 const bf* __restrict__ Lh, const bf* __restrict__ Ll,
                 int* __restrict__ idx_out) {
    extern __shared__ __align__(16) char smem[];
    __shared__ float sval[128][2];
    __shared__ int   sidx[128][2];
    const uint32_t sb = smem_u32(smem);
    const int tid = threadIdx.x, lane = tid & 31, wid = tid >> 5;
    const int m0 = blockIdx.x * 128;
    const int warp_m = (wid >> 1) * 64, warp_n = (wid & 1) * 64;

    for (int part = 0; part < 2; part++) {
        const bf* Dh = part ? Lh : Gh;
        const bf* Dl = part ? Ll : Gl;
        const int ncodes = part ? NLD : NGD;

        float bv[8]; int bi[8];
#pragma unroll
        for (int i = 0; i < 8; i++) { bv[i] = -1e30f; bi[i] = 0; }

        for (int n0 = 0; n0 < ncodes; n0 += 128) {
            float acc[4][8][4] = {};
            GEMM_MAINLOOP(Ah, Al, Dh, Dl, m0, n0, DDIM);
            __syncthreads();  // all reads done before next tile's preload overwrites
#pragma unroll
            for (int mt = 0; mt < 4; mt++)
#pragma unroll
                for (int h = 0; h < 2; h++) {
                    float* bvp = &bv[mt * 2 + h]; int* bip = &bi[mt * 2 + h];
#pragma unroll
                    for (int nt = 0; nt < 8; nt++) {
                        const int col = n0 + warp_n + nt * 8 + ((lane & 3) << 1);
                        float v0 = acc[mt][nt][2 * h], v1 = acc[mt][nt][2 * h + 1];
                        if (v0 > *bvp) { *bvp = v0; *bip = col; }
                        if (v1 > *bvp) { *bvp = v1; *bip = col + 1; }
                    }
                }
        }
#pragma unroll
        for (int i = 0; i < 8; i++) {
            float v = bv[i]; int c = bi[i];
#pragma unroll
            for (int off = 1; off <= 2; off <<= 1) {
                float ov = __shfl_xor_sync(0xffffffffu, v, off);
                int   oc = __shfl_xor_sync(0xffffffffu, c, off);
                if (ov > v || (ov == v && oc < c)) { v = ov; c = oc; }
            }
            if ((lane & 3) == 0) {
                int row = warp_m + (i >> 1) * 16 + (i & 1) * 8 + (lane >> 2);
                sval[row][wid & 1] = v;
                sidx[row][wid & 1] = c;
            }
        }
        __syncthreads();
        {
            float v = sval[tid][0]; int c = sidx[tid][0];
            float ov = sval[tid][1]; int oc = sidx[tid][1];
            if (ov > v || (ov == v && oc < c)) { v = ov; c = oc; }
            idx_out[part * NROWS + m0 + tid] = c;
            atomicAdd(&g_cnt_i[part ? NGD + c : c], 1);
        }
        __syncthreads();
    }
}

// ---------------- scan / fill / gather dict update --------------------------
__global__ __launch_bounds__(256)
void scan_kernel() {
    __shared__ int ws[8];
    const int tid = threadIdx.x, lane = tid & 31, wid = tid >> 5;
    int v[5]; int s = 0;
#pragma unroll
    for (int i = 0; i < 5; i++) { v[i] = g_cnt_i[tid * 5 + i]; s += v[i]; }
    int x = s;
#pragma unroll
    for (int off = 1; off < 32; off <<= 1) {
        int t = __shfl_up_sync(0xffffffffu, x, off);
        if (lane >= off) x += t;
    }
    if (lane == 31) ws[wid] = x;
    __syncthreads();
    if (tid == 0) {
        int a = 0;
#pragma unroll
        for (int w = 0; w < 8; w++) { int t = ws[w]; ws[w] = a; a += t; }
    }
    __syncthreads();
    int run = x - s + ws[wid];
#pragma unroll
    for (int i = 0; i < 5; i++) {
        g_off[tid * 5 + i] = run;
        g_cnts[tid * 5 + i] = (float)v[i];
        run += v[i];
    }
}

__global__ __launch_bounds__(256)
void fill_list_kernel(const int* __restrict__ idx) {
    const int r = blockIdx.x * blockDim.x + threadIdx.x;
    if (r < NROWS) {
        int ig = idx[r];
        int pos = atomicAdd(&g_cur[ig], 1);
        g_list[g_off[ig] + pos] = r;
        int il = NGD + idx[NROWS + r];
        int pos2 = atomicAdd(&g_cur[il], 1);
        g_list[g_off[il] + pos2] = r;
    }
}

__global__ __launch_bounds__(256)
void dictupd_kernel(const float* __restrict__ gd, const float* __restrict__ ld,
                    bf* __restrict__ ch, bf* __restrict__ cl) {
    __shared__ float red[8];
    const int c = blockIdx.x, tid = threadIdx.x;
    const int cnt = g_cnt_i[c], off = g_off[c];
    float4 acc = make_float4(0.f, 0.f, 0.f, 0.f);
    int i = 0;
    for (; i + 1 < cnt; i += 2) {
        int r0 = g_list[off + i], r1 = g_list[off + i + 1];
        float4 a = *reinterpret_cast<const float4*>(&g_nn[(size_t)r0 * DDIM + tid * 4]);
        float4 b = *reinterpret_cast<const float4*>(&g_nn[(size_t)r1 * DDIM + tid * 4]);
        acc.x += a.x + b.x; acc.y += a.y + b.y; acc.z += a.z + b.z; acc.w += a.w + b.w;
    }
    if (i < cnt) {
        int r0 = g_list[off + i];
        float4 a = *reinterpret_cast<const float4*>(&g_nn[(size_t)r0 * DDIM + tid * 4]);
        acc.x += a.x; acc.y += a.y; acc.z += a.z; acc.w += a.w;
    }
    const float* dsrc = (c < NGD) ? (gd + (size_t)c * DDIM) : (ld + (size_t)(c - NGD) * DDIM);
    const float m = (c < NGD) ? 0.999f : 0.8f;
    float4 d = *reinterpret_cast<const float4*>(&dsrc[tid * 4]);
    float u0, u1, u2, u3;
    if (cnt > 0) {
        float w = (1.f - m) / (float)cnt;
        u0 = m * d.x + w * acc.x; u1 = m * d.y + w * acc.y;
        u2 = m * d.z + w * acc.z; u3 = m * d.w + w * acc.w;
    } else { u0 = d.x; u1 = d.y; u2 = d.z; u3 = d.w; }
    float ss = u0 * u0 + u1 * u1 + u2 * u2 + u3 * u3;
#pragma unroll
    for (int off2 = 16; off2; off2 >>= 1) ss += __shfl_down_sync(0xffffffffu, ss, off2);
    if ((tid & 31) == 0) red[tid >> 5] = ss;
    __syncthreads();
    if (tid == 0) {
        float s = 0.f;
#pragma unroll
        for (int j = 0; j < 8; j++) s += red[j];
        red[0] = s;
    }
    __syncthreads();
    float inv = 1.f / fmaxf(sqrtf(red[0]), 1e-12f);
    float f[4] = {u0 * inv, u1 * inv, u2 * inv, u3 * inv};
    size_t o = (size_t)c * DDIM + tid * 4;
    *reinterpret_cast<float4*>(&g_comb[o]) = make_float4(f[0], f[1], f[2], f[3]);
    bf h[4], l[4];
#pragma unroll
    for (int j = 0; j < 4; j++) split2(f[j], h[j], l[j]);
    *reinterpret_cast<uint2*>(&ch[o]) = *reinterpret_cast<uint2*>(h);
    *reinterpret_cast<uint2*>(&cl[o]) = *reinterpret_cast<uint2*>(l);
}

// ---------------- softmax ----------------------------------------------------
__global__ __launch_bounds__(256)
void softmax_split_kernel(const float* __restrict__ S, bf* __restrict__ Wh,
                          bf* __restrict__ Wl) {
    __shared__ float red[8];
    const int r = blockIdx.x, tid = threadIdx.x;
    const float* s = S + (size_t)r * NCOMB;
    float v[5];
#pragma unroll
    for (int i = 0; i < 5; i++) v[i] = s[tid + i * 256];
    float mx = v[0];
#pragma unroll
    for (int i = 1; i < 5; i++) mx = fmaxf(mx, v[i]);
#pragma unroll
    for (int off = 16; off; off >>= 1) mx = fmaxf(mx, __shfl_down_sync(0xffffffffu, mx, off));
    if ((tid & 31) == 0) red[tid >> 5] = mx;
    __syncthreads();
    if (tid == 0) {
        float t = red[0];
#pragma unroll
        for (int i = 1; i < 8; i++) t = fmaxf(t, red[i]);
        red[0] = t;
    }
    __syncthreads();
    mx = red[0];
    __syncthreads();
    float ssum = 0.f;
#pragma unroll
    for (int i = 0; i < 5; i++) { v[i] = expf((v[i] - mx) * (1.f / 0.07f)); ssum += v[i]; }
#pragma unroll
    for (int off = 16; off; off >>= 1) ssum += __shfl_down_sync(0xffffffffu, ssum, off);
    if ((tid & 31) == 0) red[tid >> 5] = ssum;
    __syncthreads();
    if (tid == 0) {
        float t = 0.f;
#pragma unroll
        for (int i = 0; i < 8; i++) t += red[i];
        red[0] = t;
    }
    __syncthreads();
    float inv = 1.f / red[0];
#pragma unroll
    for (int i = 0; i < 5; i++) {
        bf h, l;
        split2(v[i] * inv, h, l);
        Wh[(size_t)r * NCOMB + tid + i * 256] = h;
        Wl[(size_t)r * NCOMB + tid + i * 256] = l;
    }
}

__global__ void finalize_kernel(float* out_loss) {
    *out_loss = (float)(g_acc[0] / ((double)NROWS * (double)NGD) +
                        g_acc[1] / ((double)NROWS * (double)NLD) +
                        g_acc[2] / (double)NROWS);
}

// ---------------- launch ----------------------------------------------------
extern "C" void kernel_launch(void* const* d_in, const int* in_sizes, int n_in,
                              void* d_out, int out_size) {
    const float* z  = (const float*)d_in[0];
    const float* u  = (const float*)d_in[1];
    const float* W1 = (const float*)d_in[2];
    const float* b1 = (const float*)d_in[3];
    const float* W2 = (const float*)d_in[4];
    const float* b2 = (const float*)d_in[5];
    const float* Wg = (const float*)d_in[6];
    const float* bg = (const float*)d_in[7];
    const float* gd = (const float*)d_in[8];
    const float* ld = (const float*)d_in[9];

    float* out       = (float*)d_out;
    float* out_zc    = out;
    float* out_loss  = out + (size_t)NROWS * DDIM;
    float* out_zproj = out_loss + 1;
    float* out_u     = out_zproj + (size_t)NROWS * DDIM;

    static float *p_zp = nullptr, *p_nn, *p_zn, *p_gate, *p_S, *p_comb;
    static int* p_idx;
    static bf *zb, *hb, *zpb, *nnb, *znb, *Sb, *W1T, *W2T, *WgT, *gdb, *ldb, *cbb, *ctb;
    static size_t szNM, szNS, szDD, szGD, szLD, szCB;
    if (!p_zp) {
        cudaGetSymbolAddress((void**)&p_zp, g_zp);
        cudaGetSymbolAddress((void**)&p_nn, g_nn);
        cudaGetSymbolAddress((void**)&p_zn, g_zn);
        cudaGetSymbolAddress((void**)&p_gate, g_gate);
        cudaGetSymbolAddress((void**)&p_S, g_S);
        cudaGetSymbolAddress((void**)&p_comb, g_comb);
        cudaGetSymbolAddress((void**)&p_idx, g_idx);
        cudaGetSymbolAddress((void**)&zb, b_z);
        cudaGetSymbolAddress((void**)&hb, b_h);
        cudaGetSymbolAddress((void**)&zpb, b_zp);
        cudaGetSymbolAddress((void**)&nnb, b_nn);
        cudaGetSymbolAddress((void**)&znb, b_zn);
        cudaGetSymbolAddress((void**)&Sb, b_S);
        cudaGetSymbolAddress((void**)&W1T, b_W1T);
        cudaGetSymbolAddress((void**)&W2T, b_W2T);
        cudaGetSymbolAddress((void**)&WgT, b_WgT);
        cudaGetSymbolAddress((void**)&gdb, b_gd);
        cudaGetSymbolAddress((void**)&ldb, b_ld);
        cudaGetSymbolAddress((void**)&cbb, b_comb);
        cudaGetSymbolAddress((void**)&ctb, b_combT);
        szNM = NM; szNS = (size_t)NROWS * NCOMB; szDD = DDIM * DDIM;
        szGD = NGD * DDIM; szLD = NLD * DDIM; szCB = NCOMB * DDIM;
        cudaFuncSetAttribute(gemm_mma<EPI_RELU_BIAS, false, true, false>,
                             cudaFuncAttributeMaxDynamicSharedMemorySize, SM_TOTAL);
        cudaFuncSetAttribute(gemm_mma<EPI_BIAS, true, true, true>,
                             cudaFuncAttributeMaxDynamicSharedMemorySize, SM_TOTAL);
        cudaFuncSetAttribute(gemm_mma<EPI_SIGMOID, true, false, false>,
                             cudaFuncAttributeMaxDynamicSharedMemorySize, SM_TOTAL);
        cudaFuncSetAttribute(gemm_mma<EPI_S_LOSS, true, false, false>,
                             cudaFuncAttributeMaxDynamicSharedMemorySize, SM_TOTAL);
        cudaFuncSetAttribute(gemm_mma<EPI_ZCLEAN, true, false, false>,
                             cudaFuncAttributeMaxDynamicSharedMemorySize, SM_TOTAL);
        cudaFuncSetAttribute(argmax_dual,
                             cudaFuncAttributeMaxDynamicSharedMemorySize, SM_TOTAL);
    }

    const dim3 gD(DDIM / 128, NROWS / 128);

    // [0] init
    init_kernel<<<5, 256>>>();
    // [1] convert z
    conv_split_kernel<<<NM / 1024, 256>>>(z, zb, zb + szNM, NM);
    // [2] W1^T
    transconv_kernel<<<dim3(DDIM / 32, DDIM / 32), 256>>>(W1, DDIM, DDIM, W1T, W1T + szDD);
    // [3] proj1 GEMM  <-- ncu capture window target
    gemm_mma<EPI_RELU_BIAS, false, true, false><<<gD, 128, SM_TOTAL>>>(
        zb, zb + szNM, W1T, W1T + szDD, b1, nullptr, hb, hb + szNM, nullptr, DDIM, DDIM,
        nullptr, nullptr);
    // [4..7] remaining conversions
    conv_split_kernel<<<(NGD * DDIM) / 1024, 256>>>(gd, gdb, gdb + szGD, NGD * DDIM);
    conv_split_kernel<<<(NLD * DDIM) / 1024, 256>>>(ld, ldb, ldb + szLD, NLD * DDIM);
    transconv_kernel<<<dim3(DDIM / 32, DDIM / 32), 256>>>(W2, DDIM, DDIM, W2T, W2T + szDD);
    transconv_kernel<<<dim3(DDIM / 32, DDIM / 32), 256>>>(Wg, DDIM, DDIM, WgT, WgT + szDD);
    // [8] noise_norm + fused raw-u copy
    rownorm_split_kernel<<<NROWS, 256>>>(u, p_nn, nnb, nnb + szNM, out_u, nullptr);
    // [9] proj2
    gemm_mma<EPI_BIAS, true, true, true><<<gD, 128, SM_TOTAL>>>(
        hb, hb + szNM, W2T, W2T + szDD, b2, p_zp, zpb, zpb + szNM, out_zproj, DDIM, DDIM,
        nullptr, nullptr);
    // [10] z_norm + fused loss_direct
    rownorm_split_kernel<<<NROWS, 256>>>(p_zp, p_zn, znb, znb + szNM, nullptr, p_nn);
    // [11] gate
    gemm_mma<EPI_SIGMOID, true, false, false><<<gD, 128, SM_TOTAL>>>(
        zpb, zpb + szNM, WgT, WgT + szDD, bg, p_gate, nullptr, nullptr, nullptr, DDIM, DDIM,
        nullptr, nullptr);
    // [12] dual argmax + counts
    argmax_dual<<<NROWS / 128, 128, SM_TOTAL>>>(nnb, nnb + szNM,
                                                gdb, gdb + szGD, ldb, ldb + szLD, p_idx);
    // [13..15] scan / fill lists / gather dict update
    scan_kernel<<<1, 256>>>();
    fill_list_kernel<<<NROWS / 256, 256>>>(p_idx);
    dictupd_kernel<<<NCOMB, 256>>>(gd, ld, cbb, cbb + szCB);
    // [16] S = z_norm @ comb^T (+ fused sum|S|)
    gemm_mma<EPI_S_LOSS, true, false, false><<<dim3(NCOMB / 128, NROWS / 128), 128, SM_TOTAL>>>(
        znb, znb + szNM, cbb, cbb + szCB, nullptr, p_S, nullptr, nullptr, nullptr, NCOMB, DDIM,
        nullptr, nullptr);
    // [17..18] softmax + comb^T
    softmax_split_kernel<<<NROWS, 256>>>(p_S, Sb, Sb + szNS);
    transconv_kernel<<<dim3(DDIM / 32, NCOMB / 32), 256>>>(p_comb, NCOMB, DDIM, ctb, ctb + szCB);
    // [19] weighted_u + fused z_clean
    gemm_mma<EPI_ZCLEAN, true, false, false><<<gD, 128, SM_TOTAL>>>(
        Sb, Sb + szNS, ctb, ctb + szCB, nullptr, out_zc, nullptr, nullptr, nullptr, DDIM, NCOMB,
        z, p_gate);
    // [20] finalize loss
    finalize_kernel<<<1, 1>>>(out_loss);
}

// round 14
// speedup vs baseline: 3.8083x; 1.2685x over previous
#include <cuda_runtime.h>
#include <cuda_bf16.h>
#include <math.h>
#include <stdint.h>

#define NROWS 32768
#define DDIM  1024
#define NGD   1024
#define NLD   256
#define NCOMB 1280
#define NM    (NROWS * DDIM)

typedef __nv_bfloat16 bf;

// ---------------- warp MMA primitives (plain sm_80+ PTX, no 'a' features) --
__device__ __forceinline__ uint32_t smem_u32(const void* p) {
    uint32_t a;
    asm("{ .reg .u64 t; cvta.to.shared.u64 t, %1; cvt.u32.u64 %0, t; }" : "=r"(a) : "l"(p));
    return a;
}
__device__ __forceinline__ void ldsm4(uint32_t addr, uint32_t* f) {
    asm volatile("ldmatrix.sync.aligned.m8n8.x4.shared.b16 {%0,%1,%2,%3}, [%4];"
                 : "=r"(f[0]), "=r"(f[1]), "=r"(f[2]), "=r"(f[3]) : "r"(addr));
}
__device__ __forceinline__ void mma16816(float* c, const uint32_t* a, uint32_t b0, uint32_t b1) {
    asm volatile("mma.sync.aligned.m16n8k16.row.col.f32.bf16.bf16.f32 "
                 "{%0,%1,%2,%3}, {%4,%5,%6,%7}, {%8,%9}, {%0,%1,%2,%3};"
                 : "+f"(c[0]), "+f"(c[1]), "+f"(c[2]), "+f"(c[3])
                 : "r"(a[0]), "r"(a[1]), "r"(a[2]), "r"(a[3]), "r"(b0), "r"(b1));
}
__device__ __forceinline__ void cp16(uint32_t dst, const void* src) {
    asm volatile("cp.async.cg.shared.global [%0], [%1], 16;" :: "r"(dst), "l"(src));
}
#define CP_COMMIT() asm volatile("cp.async.commit_group;" ::: "memory")
#define CP_WAIT(n)  asm volatile("cp.async.wait_group %0;" :: "n"(n) : "memory")

__device__ __forceinline__ void split2(float x, bf& h, bf& l) {
    h = __float2bfloat16(x);
    l = __float2bfloat16(x - __bfloat162float(h));
}

// ---------------- scratch ---------------------------------------------------
__device__ float  g_zp[NM];
__device__ float  g_nn[NM];
__device__ float  g_zn[NM];
__device__ float  g_gate[NM];
__device__ float  g_S[(size_t)NROWS * NCOMB];
__device__ float  g_comb[NCOMB * DDIM];
__device__ float  g_cnts[NCOMB];
__device__ int    g_cnt_i[NCOMB];
__device__ int    g_cur[NCOMB];
__device__ int    g_off[NCOMB];
__device__ int    g_list[2 * NROWS];
__device__ int    g_idx[2 * NROWS];
__device__ double g_acc[3];

__device__ bf b_z[2][NM];
__device__ bf b_h[2][NM];
__device__ bf b_zp[2][NM];
__device__ bf b_nn[2][NM];
__device__ bf b_zn[2][NM];
__device__ bf b_S[2][(size_t)NROWS * NCOMB];
__device__ bf b_W1T[2][DDIM * DDIM];
__device__ bf b_W2T[2][DDIM * DDIM];
__device__ bf b_WgT[2][DDIM * DDIM];
__device__ bf b_gd[2][NGD * DDIM];
__device__ bf b_ld[2][NLD * DDIM];
__device__ bf b_comb[2][NCOMB * DDIM];
__device__ bf b_combT[2][DDIM * NCOMB];

// ---------------- small kernels --------------------------------------------
__global__ void init_kernel() {
    int i = blockIdx.x * blockDim.x + threadIdx.x;
    if (i < NCOMB) { g_cnt_i[i] = 0; g_cur[i] = 0; }
    if (i < 3)     g_acc[i] = 0.0;
}

__global__ __launch_bounds__(256)
void conv_split_kernel(const float* __restrict__ src, bf* __restrict__ dh,
                       bf* __restrict__ dl, int n) {
    int i = (blockIdx.x * blockDim.x + threadIdx.x) * 4;
    if (i + 3 < n) {
        float4 v = *reinterpret_cast<const float4*>(&src[i]);
        bf h[4], l[4];
        split2(v.x, h[0], l[0]); split2(v.y, h[1], l[1]);
        split2(v.z, h[2], l[2]); split2(v.w, h[3], l[3]);
        *reinterpret_cast<uint2*>(&dh[i]) = *reinterpret_cast<uint2*>(h);
        *reinterpret_cast<uint2*>(&dl[i]) = *reinterpret_cast<uint2*>(l);
    }
}

// tiled transpose + split: src [R][C] fp32 -> dst [c][r] bf16 hi/lo
__global__ __launch_bounds__(256)
void transconv_kernel(const float* __restrict__ src, int R, int C,
                      bf* __restrict__ dh, bf* __restrict__ dl) {
    __shared__ float t[32][33];
    const int bx = blockIdx.x * 32, by = blockIdx.y * 32;
    const int tx = threadIdx.x & 31, ty = threadIdx.x >> 5;
#pragma unroll
    for (int i = 0; i < 4; i++)
        t[ty + 8 * i][tx] = src[(size_t)(by + ty + 8 * i) * C + bx + tx];
    __syncthreads();
#pragma unroll
    for (int i = 0; i < 4; i++) {
        float x = t[tx][ty + 8 * i];
        bf h, l; split2(x, h, l);
        size_t o = (size_t)(bx + ty + 8 * i) * R + by + tx;
        dh[o] = h; dl[o] = l;
    }
}

// row L2 normalize; fp32 + bf16 hi/lo; optional raw copy; optional fused
// |dot(normalized, UN_row)| accumulation into g_acc[2]
__global__ __launch_bounds__(256)
void rownorm_split_kernel(const float* __restrict__ X, float* __restrict__ Y,
                          bf* __restrict__ Yh, bf* __restrict__ Yl,
                          float* __restrict__ Cpy, const float* __restrict__ UN) {
    __shared__ float red[8];
    const int r = blockIdx.x, tid = threadIdx.x;
    float4 x = *reinterpret_cast<const float4*>(&X[(size_t)r * DDIM + tid * 4]);
    float ss = x.x * x.x + x.y * x.y + x.z * x.z + x.w * x.w;
#pragma unroll
    for (int off = 16; off; off >>= 1) ss += __shfl_down_sync(0xffffffffu, ss, off);
    if ((tid & 31) == 0) red[tid >> 5] = ss;
    __syncthreads();
    if (tid == 0) {
        float s = 0.f;
#pragma unroll
        for (int i = 0; i < 8; i++) s += red[i];
        red[0] = s;
    }
    __syncthreads();
    float inv = 1.f / fmaxf(sqrtf(red[0]), 1e-12f);
    float f[4] = {x.x * inv, x.y * inv, x.z * inv, x.w * inv};
    size_t o = (size_t)r * DDIM + tid * 4;
    *reinterpret_cast<float4*>(&Y[o]) = make_float4(f[0], f[1], f[2], f[3]);
    bf h[4], l[4];
#pragma unroll
    for (int i = 0; i < 4; i++) split2(f[i], h[i], l[i]);
    *reinterpret_cast<uint2*>(&Yh[o]) = *reinterpret_cast<uint2*>(h);
    *reinterpret_cast<uint2*>(&Yl[o]) = *reinterpret_cast<uint2*>(l);
    if (Cpy) { Cpy[o] = x.x; Cpy[o + 1] = x.y; Cpy[o + 2] = x.z; Cpy[o + 3] = x.w; }
    if (UN) {
        float4 un = *reinterpret_cast<const float4*>(&UN[o]);
        float p = f[0] * un.x + f[1] * un.y + f[2] * un.z + f[3] * un.w;
#pragma unroll
        for (int off = 16; off; off >>= 1) p += __shfl_down_sync(0xffffffffu, p, off);
        __syncthreads();
        if ((tid & 31) == 0) red[tid >> 5] = p;
        __syncthreads();
        if (tid == 0) {
            float s = 0.f;
#pragma unroll
            for (int i = 0; i < 8; i++) s += red[i];
            atomicAdd(&g_acc[2], (double)fabsf(s));
        }
    }
}

// ---------------- HMMA GEMM (3-stage cp.async, XOR swizzle, 4 warps @64x64) --
// NPROD: 1 = ah*bh, 2 = (ah+al)*bh, 3 = full hi/lo split
enum { EPI_RELU_BIAS = 0, EPI_BIAS = 1, EPI_SIGMOID = 2, EPI_S_LOSS = 3, EPI_ZCLEAN = 4 };

#define TILE_B  8192                 // 128 rows x 64 bytes (32 bf16), swizzled
#define STAGE_B (4 * TILE_B)         // 32768 per stage (slots: Ah, Al, Bh, Bl)
#define SM_TOTAL (3 * STAGE_B)       // 98304 : 2 CTAs/SM

// swizzled byte offset inside a tile: row in [0,128), c16 in [0,4)
__device__ __forceinline__ uint32_t swz(int row, int c16) {
    return (uint32_t)(row * 64 + ((c16 ^ ((row >> 1) & 3)) << 4));
}

// cp.async fill of one 32-wide K-chunk into stage s; loads only tiles NPROD needs
template <int NPROD>
__device__ __forceinline__ void fill_async(
    uint32_t sb, int s,
    const bf* __restrict__ Ah, const bf* __restrict__ Al,
    const bf* __restrict__ Bh, const bf* __restrict__ Bl,
    int m0, int n0, int k0, int K, int tid) {
    const uint32_t base = sb + s * STAGE_B;
#pragma unroll
    for (int t = 0; t < 4; t++) {
        if (t == 1 && NPROD < 2) continue;   // Al unused
        if (t == 3 && NPROD < 3) continue;   // Bl unused
        const bf* gp = (t == 0) ? Ah : (t == 1) ? Al : (t == 2) ? Bh : Bl;
        const int rb = (t < 2) ? m0 : n0;
        const uint32_t tb = base + t * TILE_B;
#pragma unroll
        for (int v = 0; v < 4; v++) {
            int idx = v * 128 + tid;
            int row = idx >> 2, c16 = idx & 3;
            cp16(tb + swz(row, c16), gp + (size_t)(rb + row) * K + k0 + c16 * 8);
        }
    }
    CP_COMMIT();
}

// NPROD-tiered compute of one K-chunk into acc[4][8][4] (warp 64x64)
template <int NPROD>
__device__ __forceinline__ void chunk_mma(float acc[4][8][4], uint32_t base,
                                          int lane, int warp_m, int warp_n) {
    const int arow = warp_m + (lane & 15);
    const int ahi  = lane >> 4;
    const int brow = warp_n + ((lane & 7) | ((lane >> 4) << 3));
    const int bhi  = (lane >> 3) & 1;
#pragma unroll
    for (int ks = 0; ks < 2; ks++) {
        uint32_t bh[16], bl[16];
#pragma unroll
        for (int i = 0; i < 4; i++) {
            uint32_t off = swz(brow + i * 16, ks * 2 + bhi);
            ldsm4(base + 2 * TILE_B + off, bh + 4 * i);
            if (NPROD >= 3) ldsm4(base + 3 * TILE_B + off, bl + 4 * i);
        }
#pragma unroll
        for (int mt = 0; mt < 4; mt++) {
            uint32_t off = swz(arow + mt * 16, ks * 2 + ahi);
            uint32_t ah[4], al[4];
            ldsm4(base + off, ah);
            if (NPROD >= 2) ldsm4(base + TILE_B + off, al);
#pragma unroll
            for (int nt = 0; nt < 8; nt++) {
                mma16816(acc[mt][nt], ah, bh[2 * nt], bh[2 * nt + 1]);
                if (NPROD >= 3) mma16816(acc[mt][nt], ah, bl[2 * nt], bl[2 * nt + 1]);
                if (NPROD >= 2) mma16816(acc[mt][nt], al, bh[2 * nt], bh[2 * nt + 1]);
            }
        }
    }
}

// 3-stage mainloop: one __syncthreads per chunk.
#define GEMM_MAINLOOP(NP, Ahp, Alp, Bhp, Blp, M0, N0, KK)                               \
    do {                                                                                \
        const int nch = (KK) >> 5;                                                      \
        fill_async<NP>(sb, 0, Ahp, Alp, Bhp, Blp, M0, N0, 0, KK, tid);                  \
        fill_async<NP>(sb, 1, Ahp, Alp, Bhp, Blp, M0, N0, 32, KK, tid);                 \
        for (int kc = 0; kc < nch; kc++) {                                              \
            if (kc + 1 < nch) { CP_WAIT(1); } else { CP_WAIT(0); }                      \
            __syncthreads();                                                            \
            if (kc + 2 < nch)                                                           \
                fill_async<NP>(sb, (kc + 2) % 3, Ahp, Alp, Bhp, Blp, M0, N0,            \
                               (kc + 2) << 5, KK, tid);                                 \
            chunk_mma<NP>(acc, sb + (kc % 3) * STAGE_B, lane, warp_m, warp_n);          \
        }                                                                               \
    } while (0)

template <int EPI, int NPROD, bool WF32, bool WSPLIT, bool WMIS>
__global__ __launch_bounds__(128)
void gemm_mma(const bf* __restrict__ Ah, const bf* __restrict__ Al,
              const bf* __restrict__ Bh, const bf* __restrict__ Bl,
              const float* __restrict__ bias, float* __restrict__ Cf,
              bf* __restrict__ Ch, bf* __restrict__ Cl, float* __restrict__ Cm,
              int Ncols, int K,
              const float* __restrict__ e1, const float* __restrict__ e2) {
    extern __shared__ __align__(16) char smem[];
    const uint32_t sb = smem_u32(smem);
    const int tid = threadIdx.x, lane = tid & 31, wid = tid >> 5;
    const int m0 = blockIdx.y * 128, n0 = blockIdx.x * 128;
    const int warp_m = (wid >> 1) * 64, warp_n = (wid & 1) * 64;

    float acc[4][8][4] = {};
    GEMM_MAINLOOP(NPROD, Ah, Al, Bh, Bl, m0, n0, K);

    // ---------------- epilogue ----------------
    double part = 0.0;
#pragma unroll
    for (int mt = 0; mt < 4; mt++) {
        const int r0 = m0 + warp_m + mt * 16 + (lane >> 2);
#pragma unroll
        for (int nt = 0; nt < 8; nt++) {
            const int col = n0 + warp_n + nt * 8 + ((lane & 3) << 1);
            float b2x = 0.f, b2y = 0.f;
            if (EPI == EPI_RELU_BIAS || EPI == EPI_BIAS || EPI == EPI_SIGMOID) {
                float2 bb = *reinterpret_cast<const float2*>(bias + col);
                b2x = bb.x; b2y = bb.y;
            }
#pragma unroll
            for (int h = 0; h < 2; h++) {
                const int row = r0 + h * 8;
                float v0 = acc[mt][nt][2 * h], v1 = acc[mt][nt][2 * h + 1];
                if (EPI == EPI_RELU_BIAS) { v0 = fmaxf(v0 + b2x, 0.f); v1 = fmaxf(v1 + b2y, 0.f); }
                else if (EPI == EPI_BIAS) { v0 += b2x; v1 += b2y; }
                else if (EPI == EPI_SIGMOID) {
                    v0 = 1.f / (1.f + expf(-(v0 + b2x)));
                    v1 = 1.f / (1.f + expf(-(v1 + b2y)));
                }
                const size_t ro = (size_t)row * Ncols + col;
                if (EPI == EPI_ZCLEAN) {
                    float2 z2 = *reinterpret_cast<const float2*>(e1 + ro);
                    float2 q2 = *reinterpret_cast<const float2*>(e2 + ro);
                    v0 = z2.x - q2.x * v0;
                    v1 = z2.y - q2.y * v1;
                }
                if (EPI == EPI_S_LOSS) part += (double)fabsf(v0) + (double)fabsf(v1);
                if (WF32)
                    *reinterpret_cast<float2*>(Cf + ro) = make_float2(v0, v1);
                if (WMIS) { Cm[ro] = v0; Cm[ro + 1] = v1; }
                if (WSPLIT) {
                    bf h0, l0, h1, l1;
                    split2(v0, h0, l0); split2(v1, h1, l1);
                    bf hp[2] = {h0, h1}, lp[2] = {l0, l1};
                    *reinterpret_cast<uint32_t*>(Ch + ro) = *reinterpret_cast<uint32_t*>(hp);
                    *reinterpret_cast<uint32_t*>(Cl + ro) = *reinterpret_cast<uint32_t*>(lp);
                }
            }
        }
    }
    if (EPI == EPI_S_LOSS) {
#pragma unroll
        for (int off = 16; off; off >>= 1) part += __shfl_down_sync(0xffffffffu, part, off);
        if (lane == 0) atomicAdd(&g_acc[(n0 < NGD) ? 0 : 1], part);
    }
}

// ---------------- dual-dict HMMA argmax + count ------------------------------
__global__ __launch_bounds__(128)
void argmax_dual(const bf* __restrict__ Ah, const bf* __restrict__ Al,
                 const bf* __restrict__ Gh, const bf* __restrict__ Gl,
                 const bf* __restrict__ Lh, const bf* __restrict__ Ll,
                 int* __restrict__ idx_out) {
    extern __shared__ __align__(16) char smem[];
    __shared__ float sval[128][2];
    __shared__ int   sidx[128][2];
    const uint32_t sb = smem_u32(smem);
    const int tid = threadIdx.x, lane = tid & 31, wid = tid >> 5;
    const int m0 = blockIdx.x * 128;
    const int warp_m = (wid >> 1) * 64, warp_n = (wid & 1) * 64;

    for (int part = 0; part < 2; part++) {
        const bf* Dh = part ? Lh : Gh;
        const bf* Dl = part ? Ll : Gl;
        const int ncodes = part ? NLD : NGD;

        float bv[8]; int bi[8];
#pragma unroll
        for (int i = 0; i < 8; i++) { bv[i] = -1e30f; bi[i] = 0; }

        for (int n0 = 0; n0 < ncodes; n0 += 128) {
            float acc[4][8][4] = {};
            GEMM_MAINLOOP(3, Ah, Al, Dh, Dl, m0, n0, DDIM);
            __syncthreads();  // reads done before next tile's preload overwrites
#pragma unroll
            for (int mt = 0; mt < 4; mt++)
#pragma unroll
                for (int h = 0; h < 2; h++) {
                    float* bvp = &bv[mt * 2 + h]; int* bip = &bi[mt * 2 + h];
#pragma unroll
                    for (int nt = 0; nt < 8; nt++) {
                        const int col = n0 + warp_n + nt * 8 + ((lane & 3) << 1);
                        float v0 = acc[mt][nt][2 * h], v1 = acc[mt][nt][2 * h + 1];
                        if (v0 > *bvp) { *bvp = v0; *bip = col; }
                        if (v1 > *bvp) { *bvp = v1; *bip = col + 1; }
                    }
                }
        }
#pragma unroll
        for (int i = 0; i < 8; i++) {
            float v = bv[i]; int c = bi[i];
#pragma unroll
            for (int off = 1; off <= 2; off <<= 1) {
                float ov = __shfl_xor_sync(0xffffffffu, v, off);
                int   oc = __shfl_xor_sync(0xffffffffu, c, off);
                if (ov > v || (ov == v && oc < c)) { v = ov; c = oc; }
            }
            if ((lane & 3) == 0) {
                int row = warp_m + (i >> 1) * 16 + (i & 1) * 8 + (lane >> 2);
                sval[row][wid & 1] = v;
                sidx[row][wid & 1] = c;
            }
        }
        __syncthreads();
        {
            float v = sval[tid][0]; int c = sidx[tid][0];
            float ov = sval[tid][1]; int oc = sidx[tid][1];
            if (ov > v || (ov == v && oc < c)) { v = ov; c = oc; }
            idx_out[part * NROWS + m0 + tid] = c;
            atomicAdd(&g_cnt_i[part ? NGD + c : c], 1);
        }
        __syncthreads();
    }
}

// ---------------- scan / fill / gather dict update --------------------------
__global__ __launch_bounds__(256)
void scan_kernel() {
    __shared__ int ws[8];
    const int tid = threadIdx.x, lane = tid & 31, wid = tid >> 5;
    int v[5]; int s = 0;
#pragma unroll
    for (int i = 0; i < 5; i++) { v[i] = g_cnt_i[tid * 5 + i]; s += v[i]; }
    int x = s;
#pragma unroll
    for (int off = 1; off < 32; off <<= 1) {
        int t = __shfl_up_sync(0xffffffffu, x, off);
        if (lane >= off) x += t;
    }
    if (lane == 31) ws[wid] = x;
    __syncthreads();
    if (tid == 0) {
        int a = 0;
#pragma unroll
        for (int w = 0; w < 8; w++) { int t = ws[w]; ws[w] = a; a += t; }
    }
    __syncthreads();
    int run = x - s + ws[wid];
#pragma unroll
    for (int i = 0; i < 5; i++) {
        g_off[tid * 5 + i] = run;
        g_cnts[tid * 5 + i] = (float)v[i];
        run += v[i];
    }
}

__global__ __launch_bounds__(256)
void fill_list_kernel(const int* __restrict__ idx) {
    const int r = blockIdx.x * blockDim.x + threadIdx.x;
    if (r < NROWS) {
        int ig = idx[r];
        int pos = atomicAdd(&g_cur[ig], 1);
        g_list[g_off[ig] + pos] = r;
        int il = NGD + idx[NROWS + r];
        int pos2 = atomicAdd(&g_cur[il], 1);
        g_list[g_off[il] + pos2] = r;
    }
}

__global__ __launch_bounds__(256)
void dictupd_kernel(const float* __restrict__ gd, const float* __restrict__ ld,
                    bf* __restrict__ ch, bf* __restrict__ cl) {
    __shared__ float red[8];
    const int c = blockIdx.x, tid = threadIdx.x;
    const int cnt = g_cnt_i[c], off = g_off[c];
    float4 acc = make_float4(0.f, 0.f, 0.f, 0.f);
    int i = 0;
    for (; i + 1 < cnt; i += 2) {
        int r0 = g_list[off + i], r1 = g_list[off + i + 1];
        float4 a = *reinterpret_cast<const float4*>(&g_nn[(size_t)r0 * DDIM + tid * 4]);
        float4 b = *reinterpret_cast<const float4*>(&g_nn[(size_t)r1 * DDIM + tid * 4]);
        acc.x += a.x + b.x; acc.y += a.y + b.y; acc.z += a.z + b.z; acc.w += a.w + b.w;
    }
    if (i < cnt) {
        int r0 = g_list[off + i];
        float4 a = *reinterpret_cast<const float4*>(&g_nn[(size_t)r0 * DDIM + tid * 4]);
        acc.x += a.x; acc.y += a.y; acc.z += a.z; acc.w += a.w;
    }
    const float* dsrc = (c < NGD) ? (gd + (size_t)c * DDIM) : (ld + (size_t)(c - NGD) * DDIM);
    const float m = (c < NGD) ? 0.999f : 0.8f;
    float4 d = *reinterpret_cast<const float4*>(&dsrc[tid * 4]);
    float u0, u1, u2, u3;
    if (cnt > 0) {
        float w = (1.f - m) / (float)cnt;
        u0 = m * d.x + w * acc.x; u1 = m * d.y + w * acc.y;
        u2 = m * d.z + w * acc.z; u3 = m * d.w + w * acc.w;
    } else { u0 = d.x; u1 = d.y; u2 = d.z; u3 = d.w; }
    float ss = u0 * u0 + u1 * u1 + u2 * u2 + u3 * u3;
#pragma unroll
    for (int off2 = 16; off2; off2 >>= 1) ss += __shfl_down_sync(0xffffffffu, ss, off2);
    if ((tid & 31) == 0) red[tid >> 5] = ss;
    __syncthreads();
    if (tid == 0) {
        float s = 0.f;
#pragma unroll
        for (int j = 0; j < 8; j++) s += red[j];
        red[0] = s;
    }
    __syncthreads();
    float inv = 1.f / fmaxf(sqrtf(red[0]), 1e-12f);
    float f[4] = {u0 * inv, u1 * inv, u2 * inv, u3 * inv};
    size_t o = (size_t)c * DDIM + tid * 4;
    *reinterpret_cast<float4*>(&g_comb[o]) = make_float4(f[0], f[1], f[2], f[3]);
    bf h[4], l[4];
#pragma unroll
    for (int j = 0; j < 4; j++) split2(f[j], h[j], l[j]);
    *reinterpret_cast<uint2*>(&ch[o]) = *reinterpret_cast<uint2*>(h);
    *reinterpret_cast<uint2*>(&cl[o]) = *reinterpret_cast<uint2*>(l);
}

// ---------------- softmax ----------------------------------------------------
__global__ __launch_bounds__(256)
void softmax_split_kernel(const float* __restrict__ S, bf* __restrict__ Wh,
                          bf* __restrict__ Wl) {
    __shared__ float red[8];
    const int r = blockIdx.x, tid = threadIdx.x;
    const float* s = S + (size_t)r * NCOMB;
    float v[5];
#pragma unroll
    for (int i = 0; i < 5; i++) v[i] = s[tid + i * 256];
    float mx = v[0];
#pragma unroll
    for (int i = 1; i < 5; i++) mx = fmaxf(mx, v[i]);
#pragma unroll
    for (int off = 16; off; off >>= 1) mx = fmaxf(mx, __shfl_down_sync(0xffffffffu, mx, off));
    if ((tid & 31) == 0) red[tid >> 5] = mx;
    __syncthreads();
    if (tid == 0) {
        float t = red[0];
#pragma unroll
        for (int i = 1; i < 8; i++) t = fmaxf(t, red[i]);
        red[0] = t;
    }
    __syncthreads();
    mx = red[0];
    __syncthreads();
    float ssum = 0.f;
#pragma unroll
    for (int i = 0; i < 5; i++) { v[i] = expf((v[i] - mx) * (1.f / 0.07f)); ssum += v[i]; }
#pragma unroll
    for (int off = 16; off; off >>= 1) ssum += __shfl_down_sync(0xffffffffu, ssum, off);
    if ((tid & 31) == 0) red[tid >> 5] = ssum;
    __syncthreads();
    if (tid == 0) {
        float t = 0.f;
#pragma unroll
        for (int i = 0; i < 8; i++) t += red[i];
        red[0] = t;
    }
    __syncthreads();
    float inv = 1.f / red[0];
#pragma unroll
    for (int i = 0; i < 5; i++) {
        bf h, l;
        split2(v[i] * inv, h, l);
        Wh[(size_t)r * NCOMB + tid + i * 256] = h;
        Wl[(size_t)r * NCOMB + tid + i * 256] = l;
    }
}

__global__ void finalize_kernel(float* out_loss) {
    *out_loss = (float)(g_acc[0] / ((double)NROWS * (double)NGD) +
                        g_acc[1] / ((double)NROWS * (double)NLD) +
                        g_acc[2] / (double)NROWS);
}

// ---------------- launch ----------------------------------------------------
extern "C" void kernel_launch(void* const* d_in, const int* in_sizes, int n_in,
                              void* d_out, int out_size) {
    const float* z  = (const float*)d_in[0];
    const float* u  = (const float*)d_in[1];
    const float* W1 = (const float*)d_in[2];
    const float* b1 = (const float*)d_in[3];
    const float* W2 = (const float*)d_in[4];
    const float* b2 = (const float*)d_in[5];
    const float* Wg = (const float*)d_in[6];
    const float* bg = (const float*)d_in[7];
    const float* gd = (const float*)d_in[8];
    const float* ld = (const float*)d_in[9];

    float* out       = (float*)d_out;
    float* out_zc    = out;
    float* out_loss  = out + (size_t)NROWS * DDIM;
    float* out_zproj = out_loss + 1;
    float* out_u     = out_zproj + (size_t)NROWS * DDIM;

    static float *p_zp = nullptr, *p_nn, *p_zn, *p_gate, *p_S, *p_comb;
    static int* p_idx;
    static bf *zb, *hb, *zpb, *nnb, *znb, *Sb, *W1T, *W2T, *WgT, *gdb, *ldb, *cbb, *ctb;
    static size_t szNM, szNS, szDD, szGD, szLD, szCB;
    if (!p_zp) {
        cudaGetSymbolAddress((void**)&p_zp, g_zp);
        cudaGetSymbolAddress((void**)&p_nn, g_nn);
        cudaGetSymbolAddress((void**)&p_zn, g_zn);
        cudaGetSymbolAddress((void**)&p_gate, g_gate);
        cudaGetSymbolAddress((void**)&p_S, g_S);
        cudaGetSymbolAddress((void**)&p_comb, g_comb);
        cudaGetSymbolAddress((void**)&p_idx, g_idx);
        cudaGetSymbolAddress((void**)&zb, b_z);
        cudaGetSymbolAddress((void**)&hb, b_h);
        cudaGetSymbolAddress((void**)&zpb, b_zp);
        cudaGetSymbolAddress((void**)&nnb, b_nn);
        cudaGetSymbolAddress((void**)&znb, b_zn);
        cudaGetSymbolAddress((void**)&Sb, b_S);
        cudaGetSymbolAddress((void**)&W1T, b_W1T);
        cudaGetSymbolAddress((void**)&W2T, b_W2T);
        cudaGetSymbolAddress((void**)&WgT, b_WgT);
        cudaGetSymbolAddress((void**)&gdb, b_gd);
        cudaGetSymbolAddress((void**)&ldb, b_ld);
        cudaGetSymbolAddress((void**)&cbb, b_comb);
        cudaGetSymbolAddress((void**)&ctb, b_combT);
        szNM = NM; szNS = (size_t)NROWS * NCOMB; szDD = DDIM * DDIM;
        szGD = NGD * DDIM; szLD = NLD * DDIM; szCB = NCOMB * DDIM;
        cudaFuncSetAttribute(gemm_mma<EPI_RELU_BIAS, 3, false, true, false>,
                             cudaFuncAttributeMaxDynamicSharedMemorySize, SM_TOTAL);
        cudaFuncSetAttribute(gemm_mma<EPI_BIAS, 3, true, true, true>,
                             cudaFuncAttributeMaxDynamicSharedMemorySize, SM_TOTAL);
        cudaFuncSetAttribute(gemm_mma<EPI_SIGMOID, 1, true, false, false>,
                             cudaFuncAttributeMaxDynamicSharedMemorySize, SM_TOTAL);
        cudaFuncSetAttribute(gemm_mma<EPI_S_LOSS, 2, true, false, false>,
                             cudaFuncAttributeMaxDynamicSharedMemorySize, SM_TOTAL);
        cudaFuncSetAttribute(gemm_mma<EPI_ZCLEAN, 1, true, false, false>,
                             cudaFuncAttributeMaxDynamicSharedMemorySize, SM_TOTAL);
        cudaFuncSetAttribute(argmax_dual,
                             cudaFuncAttributeMaxDynamicSharedMemorySize, SM_TOTAL);
    }

    const dim3 gD(DDIM / 128, NROWS / 128);

    // [0] init
    init_kernel<<<5, 256>>>();
    // [1] convert z
    conv_split_kernel<<<NM / 1024, 256>>>(z, zb, zb + szNM, NM);
    // [2] W1^T
    transconv_kernel<<<dim3(DDIM / 32, DDIM / 32), 256>>>(W1, DDIM, DDIM, W1T, W1T + szDD);
    // [3] proj1 GEMM (NPROD=3)  <-- ncu capture window target
    gemm_mma<EPI_RELU_BIAS, 3, false, true, false><<<gD, 128, SM_TOTAL>>>(
        zb, zb + szNM, W1T, W1T + szDD, b1, nullptr, hb, hb + szNM, nullptr, DDIM, DDIM,
        nullptr, nullptr);
    // [4..7] remaining conversions
    conv_split_kernel<<<(NGD * DDIM) / 1024, 256>>>(gd, gdb, gdb + szGD, NGD * DDIM);
    conv_split_kernel<<<(NLD * DDIM) / 1024, 256>>>(ld, ldb, ldb + szLD, NLD * DDIM);
    transconv_kernel<<<dim3(DDIM / 32, DDIM / 32), 256>>>(W2, DDIM, DDIM, W2T, W2T + szDD);
    transconv_kernel<<<dim3(DDIM / 32, DDIM / 32), 256>>>(Wg, DDIM, DDIM, WgT, WgT + szDD);
    // [8] noise_norm + fused raw-u copy
    rownorm_split_kernel<<<NROWS, 256>>>(u, p_nn, nnb, nnb + szNM, out_u, nullptr);
    // [9] proj2 (NPROD=3)
    gemm_mma<EPI_BIAS, 3, true, true, true><<<gD, 128, SM_TOTAL>>>(
        hb, hb + szNM, W2T, W2T + szDD, b2, p_zp, zpb, zpb + szNM, out_zproj, DDIM, DDIM,
        nullptr, nullptr);
    // [10] z_norm + fused loss_direct
    rownorm_split_kernel<<<NROWS, 256>>>(p_zp, p_zn, znb, znb + szNM, nullptr, p_nn);
    // [11] gate (NPROD=1: sigmoid output tolerates bf16 product error)
    gemm_mma<EPI_SIGMOID, 1, true, false, false><<<gD, 128, SM_TOTAL>>>(
        zpb, zpb + szNM, WgT, WgT + szDD, bg, p_gate, nullptr, nullptr, nullptr, DDIM, DDIM,
        nullptr, nullptr);
    // [12] dual argmax + counts (NPROD=3: discrete decision)
    argmax_dual<<<NROWS / 128, 128, SM_TOTAL>>>(nnb, nnb + szNM,
                                                gdb, gdb + szGD, ldb, ldb + szLD, p_idx);
    // [13..15] scan / fill lists / gather dict update
    scan_kernel<<<1, 256>>>();
    fill_list_kernel<<<NROWS / 256, 256>>>(p_idx);
    dictupd_kernel<<<NCOMB, 256>>>(gd, ld, cbb, cbb + szCB);
    // [16] S = z_norm @ comb^T (NPROD=2; + fused sum|S|)
    gemm_mma<EPI_S_LOSS, 2, true, false, false><<<dim3(NCOMB / 128, NROWS / 128), 128, SM_TOTAL>>>(
        znb, znb + szNM, cbb, cbb + szCB, nullptr, p_S, nullptr, nullptr, nullptr, NCOMB, DDIM,
        nullptr, nullptr);
    // [17..18] softmax + comb^T
    softmax_split_kernel<<<NROWS, 256>>>(p_S, Sb, Sb + szNS);
    transconv_kernel<<<dim3(DDIM / 32, NCOMB / 32), 256>>>(p_comb, NCOMB, DDIM, ctb, ctb + szCB);
    // [19] weighted_u + fused z_clean (NPROD=1: wu scaled by gate*~0.03 vs z~1)
    gemm_mma<EPI_ZCLEAN, 1, true, false, false><<<gD, 128, SM_TOTAL>>>(
        Sb, Sb + szNS, ctb, ctb + szCB, nullptr, out_zc, nullptr, nullptr, nullptr, DDIM, NCOMB,
        z, p_gate);
    // [20] finalize loss
    finalize_kernel<<<1, 1>>>(out_loss);
}